// round 6
// baseline (speedup 1.0000x reference)
#include <cuda_runtime.h>
#include <cstdint>

// ---------------- problem constants ----------------
#define M_     4
#define B_     256
#define NPG_   64
#define N_     16384
#define DEG_   8
#define E_     131072
#define DF_    16
#define D_     256
#define L_     5
#define NA_    2
#define TASKS_ 10

// ---------------- device scratch (no allocs allowed) ----------------
__device__ float g_h0[(size_t)N_ * D_];            // 16 MB
__device__ float g_xcur[(size_t)M_ * N_ * D_];     // 64 MB
__device__ float g_hA[(size_t)M_ * N_ * D_];       // 64 MB
__device__ float g_z[(size_t)M_ * N_ * D_];        // 64 MB
__device__ float g_t[(size_t)M_ * N_ * D_];        // 64 MB
__device__ float g_mind[(size_t)M_ * N_];
__device__ int   g_anchor[(size_t)M_ * N_];

// ---------------- threefry2x32 (exact JAX rounds) ----------------
#define TF_ROT(x,d) (((x) << (d)) | ((x) >> (32 - (d))))
static __host__ __device__ __forceinline__
void tf2x32(unsigned k0, unsigned k1, unsigned x0, unsigned x1,
            unsigned* o0, unsigned* o1)
{
    unsigned ks2 = k0 ^ k1 ^ 0x1BD11BDAu;
    x0 += k0; x1 += k1;
    x0 += x1; x1 = TF_ROT(x1,13); x1 ^= x0;
    x0 += x1; x1 = TF_ROT(x1,15); x1 ^= x0;
    x0 += x1; x1 = TF_ROT(x1,26); x1 ^= x0;
    x0 += x1; x1 = TF_ROT(x1, 6); x1 ^= x0;
    x0 += k1; x1 += ks2 + 1u;
    x0 += x1; x1 = TF_ROT(x1,17); x1 ^= x0;
    x0 += x1; x1 = TF_ROT(x1,29); x1 ^= x0;
    x0 += x1; x1 = TF_ROT(x1,16); x1 ^= x0;
    x0 += x1; x1 = TF_ROT(x1,24); x1 ^= x0;
    x0 += ks2; x1 += k0 + 2u;
    x0 += x1; x1 = TF_ROT(x1,13); x1 ^= x0;
    x0 += x1; x1 = TF_ROT(x1,15); x1 ^= x0;
    x0 += x1; x1 = TF_ROT(x1,26); x1 ^= x0;
    x0 += x1; x1 = TF_ROT(x1, 6); x1 ^= x0;
    x0 += k0; x1 += k1 + 3u;
    x0 += x1; x1 = TF_ROT(x1,17); x1 ^= x0;
    x0 += x1; x1 = TF_ROT(x1,29); x1 ^= x0;
    x0 += x1; x1 = TF_ROT(x1,16); x1 ^= x0;
    x0 += x1; x1 = TF_ROT(x1,24); x1 ^= x0;
    x0 += k1; x1 += ks2 + 4u;
    x0 += x1; x1 = TF_ROT(x1,13); x1 ^= x0;
    x0 += x1; x1 = TF_ROT(x1,15); x1 ^= x0;
    x0 += x1; x1 = TF_ROT(x1,26); x1 ^= x0;
    x0 += x1; x1 = TF_ROT(x1, 6); x1 ^= x0;
    x0 += ks2; x1 += k0 + 5u;
    *o0 = x0; *o1 = x1;
}

// ---------------- encoder: h0 = relu(x @ W_enc + b_enc) ----------------
__global__ void encoder_kernel(const float* __restrict__ x,
                               const float* __restrict__ W,
                               const float* __restrict__ b,
                               float* __restrict__ h0)
{
    int n = blockIdx.x;
    int d = threadIdx.x;           // 256
    __shared__ float xr[DF_];
    if (d < DF_) xr[d] = x[n * DF_ + d];
    __syncthreads();
    float acc = b[d];
#pragma unroll
    for (int k = 0; k < DF_; k++) acc = fmaf(xr[k], W[k * D_ + d], acc);
    h0[(size_t)n * D_ + d] = fmaxf(acc, 0.f);
}

// ---------------- init: xcur = broadcast(h0) ----------------
__global__ void init_xcur_kernel(const float* __restrict__ h0,
                                 float* __restrict__ xc)
{
    size_t idx = (size_t)blockIdx.x * 256 + threadIdx.x;  // grid covers M*N*D
    size_t mn = idx >> 8;
    int d = (int)(idx & 255);
    int n = (int)(mn & (N_ - 1));
    xc[idx] = h0[((size_t)n << 8) + d];
}

__global__ void zero_anchor_kernel(int* __restrict__ anc)
{
    int idx = blockIdx.x * 256 + threadIdx.x;
    if (idx < M_ * N_) anc[idx] = 0;
}

// ---------------- graph aggregation + eps: z = (1+eps)*h + scatter_add ----
__global__ __launch_bounds__(256)
void agg_kernel(const float* __restrict__ h,
                const int* __restrict__ esrc, const int* __restrict__ edst,
                const float* __restrict__ eps, int layer,
                float* __restrict__ z)
{
    extern __shared__ float sagg[];              // 64*256 floats
    int b = blockIdx.x, m = blockIdx.y;
    int tid = threadIdx.x;
    for (int idx = tid; idx < NPG_ * D_; idx += 256) sagg[idx] = 0.f;
    __syncthreads();

    const float* H = h + ((size_t)m * N_ + (size_t)b * NPG_) * D_;
    int lane = tid & 31, w = tid >> 5;
    int ebase = b * (NPG_ * DEG_);               // 512 edges per graph
    for (int e8 = 0; e8 < 64; e8++) {
        int e = ebase + (w << 6) + e8;
        int s  = esrc[e] - b * NPG_;
        int dd = edst[e] - b * NPG_;
        const float* hr = H + (size_t)s * D_;
#pragma unroll
        for (int j = 0; j < 8; j++)
            atomicAdd(&sagg[dd * D_ + lane + j * 32], hr[lane + j * 32]);
    }
    __syncthreads();

    float ep = 1.0f + eps[layer];
    float* Z = z + ((size_t)m * N_ + (size_t)b * NPG_) * D_;
    for (int idx = tid; idx < NPG_ * D_; idx += 256)
        Z[idx] = ep * H[idx] + sagg[idx];
}

// ------- GEMM: C = relu(A @ W + bias), A:[Mx256] W:[256x256], fp32 --------
__global__ __launch_bounds__(256, 2)
void gemm_rr(const float* __restrict__ A, const float* __restrict__ W,
             const float* __restrict__ bias, float* __restrict__ C)
{
    __shared__ float As[8][128];
    __shared__ float Bs[8][128];
    const int tid  = threadIdx.x;
    const size_t row0 = (size_t)blockIdx.x * 128;
    const int col0 = blockIdx.y * 128;
    const int arow = tid >> 1;
    const int acol = (tid & 1) << 2;
    const int brow = tid >> 5;
    const int bcol = (tid & 31) << 2;
    const int tx = tid & 15;
    const int ty = tid >> 4;

    const float* Aptr = A + (row0 + arow) * 256 + acol;
    const float* Wptr = W + (size_t)brow * 256 + col0 + bcol;

    float4 pa = *(const float4*)Aptr;
    float4 pb = *(const float4*)Wptr;

    float acc[8][8];
#pragma unroll
    for (int i = 0; i < 8; i++)
#pragma unroll
        for (int j = 0; j < 8; j++) acc[i][j] = 0.f;

#pragma unroll 1
    for (int kt = 0; kt < 32; kt++) {
        As[acol + 0][arow] = pa.x;
        As[acol + 1][arow] = pa.y;
        As[acol + 2][arow] = pa.z;
        As[acol + 3][arow] = pa.w;
        *(float4*)&Bs[brow][bcol] = pb;
        __syncthreads();
        if (kt < 31) {
            pa = *(const float4*)(Aptr + (size_t)(kt + 1) * 8);
            pb = *(const float4*)(Wptr + (size_t)(kt + 1) * 8 * 256);
        }
#pragma unroll
        for (int kk = 0; kk < 8; kk++) {
            float a[8], bfr[8];
            *(float4*)&a[0]   = *(const float4*)&As[kk][ty * 8];
            *(float4*)&a[4]   = *(const float4*)&As[kk][ty * 8 + 4];
            *(float4*)&bfr[0] = *(const float4*)&Bs[kk][tx * 8];
            *(float4*)&bfr[4] = *(const float4*)&Bs[kk][tx * 8 + 4];
#pragma unroll
            for (int i = 0; i < 8; i++)
#pragma unroll
                for (int j = 0; j < 8; j++)
                    acc[i][j] = fmaf(a[i], bfr[j], acc[i][j]);
        }
        __syncthreads();
    }

#pragma unroll
    for (int i = 0; i < 8; i++) {
        float* Crow = C + (row0 + ty * 8 + i) * 256 + col0 + tx * 8;
#pragma unroll
        for (int j0 = 0; j0 < 8; j0 += 4) {
            float4 v;
            v.x = fmaxf(acc[i][j0 + 0] + bias[col0 + tx * 8 + j0 + 0], 0.f);
            v.y = fmaxf(acc[i][j0 + 1] + bias[col0 + tx * 8 + j0 + 1], 0.f);
            v.z = fmaxf(acc[i][j0 + 2] + bias[col0 + tx * 8 + j0 + 2], 0.f);
            v.w = fmaxf(acc[i][j0 + 3] + bias[col0 + tx * 8 + j0 + 3], 0.f);
            *(float4*)&Crow[j0] = v;
        }
    }
}

// ---------------- per-graph pairwise min distance (fp32) ----------------
#define MD_SMEM ((64 * 257 + 64 + 64) * 4)
__global__ __launch_bounds__(256)
void mindist_kernel(const float* __restrict__ h, float* __restrict__ mind)
{
    extern __shared__ float sm[];
    float* sh  = sm;                   // 64 x 257 (padded)
    float* ssq = sm + 64 * 257;        // 64
    int*   smn = (int*)(ssq + 64);     // 64 (float-as-int min, values >= 0)
    int b = blockIdx.x, m = blockIdx.y;
    int tid = threadIdx.x;

    const float* H = h + ((size_t)m * N_ + (size_t)b * NPG_) * D_;
    for (int idx = tid; idx < NPG_ * D_; idx += 256) {
        int r = idx >> 8, d = idx & 255;
        sh[r * 257 + d] = H[idx];
    }
    if (tid < 64) smn[tid] = 0x7f7fffff;   // FLT_MAX bits
    __syncthreads();

    if (tid < 64) {
        const float* row = sh + tid * 257;
        float s = 0.f;
        for (int d = 0; d < D_; d++) s = fmaf(row[d], row[d], s);
        ssq[tid] = s;
    }
    __syncthreads();

    int i  = tid >> 2;
    int j0 = (tid & 3) * 16;
    float acc[16];
#pragma unroll
    for (int jj = 0; jj < 16; jj++) acc[jj] = 0.f;
    const float* ri = sh + i * 257;
    for (int d = 0; d < D_; d++) {
        float a = ri[d];
#pragma unroll
        for (int jj = 0; jj < 16; jj++)
            acc[jj] = fmaf(a, sh[(j0 + jj) * 257 + d], acc[jj]);
    }
    float sqi = ssq[i];
    float lmin = 3.0e38f;
#pragma unroll
    for (int jj = 0; jj < 16; jj++) {
        int j = j0 + jj;
        float d2 = fmaxf(sqi + ssq[j] - 2.0f * acc[jj], 0.f);
        if (j == i) d2 += 1.0e9f;
        lmin = fminf(lmin, d2);
    }
    atomicMin(&smn[i], __float_as_int(lmin));
    __syncthreads();
    if (tid < 64)
        mind[(size_t)m * N_ + (size_t)b * NPG_ + tid] = __int_as_float(smn[tid]);
}

// ------------- gumbel sample + argmax + anchor set (exact JAX) -----------
// JAX partitionable random_bits (bit_width=32):
//   bits = out0 ^ out1 of threefry2x32(key, hi=0, lo=flat_index)
__global__ void gumbel_kernel(const float* __restrict__ mind,
                              int* __restrict__ anchor,
                              int it, unsigned fk0, unsigned fk1)
{
    int b = blockIdx.x, m = blockIdx.y;
    int p = threadIdx.x;                       // 64
    __shared__ float sg[NPG_];
    int node = m * N_ + b * NPG_ + p;          // flat index into (M,B,NPG)

    unsigned o0, o1;
    tf2x32(fk0, fk1, 0u, (unsigned)node, &o0, &o1);
    unsigned bits = o0 ^ o1;                    // XOR fold of both words
    float f = __uint_as_float((bits >> 9) | 0x3f800000u) - 1.0f;
    const float mn = 1e-9f;
    float u = fmaxf(mn, f * (1.0f - mn) + mn);
    float logit = -mind[node] - 10.0f * (anchor[node] > 0 ? 1.0f : 0.0f);
    sg[p] = logit - logf(-logf(u));
    __syncthreads();
    if (p == 0) {
        int best = 0; float bv = sg[0];
        for (int q = 1; q < NPG_; q++)
            if (sg[q] > bv) { bv = sg[q]; best = q; }   // first-max tie rule
        anchor[m * N_ + b * NPG_ + best] = it;
    }
}

// ---------------- xcur = tx * anchor_emb[anchor] + tx ----------------
__global__ void update_xcur_kernel(const float* __restrict__ h0,
                                   const int* __restrict__ anchor,
                                   const float* __restrict__ emb,
                                   float* __restrict__ xc)
{
    size_t idx = (size_t)blockIdx.x * 256 + threadIdx.x;
    size_t mn = idx >> 8;
    int d = (int)(idx & 255);
    int n = (int)(mn & (N_ - 1));
    int a = anchor[mn];
    float tv = h0[((size_t)n << 8) + d];
    xc[idx] = tv * emb[a * D_ + d] + tv;
}

// --------- finalize: per-m group mean -> dot W_pred -> mean over m --------
__global__ void finalize_kernel(const float* __restrict__ hn,
                                const float* __restrict__ Wp,
                                const float* __restrict__ bp,
                                float* __restrict__ out)
{
    int b = blockIdx.x;
    int d = threadIdx.x;                  // 256
    __shared__ float g[M_][D_];
#pragma unroll
    for (int m = 0; m < M_; m++) {
        const float* base = hn + ((size_t)m * N_ + (size_t)b * NPG_) * D_ + d;
        float s = 0.f;
        for (int p = 0; p < NPG_; p++) s += base[(size_t)p * D_];
        g[m][d] = s * (1.0f / (float)NPG_);   // hg per-m
    }
    __syncthreads();
    if (d < TASKS_) {
        float acc = 0.f;
#pragma unroll
        for (int m = 0; m < M_; m++) {
            float a = 0.f;
            for (int k = 0; k < D_; k++)
                a = fmaf(g[m][k], Wp[k * TASKS_ + d], a);
            acc += a + bp[d];
        }
        out[b * TASKS_ + d] = acc * (1.0f / (float)M_);
    }
}

// ---------------- host orchestration ----------------
extern "C" void kernel_launch(void* const* d_in, const int* in_sizes, int n_in,
                              void* d_out, int out_size)
{
    const float* x     = (const float*)d_in[0];
    const float* W_enc = (const float*)d_in[1];
    const float* b_enc = (const float*)d_in[2];
    const float* gW1   = (const float*)d_in[3];
    const float* gb1   = (const float*)d_in[4];
    const float* gW2   = (const float*)d_in[5];
    const float* gb2   = (const float*)d_in[6];
    const float* eps   = (const float*)d_in[7];
    const float* aemb  = (const float*)d_in[8];
    const float* Wn2n  = (const float*)d_in[9];
    const float* bn2n  = (const float*)d_in[10];
    const float* Wp    = (const float*)d_in[11];
    const float* bp    = (const float*)d_in[12];
    const int*   esrc  = (const int*)d_in[13];
    const int*   edst  = (const int*)d_in[14];
    float* out = (float*)d_out;

    float *h0, *xc, *hA, *z, *t, *mind; int* anc;
    cudaGetSymbolAddress((void**)&h0,   g_h0);
    cudaGetSymbolAddress((void**)&xc,   g_xcur);
    cudaGetSymbolAddress((void**)&hA,   g_hA);
    cudaGetSymbolAddress((void**)&z,    g_z);
    cudaGetSymbolAddress((void**)&t,    g_t);
    cudaGetSymbolAddress((void**)&mind, g_mind);
    cudaGetSymbolAddress((void**)&anc,  g_anchor);

    cudaFuncSetAttribute(agg_kernel, cudaFuncAttributeMaxDynamicSharedMemorySize, 65536);
    cudaFuncSetAttribute(mindist_kernel, cudaFuncAttributeMaxDynamicSharedMemorySize, MD_SMEM);

    // folded keys: fold_in(key(42), i) = threefry((0,42),(0,i))
    unsigned fk0[NA_ + 1], fk1[NA_ + 1];
    for (int i = 1; i <= NA_; i++)
        tf2x32(0u, 42u, 0u, (unsigned)i, &fk0[i], &fk1[i]);

    const dim3 gemm_grid(512, 2);
    const dim3 graph_grid(B_, M_);
    const int  bcast_blocks = (M_ * N_ * D_) / 256;   // 65536

    encoder_kernel<<<N_, 256>>>(x, W_enc, b_enc, h0);
    init_xcur_kernel<<<bcast_blocks, 256>>>(h0, xc);
    zero_anchor_kernel<<<(M_ * N_) / 256, 256>>>(anc);

    for (int it = 1; it <= NA_; it++) {
        const float* cur = xc;
        for (int l = 0; l < L_; l++) {
            agg_kernel<<<graph_grid, 256, 65536>>>(cur, esrc, edst, eps, l, z);
            gemm_rr<<<gemm_grid, 256>>>(z, gW1 + (size_t)l * D_ * D_, gb1 + l * D_, t);
            gemm_rr<<<gemm_grid, 256>>>(t, gW2 + (size_t)l * D_ * D_, gb2 + l * D_, hA);
            cur = hA;
        }
        mindist_kernel<<<graph_grid, 256, MD_SMEM>>>(hA, mind);
        gumbel_kernel<<<graph_grid, 64>>>(mind, anc, it, fk0[it], fk1[it]);
        update_xcur_kernel<<<bcast_blocks, 256>>>(h0, anc, aemb, xc);
    }

    // final GNN on xcur
    {
        const float* cur = xc;
        for (int l = 0; l < L_; l++) {
            agg_kernel<<<graph_grid, 256, 65536>>>(cur, esrc, edst, eps, l, z);
            gemm_rr<<<gemm_grid, 256>>>(z, gW1 + (size_t)l * D_ * D_, gb1 + l * D_, t);
            gemm_rr<<<gemm_grid, 256>>>(t, gW2 + (size_t)l * D_ * D_, gb2 + l * D_, hA);
            cur = hA;
        }
    }
    gemm_rr<<<gemm_grid, 256>>>(hA, Wn2n, bn2n, t);   // hn = relu(h@W_n2n+b)
    finalize_kernel<<<B_, 256>>>(t, Wp, bp, out);
}

// round 7
// speedup vs baseline: 1.7150x; 1.7150x over previous
#include <cuda_runtime.h>
#include <cstdint>

// ---------------- problem constants ----------------
#define M_     4
#define B_     256
#define NPG_   64
#define N_     16384
#define DEG_   8
#define E_     131072
#define DF_    16
#define D_     256
#define L_     5
#define NA_    2
#define TASKS_ 10

// ---------------- device scratch (no allocs allowed) ----------------
__device__ float g_h0[(size_t)N_ * D_];            // 16 MB
__device__ float g_xcur[(size_t)M_ * N_ * D_];     // 64 MB
__device__ float g_hA[(size_t)M_ * N_ * D_];       // 64 MB
__device__ float g_z[(size_t)M_ * N_ * D_];        // 64 MB
__device__ float g_t[(size_t)M_ * N_ * D_];        // 64 MB
__device__ float g_mind[(size_t)M_ * N_];
__device__ int   g_anchor[(size_t)M_ * N_];

// ---------------- threefry2x32 (exact JAX rounds) ----------------
#define TF_ROT(x,d) (((x) << (d)) | ((x) >> (32 - (d))))
static __host__ __device__ __forceinline__
void tf2x32(unsigned k0, unsigned k1, unsigned x0, unsigned x1,
            unsigned* o0, unsigned* o1)
{
    unsigned ks2 = k0 ^ k1 ^ 0x1BD11BDAu;
    x0 += k0; x1 += k1;
    x0 += x1; x1 = TF_ROT(x1,13); x1 ^= x0;
    x0 += x1; x1 = TF_ROT(x1,15); x1 ^= x0;
    x0 += x1; x1 = TF_ROT(x1,26); x1 ^= x0;
    x0 += x1; x1 = TF_ROT(x1, 6); x1 ^= x0;
    x0 += k1; x1 += ks2 + 1u;
    x0 += x1; x1 = TF_ROT(x1,17); x1 ^= x0;
    x0 += x1; x1 = TF_ROT(x1,29); x1 ^= x0;
    x0 += x1; x1 = TF_ROT(x1,16); x1 ^= x0;
    x0 += x1; x1 = TF_ROT(x1,24); x1 ^= x0;
    x0 += ks2; x1 += k0 + 2u;
    x0 += x1; x1 = TF_ROT(x1,13); x1 ^= x0;
    x0 += x1; x1 = TF_ROT(x1,15); x1 ^= x0;
    x0 += x1; x1 = TF_ROT(x1,26); x1 ^= x0;
    x0 += x1; x1 = TF_ROT(x1, 6); x1 ^= x0;
    x0 += k0; x1 += k1 + 3u;
    x0 += x1; x1 = TF_ROT(x1,17); x1 ^= x0;
    x0 += x1; x1 = TF_ROT(x1,29); x1 ^= x0;
    x0 += x1; x1 = TF_ROT(x1,16); x1 ^= x0;
    x0 += x1; x1 = TF_ROT(x1,24); x1 ^= x0;
    x0 += k1; x1 += ks2 + 4u;
    x0 += x1; x1 = TF_ROT(x1,13); x1 ^= x0;
    x0 += x1; x1 = TF_ROT(x1,15); x1 ^= x0;
    x0 += x1; x1 = TF_ROT(x1,26); x1 ^= x0;
    x0 += x1; x1 = TF_ROT(x1, 6); x1 ^= x0;
    x0 += ks2; x1 += k0 + 5u;
    *o0 = x0; *o1 = x1;
}

// ---------------- encoder: h0 = relu(x @ W_enc + b_enc) ----------------
__global__ void encoder_kernel(const float* __restrict__ x,
                               const float* __restrict__ W,
                               const float* __restrict__ b,
                               float* __restrict__ h0)
{
    int n = blockIdx.x;
    int d = threadIdx.x;           // 256
    __shared__ float xr[DF_];
    if (d < DF_) xr[d] = x[n * DF_ + d];
    __syncthreads();
    float acc = b[d];
#pragma unroll
    for (int k = 0; k < DF_; k++) acc = fmaf(xr[k], W[k * D_ + d], acc);
    h0[(size_t)n * D_ + d] = fmaxf(acc, 0.f);
}

__global__ void zero_anchor_kernel(int* __restrict__ anc)
{
    int idx = blockIdx.x * 256 + threadIdx.x;
    if (idx < M_ * N_) anc[idx] = 0;
}

// ------- graph aggregation via count-matrix: z = (1+eps)*h + C @ h --------
// C[dst][src] = multiplicity of edge (src->dst) within the graph (64x64).
// Builds C with cheap scalar smem atomics (512 ops), then does a dense
// 64x64 x 64x256 mini-GEMM with warp-uniform zero skipping (~87% sparse).
#define AGG_SMEM ((64 * 256 + 64 * 64) * 4)   // H tile 64KB + counts 16KB
__global__ __launch_bounds__(256)
void agg_fast_kernel(const float* __restrict__ h,
                     const int* __restrict__ esrc, const int* __restrict__ edst,
                     const float* __restrict__ eps, int layer,
                     float* __restrict__ z)
{
    extern __shared__ float sm[];
    float* sH = sm;                 // 64 x 256
    float* sC = sm + 64 * 256;      // 64 x 64, dst-major
    int b = blockIdx.x, m = blockIdx.y;
    int tid = threadIdx.x;

    const float4* H4 = (const float4*)(h + ((size_t)m * N_ + (size_t)b * NPG_) * D_);
    float4* sH4 = (float4*)sH;
#pragma unroll
    for (int k = 0; k < 16; k++) sH4[tid + k * 256] = H4[tid + k * 256];
#pragma unroll
    for (int k = 0; k < 16; k++) sC[tid + k * 256] = 0.f;
    __syncthreads();

    int ebase = b * (NPG_ * DEG_);            // 512 edges per graph
#pragma unroll
    for (int k = 0; k < 2; k++) {
        int e = ebase + tid + k * 256;
        int s  = esrc[e] & (NPG_ - 1);        // node ids are b*64 + local
        int dd = edst[e] & (NPG_ - 1);
        atomicAdd(&sC[dd * 64 + s], 1.0f);
    }
    __syncthreads();

    float ep = 1.0f + eps[layer];
    int l = tid & 63;                         // float4-column 0..63 (dims 4l..)
    int g = tid >> 6;                         // row group 0..3 -> rows g*16..
    float4 acc[16];
#pragma unroll
    for (int i = 0; i < 16; i++) {
        float4 v = sH4[(g * 16 + i) * 64 + l];
        acc[i] = make_float4(ep * v.x, ep * v.y, ep * v.z, ep * v.w);
    }
#pragma unroll 4
    for (int j = 0; j < 64; j++) {
        float4 hj = make_float4(0.f, 0.f, 0.f, 0.f);
        bool loaded = false;
#pragma unroll
        for (int i = 0; i < 16; i++) {
            float c = sC[(g * 16 + i) * 64 + j];   // warp-uniform (broadcast)
            if (c != 0.f) {
                if (!loaded) { hj = sH4[j * 64 + l]; loaded = true; }
                acc[i].x = fmaf(c, hj.x, acc[i].x);
                acc[i].y = fmaf(c, hj.y, acc[i].y);
                acc[i].z = fmaf(c, hj.z, acc[i].z);
                acc[i].w = fmaf(c, hj.w, acc[i].w);
            }
        }
    }
    float4* Z4 = (float4*)(z + ((size_t)m * N_ + (size_t)b * NPG_) * D_);
#pragma unroll
    for (int i = 0; i < 16; i++)
        Z4[(g * 16 + i) * 64 + l] = acc[i];
}

// ------- GEMM: C = relu(A @ W + bias), fp32, ping-pong smem ---------------
__global__ __launch_bounds__(256, 2)
void gemm_rr(const float* __restrict__ A, const float* __restrict__ W,
             const float* __restrict__ bias, float* __restrict__ C)
{
    __shared__ float As[2][8][128];
    __shared__ float Bs[2][8][128];
    const int tid  = threadIdx.x;
    const size_t row0 = (size_t)blockIdx.x * 128;
    const int col0 = blockIdx.y * 128;
    const int arow = tid >> 1;
    const int acol = (tid & 1) << 2;
    const int brow = tid >> 5;
    const int bcol = (tid & 31) << 4;   // byte-ish? no: element idx, (tid&31)*4
    const int bcolE = (tid & 31) << 2;
    const int tx = tid & 15;
    const int ty = tid >> 4;
    (void)bcol;

    const float* Aptr = A + (row0 + arow) * 256 + acol;
    const float* Wptr = W + (size_t)brow * 256 + col0 + bcolE;

    float4 pa = *(const float4*)Aptr;
    float4 pb = *(const float4*)Wptr;
    As[0][acol + 0][arow] = pa.x;
    As[0][acol + 1][arow] = pa.y;
    As[0][acol + 2][arow] = pa.z;
    As[0][acol + 3][arow] = pa.w;
    *(float4*)&Bs[0][brow][bcolE] = pb;
    __syncthreads();

    float acc[8][8];
#pragma unroll
    for (int i = 0; i < 8; i++)
#pragma unroll
        for (int j = 0; j < 8; j++) acc[i][j] = 0.f;

#pragma unroll 2
    for (int kt = 0; kt < 32; kt++) {
        const int cur = kt & 1;
        float4 na, nb;
        if (kt < 31) {
            na = *(const float4*)(Aptr + (size_t)(kt + 1) * 8);
            nb = *(const float4*)(Wptr + (size_t)(kt + 1) * 8 * 256);
        }
#pragma unroll
        for (int kk = 0; kk < 8; kk++) {
            float a[8], bfr[8];
            *(float4*)&a[0]   = *(const float4*)&As[cur][kk][ty * 8];
            *(float4*)&a[4]   = *(const float4*)&As[cur][kk][ty * 8 + 4];
            *(float4*)&bfr[0] = *(const float4*)&Bs[cur][kk][tx * 8];
            *(float4*)&bfr[4] = *(const float4*)&Bs[cur][kk][tx * 8 + 4];
#pragma unroll
            for (int i = 0; i < 8; i++)
#pragma unroll
                for (int j = 0; j < 8; j++)
                    acc[i][j] = fmaf(a[i], bfr[j], acc[i][j]);
        }
        if (kt < 31) {
            As[cur ^ 1][acol + 0][arow] = na.x;
            As[cur ^ 1][acol + 1][arow] = na.y;
            As[cur ^ 1][acol + 2][arow] = na.z;
            As[cur ^ 1][acol + 3][arow] = na.w;
            *(float4*)&Bs[cur ^ 1][brow][bcolE] = nb;
            __syncthreads();
        }
    }

#pragma unroll
    for (int i = 0; i < 8; i++) {
        float* Crow = C + (row0 + ty * 8 + i) * 256 + col0 + tx * 8;
#pragma unroll
        for (int j0 = 0; j0 < 8; j0 += 4) {
            float4 v;
            v.x = fmaxf(acc[i][j0 + 0] + bias[col0 + tx * 8 + j0 + 0], 0.f);
            v.y = fmaxf(acc[i][j0 + 1] + bias[col0 + tx * 8 + j0 + 1], 0.f);
            v.z = fmaxf(acc[i][j0 + 2] + bias[col0 + tx * 8 + j0 + 2], 0.f);
            v.w = fmaxf(acc[i][j0 + 3] + bias[col0 + tx * 8 + j0 + 3], 0.f);
            *(float4*)&Crow[j0] = v;
        }
    }
}

// ---------------- per-graph pairwise min distance (fp32) ----------------
#define MD_SMEM ((64 * 257 + 64 + 64) * 4)
__global__ __launch_bounds__(256)
void mindist_kernel(const float* __restrict__ h, float* __restrict__ mind)
{
    extern __shared__ float sm[];
    float* sh  = sm;                   // 64 x 257 (padded)
    float* ssq = sm + 64 * 257;        // 64
    int*   smn = (int*)(ssq + 64);     // 64 (float-as-int min, values >= 0)
    int b = blockIdx.x, m = blockIdx.y;
    int tid = threadIdx.x;

    const float* H = h + ((size_t)m * N_ + (size_t)b * NPG_) * D_;
    for (int idx = tid; idx < NPG_ * D_; idx += 256) {
        int r = idx >> 8, d = idx & 255;
        sh[r * 257 + d] = H[idx];
    }
    if (tid < 64) smn[tid] = 0x7f7fffff;   // FLT_MAX bits
    __syncthreads();

    if (tid < 64) {
        const float* row = sh + tid * 257;
        float s = 0.f;
        for (int d = 0; d < D_; d++) s = fmaf(row[d], row[d], s);
        ssq[tid] = s;
    }
    __syncthreads();

    int i  = tid >> 2;
    int j0 = (tid & 3) * 16;
    float acc[16];
#pragma unroll
    for (int jj = 0; jj < 16; jj++) acc[jj] = 0.f;
    const float* ri = sh + i * 257;
    for (int d = 0; d < D_; d++) {
        float a = ri[d];
#pragma unroll
        for (int jj = 0; jj < 16; jj++)
            acc[jj] = fmaf(a, sh[(j0 + jj) * 257 + d], acc[jj]);
    }
    float sqi = ssq[i];
    float lmin = 3.0e38f;
#pragma unroll
    for (int jj = 0; jj < 16; jj++) {
        int j = j0 + jj;
        float d2 = fmaxf(sqi + ssq[j] - 2.0f * acc[jj], 0.f);
        if (j == i) d2 += 1.0e9f;
        lmin = fminf(lmin, d2);
    }
    atomicMin(&smn[i], __float_as_int(lmin));
    __syncthreads();
    if (tid < 64)
        mind[(size_t)m * N_ + (size_t)b * NPG_ + tid] = __int_as_float(smn[tid]);
}

// ------------- gumbel sample + argmax + anchor set (exact JAX) -----------
// mind_stride_m: N_ for full-per-m mind, 0 when mind is shared (iteration 1,
// where xcur is broadcast so mind is identical across m).
__global__ void gumbel_kernel(const float* __restrict__ mind,
                              int* __restrict__ anchor,
                              int it, unsigned fk0, unsigned fk1,
                              int mind_stride_m)
{
    int b = blockIdx.x, m = blockIdx.y;
    int p = threadIdx.x;                       // 64
    __shared__ float sg[NPG_];
    int node = m * N_ + b * NPG_ + p;          // flat index into (M,B,NPG)

    unsigned o0, o1;
    tf2x32(fk0, fk1, 0u, (unsigned)node, &o0, &o1);
    unsigned bits = o0 ^ o1;                    // XOR fold of both words
    float f = __uint_as_float((bits >> 9) | 0x3f800000u) - 1.0f;
    const float mn = 1e-9f;
    float u = fmaxf(mn, f * (1.0f - mn) + mn);
    float md = mind[(size_t)m * mind_stride_m + b * NPG_ + p];
    float logit = -md - 10.0f * (anchor[node] > 0 ? 1.0f : 0.0f);
    sg[p] = logit - logf(-logf(u));
    __syncthreads();
    if (p == 0) {
        int best = 0; float bv = sg[0];
        for (int q = 1; q < NPG_; q++)
            if (sg[q] > bv) { bv = sg[q]; best = q; }   // first-max tie rule
        anchor[m * N_ + b * NPG_ + best] = it;
    }
}

// ---------------- xcur = tx * anchor_emb[anchor] + tx ----------------
__global__ void update_xcur_kernel(const float* __restrict__ h0,
                                   const int* __restrict__ anchor,
                                   const float* __restrict__ emb,
                                   float* __restrict__ xc)
{
    size_t idx = (size_t)blockIdx.x * 256 + threadIdx.x;
    size_t mn = idx >> 8;
    int d = (int)(idx & 255);
    int n = (int)(mn & (N_ - 1));
    int a = anchor[mn];
    float tv = h0[((size_t)n << 8) + d];
    xc[idx] = tv * emb[a * D_ + d] + tv;
}

// --------- finalize: per-m group mean -> dot W_pred -> mean over m --------
__global__ void finalize_kernel(const float* __restrict__ hn,
                                const float* __restrict__ Wp,
                                const float* __restrict__ bp,
                                float* __restrict__ out)
{
    int b = blockIdx.x;
    int d = threadIdx.x;                  // 256
    __shared__ float g[M_][D_];
#pragma unroll
    for (int m = 0; m < M_; m++) {
        const float* base = hn + ((size_t)m * N_ + (size_t)b * NPG_) * D_ + d;
        float s = 0.f;
        for (int p = 0; p < NPG_; p++) s += base[(size_t)p * D_];
        g[m][d] = s * (1.0f / (float)NPG_);   // hg per-m
    }
    __syncthreads();
    if (d < TASKS_) {
        float acc = 0.f;
#pragma unroll
        for (int m = 0; m < M_; m++) {
            float a = 0.f;
            for (int k = 0; k < D_; k++)
                a = fmaf(g[m][k], Wp[k * TASKS_ + d], a);
            acc += a + bp[d];
        }
        out[b * TASKS_ + d] = acc * (1.0f / (float)M_);
    }
}

// ---------------- host orchestration ----------------
extern "C" void kernel_launch(void* const* d_in, const int* in_sizes, int n_in,
                              void* d_out, int out_size)
{
    const float* x     = (const float*)d_in[0];
    const float* W_enc = (const float*)d_in[1];
    const float* b_enc = (const float*)d_in[2];
    const float* gW1   = (const float*)d_in[3];
    const float* gb1   = (const float*)d_in[4];
    const float* gW2   = (const float*)d_in[5];
    const float* gb2   = (const float*)d_in[6];
    const float* eps   = (const float*)d_in[7];
    const float* aemb  = (const float*)d_in[8];
    const float* Wn2n  = (const float*)d_in[9];
    const float* bn2n  = (const float*)d_in[10];
    const float* Wp    = (const float*)d_in[11];
    const float* bp    = (const float*)d_in[12];
    const int*   esrc  = (const int*)d_in[13];
    const int*   edst  = (const int*)d_in[14];
    float* out = (float*)d_out;

    float *h0, *xc, *hA, *z, *t, *mind; int* anc;
    cudaGetSymbolAddress((void**)&h0,   g_h0);
    cudaGetSymbolAddress((void**)&xc,   g_xcur);
    cudaGetSymbolAddress((void**)&hA,   g_hA);
    cudaGetSymbolAddress((void**)&z,    g_z);
    cudaGetSymbolAddress((void**)&t,    g_t);
    cudaGetSymbolAddress((void**)&mind, g_mind);
    cudaGetSymbolAddress((void**)&anc,  g_anchor);

    cudaFuncSetAttribute(agg_fast_kernel, cudaFuncAttributeMaxDynamicSharedMemorySize, AGG_SMEM);
    cudaFuncSetAttribute(mindist_kernel, cudaFuncAttributeMaxDynamicSharedMemorySize, MD_SMEM);

    // folded keys: fold_in(key(42), i) = threefry((0,42),(0,i))
    unsigned fk0[NA_ + 1], fk1[NA_ + 1];
    for (int i = 1; i <= NA_; i++)
        tf2x32(0u, 42u, 0u, (unsigned)i, &fk0[i], &fk1[i]);

    const dim3 gemm_full(512, 2), gemm_q(128, 2);
    const dim3 graph_full(B_, M_), graph_q(B_, 1);
    const int  bcast_blocks = (M_ * N_ * D_) / 256;   // 65536

    encoder_kernel<<<N_, 256>>>(x, W_enc, b_enc, h0);
    zero_anchor_kernel<<<(M_ * N_) / 256, 256>>>(anc);

    // ---- iteration 1: xcur is an identical broadcast of h0 across m, so
    // the GNN + mindist are computed once (N rows) instead of M*N. ----
    {
        const float* cur = h0;
        for (int l = 0; l < L_; l++) {
            agg_fast_kernel<<<graph_q, 256, AGG_SMEM>>>(cur, esrc, edst, eps, l, z);
            gemm_rr<<<gemm_q, 256>>>(z, gW1 + (size_t)l * D_ * D_, gb1 + l * D_, t);
            gemm_rr<<<gemm_q, 256>>>(t, gW2 + (size_t)l * D_ * D_, gb2 + l * D_, hA);
            cur = hA;
        }
        mindist_kernel<<<graph_q, 256, MD_SMEM>>>(hA, mind);
        gumbel_kernel<<<graph_full, 64>>>(mind, anc, 1, fk0[1], fk1[1], 0);
        update_xcur_kernel<<<bcast_blocks, 256>>>(h0, anc, aemb, xc);
    }

    // ---- iteration 2: full per-m pipeline ----
    {
        const float* cur = xc;
        for (int l = 0; l < L_; l++) {
            agg_fast_kernel<<<graph_full, 256, AGG_SMEM>>>(cur, esrc, edst, eps, l, z);
            gemm_rr<<<gemm_full, 256>>>(z, gW1 + (size_t)l * D_ * D_, gb1 + l * D_, t);
            gemm_rr<<<gemm_full, 256>>>(t, gW2 + (size_t)l * D_ * D_, gb2 + l * D_, hA);
            cur = hA;
        }
        mindist_kernel<<<graph_full, 256, MD_SMEM>>>(hA, mind);
        gumbel_kernel<<<graph_full, 64>>>(mind, anc, 2, fk0[2], fk1[2], N_);
        update_xcur_kernel<<<bcast_blocks, 256>>>(h0, anc, aemb, xc);
    }

    // ---- final GNN on xcur ----
    {
        const float* cur = xc;
        for (int l = 0; l < L_; l++) {
            agg_fast_kernel<<<graph_full, 256, AGG_SMEM>>>(cur, esrc, edst, eps, l, z);
            gemm_rr<<<gemm_full, 256>>>(z, gW1 + (size_t)l * D_ * D_, gb1 + l * D_, t);
            gemm_rr<<<gemm_full, 256>>>(t, gW2 + (size_t)l * D_ * D_, gb2 + l * D_, hA);
            cur = hA;
        }
    }
    gemm_rr<<<gemm_full, 256>>>(hA, Wn2n, bn2n, t);   // hn = relu(h@W_n2n+b)
    finalize_kernel<<<B_, 256>>>(t, Wp, bp, out);
}

// round 9
// speedup vs baseline: 2.0175x; 1.1764x over previous
#include <cuda_runtime.h>
#include <cstdint>

// ---------------- problem constants ----------------
#define M_     4
#define B_     256
#define NPG_   64
#define N_     16384
#define DEG_   8
#define E_     131072
#define DF_    16
#define D_     256
#define L_     5
#define NA_    2
#define TASKS_ 10

// ---------------- device scratch (no allocs allowed) ----------------
__device__ float g_h0[(size_t)N_ * D_];            // 16 MB
__device__ float g_xcur[(size_t)M_ * N_ * D_];     // 64 MB
__device__ float g_hA[(size_t)M_ * N_ * D_];       // 64 MB
__device__ float g_z[(size_t)M_ * N_ * D_];        // 64 MB
__device__ float g_t[(size_t)M_ * N_ * D_];        // 64 MB
__device__ float g_mind[(size_t)M_ * N_];
__device__ int   g_anchor[(size_t)M_ * N_];
// pre-split, frag-permuted weights: [11][65536]
__device__ float g_wt_big[11 * 65536];
__device__ float g_wt_small[11 * 65536];

static __device__ __forceinline__ float tf32r(float x) {
    float r;
    asm("cvt.rna.tf32.f32 %0, %1;" : "=f"(r) : "f"(x));
    return r;
}

// m16n8k8 tf32 mma (sm_80+ PTX, works on base compute_103 target)
#define MMA_TF32(d, a, b) \
    asm volatile("mma.sync.aligned.m16n8k8.row.col.f32.tf32.tf32.f32 " \
                 "{%0,%1,%2,%3}, {%4,%5,%6,%7}, {%8,%9}, {%0,%1,%2,%3};" \
                 : "+f"((d)[0]), "+f"((d)[1]), "+f"((d)[2]), "+f"((d)[3]) \
                 : "r"((a)[0]), "r"((a)[1]), "r"((a)[2]), "r"((a)[3]), \
                   "r"((b)[0]), "r"((b)[1]))

// ---------------- threefry2x32 (exact JAX rounds) ----------------
#define TF_ROT(x,d) (((x) << (d)) | ((x) >> (32 - (d))))
static __host__ __device__ __forceinline__
void tf2x32(unsigned k0, unsigned k1, unsigned x0, unsigned x1,
            unsigned* o0, unsigned* o1)
{
    unsigned ks2 = k0 ^ k1 ^ 0x1BD11BDAu;
    x0 += k0; x1 += k1;
    x0 += x1; x1 = TF_ROT(x1,13); x1 ^= x0;
    x0 += x1; x1 = TF_ROT(x1,15); x1 ^= x0;
    x0 += x1; x1 = TF_ROT(x1,26); x1 ^= x0;
    x0 += x1; x1 = TF_ROT(x1, 6); x1 ^= x0;
    x0 += k1; x1 += ks2 + 1u;
    x0 += x1; x1 = TF_ROT(x1,17); x1 ^= x0;
    x0 += x1; x1 = TF_ROT(x1,29); x1 ^= x0;
    x0 += x1; x1 = TF_ROT(x1,16); x1 ^= x0;
    x0 += x1; x1 = TF_ROT(x1,24); x1 ^= x0;
    x0 += ks2; x1 += k0 + 2u;
    x0 += x1; x1 = TF_ROT(x1,13); x1 ^= x0;
    x0 += x1; x1 = TF_ROT(x1,15); x1 ^= x0;
    x0 += x1; x1 = TF_ROT(x1,26); x1 ^= x0;
    x0 += x1; x1 = TF_ROT(x1, 6); x1 ^= x0;
    x0 += k0; x1 += k1 + 3u;
    x0 += x1; x1 = TF_ROT(x1,17); x1 ^= x0;
    x0 += x1; x1 = TF_ROT(x1,29); x1 ^= x0;
    x0 += x1; x1 = TF_ROT(x1,16); x1 ^= x0;
    x0 += x1; x1 = TF_ROT(x1,24); x1 ^= x0;
    x0 += k1; x1 += ks2 + 4u;
    x0 += x1; x1 = TF_ROT(x1,13); x1 ^= x0;
    x0 += x1; x1 = TF_ROT(x1,15); x1 ^= x0;
    x0 += x1; x1 = TF_ROT(x1,26); x1 ^= x0;
    x0 += x1; x1 = TF_ROT(x1, 6); x1 ^= x0;
    x0 += ks2; x1 += k0 + 5u;
    *o0 = x0; *o1 = x1;
}

// ---------------- encoder: h0 = relu(x @ W_enc + b_enc) ----------------
__global__ void encoder_kernel(const float* __restrict__ x,
                               const float* __restrict__ W,
                               const float* __restrict__ b,
                               float* __restrict__ h0)
{
    int n = blockIdx.x;
    int d = threadIdx.x;           // 256
    __shared__ float xr[DF_];
    if (d < DF_) xr[d] = x[n * DF_ + d];
    __syncthreads();
    float acc = b[d];
#pragma unroll
    for (int k = 0; k < DF_; k++) acc = fmaf(xr[k], W[k * D_ + d], acc);
    h0[(size_t)n * D_ + d] = fmaxf(acc, 0.f);
}

__global__ void zero_anchor_kernel(int* __restrict__ anc)
{
    int idx = blockIdx.x * 256 + threadIdx.x;
    if (idx < M_ * N_) anc[idx] = 0;
}

// ---- weight split into tf32 big/small, permuted to mma B-frag order ----
// B-frag layout: flat = (((((by*8+ch)*4+wn)*4+nt)*4+k8)*32+lane)*2 + breg
// where n = by*128 + wn*32 + nt*8 + (lane>>2), k = ch*32 + k8*8 + (lane&3) + breg*4
__global__ void split_w_kernel(const float* __restrict__ gW1,
                               const float* __restrict__ gW2,
                               const float* __restrict__ Wn2n,
                               float* __restrict__ big,
                               float* __restrict__ small)
{
    int id = blockIdx.x;  // 0..10
    const float* W = (id < 5) ? gW1 + (size_t)id * 65536
                   : (id < 10) ? gW2 + (size_t)(id - 5) * 65536
                   : Wn2n;
    int base = blockIdx.y * 4096;
    for (int i = threadIdx.x; i < 4096; i += 256) {
        int idx = base + i;              // = k*256 + n
        int k = idx >> 8, n = idx & 255;
        float v = W[idx];
        float b = tf32r(v), s = tf32r(v - b);
        int by = n >> 7, wn = (n >> 5) & 3, nt = (n >> 3) & 3, lh = n & 7;
        int ch = k >> 5, k8 = (k >> 3) & 3, tg = k & 3, br = (k >> 2) & 1;
        int ln = lh * 4 + tg;
        size_t o = (size_t)id * 65536 +
            (size_t)((((((by * 8 + ch) * 4 + wn) * 4 + nt) * 4 + k8) * 32 + ln) * 2 + br);
        big[o] = b; small[o] = s;
    }
}

// ------- graph aggregation via count-matrix: z = (1+eps)*h + C @ h --------
#define AGG_SMEM ((64 * 256 + 64 * 64) * 4)
__global__ __launch_bounds__(256)
void agg_fast_kernel(const float* __restrict__ h,
                     const int* __restrict__ esrc, const int* __restrict__ edst,
                     const float* __restrict__ eps, int layer,
                     float* __restrict__ z)
{
    extern __shared__ float sm[];
    float* sH = sm;                 // 64 x 256
    float* sC = sm + 64 * 256;      // 64 x 64, dst-major
    int b = blockIdx.x, m = blockIdx.y;
    int tid = threadIdx.x;

    const float4* H4 = (const float4*)(h + ((size_t)m * N_ + (size_t)b * NPG_) * D_);
    float4* sH4 = (float4*)sH;
#pragma unroll
    for (int k = 0; k < 16; k++) sH4[tid + k * 256] = H4[tid + k * 256];
#pragma unroll
    for (int k = 0; k < 16; k++) sC[tid + k * 256] = 0.f;
    __syncthreads();

    int ebase = b * (NPG_ * DEG_);
#pragma unroll
    for (int k = 0; k < 2; k++) {
        int e = ebase + tid + k * 256;
        int s  = esrc[e] & (NPG_ - 1);
        int dd = edst[e] & (NPG_ - 1);
        atomicAdd(&sC[dd * 64 + s], 1.0f);
    }
    __syncthreads();

    float ep = 1.0f + eps[layer];
    int l = tid & 63;
    int g = tid >> 6;
    float4 acc[16];
#pragma unroll
    for (int i = 0; i < 16; i++) {
        float4 v = sH4[(g * 16 + i) * 64 + l];
        acc[i] = make_float4(ep * v.x, ep * v.y, ep * v.z, ep * v.w);
    }
#pragma unroll 4
    for (int j = 0; j < 64; j++) {
        float4 hj = make_float4(0.f, 0.f, 0.f, 0.f);
        bool loaded = false;
#pragma unroll
        for (int i = 0; i < 16; i++) {
            float c = sC[(g * 16 + i) * 64 + j];
            if (c != 0.f) {
                if (!loaded) { hj = sH4[j * 64 + l]; loaded = true; }
                acc[i].x = fmaf(c, hj.x, acc[i].x);
                acc[i].y = fmaf(c, hj.y, acc[i].y);
                acc[i].z = fmaf(c, hj.z, acc[i].z);
                acc[i].w = fmaf(c, hj.w, acc[i].w);
            }
        }
    }
    float4* Z4 = (float4*)(z + ((size_t)m * N_ + (size_t)b * NPG_) * D_);
#pragma unroll
    for (int i = 0; i < 16; i++)
        Z4[(g * 16 + i) * 64 + l] = acc[i];
}

// -------- 3xTF32 mma.sync GEMM: C = relu(A @ W^T + bias) ------------------
// Block: 128 rows x 128 cols. 8 warps (2m x 4n), warp tile 64x32.
// A smem: stride-36 rows (conflict-free frag LDS.32). B smem: frag-permuted.
#define GM_F_AB   0
#define GM_F_AS   (128 * 36)
#define GM_F_BB   (2 * 128 * 36)
#define GM_F_BS   (2 * 128 * 36 + 4096)
#define GM_F_BIAS (2 * 128 * 36 + 8192)
#define GM_SMEM_BYTES ((2 * 128 * 36 + 8192 + 128) * 4)

__global__ __launch_bounds__(256)
void gemm_mma(const float* __restrict__ A,
              const float* __restrict__ Bb_perm, const float* __restrict__ Bs_perm,
              const float* __restrict__ bias, float* __restrict__ C)
{
    extern __shared__ float sm[];
    float* sAb = sm + GM_F_AB;
    float* sAs = sm + GM_F_AS;
    float* sBb = sm + GM_F_BB;
    float* sBs = sm + GM_F_BS;
    float* sbias = sm + GM_F_BIAS;

    const int tid = threadIdx.x, lane = tid & 31, wid = tid >> 5;
    const int wm = wid >> 2, wn = wid & 3;
    const size_t row0 = (size_t)blockIdx.x * 128;
    const int by = blockIdx.y, col0 = by * 128;

    if (tid < 128) sbias[tid] = bias[col0 + tid];

    float acc[4][4][4];
#pragma unroll
    for (int mt = 0; mt < 4; mt++)
#pragma unroll
        for (int nt = 0; nt < 4; nt++)
#pragma unroll
            for (int r = 0; r < 4; r++) acc[mt][nt][r] = 0.f;

    const int R  = tid >> 1;
    const int kh = (tid & 1) * 16;
    const float* Arow = A + (row0 + R) * 256 + kh;
    const float4* gBb = (const float4*)(Bb_perm + (size_t)by * 8 * 4096);
    const float4* gBs = (const float4*)(Bs_perm + (size_t)by * 8 * 4096);

    // prefetch chunk 0
    float4 pa[4], pbb[4], pbs[4];
#pragma unroll
    for (int q = 0; q < 4; q++) {
        pa[q]  = *(const float4*)(Arow + q * 4);
        pbb[q] = gBb[tid + q * 256];
        pbs[q] = gBs[tid + q * 256];
    }

#pragma unroll 1
    for (int ch = 0; ch < 8; ch++) {
        if (ch) __syncthreads();
        // store A (split) at stride-36, and B (plain permuted copy)
#pragma unroll
        for (int q = 0; q < 4; q++) {
            float4 x = pa[q];
            float4 hb, hs;
            hb.x = tf32r(x.x); hs.x = tf32r(x.x - hb.x);
            hb.y = tf32r(x.y); hs.y = tf32r(x.y - hb.y);
            hb.z = tf32r(x.z); hs.z = tf32r(x.z - hb.z);
            hb.w = tf32r(x.w); hs.w = tf32r(x.w - hb.w);
            int kk = kh + q * 4;
            *(float4*)(sAb + R * 36 + kk) = hb;
            *(float4*)(sAs + R * 36 + kk) = hs;
            *(float4*)(sBb + (tid + q * 256) * 4) = pbb[q];
            *(float4*)(sBs + (tid + q * 256) * 4) = pbs[q];
        }
        __syncthreads();
        // prefetch next chunk (LDG issued now, consumed next iteration)
        if (ch < 7) {
#pragma unroll
            for (int q = 0; q < 4; q++) {
                pa[q]  = *(const float4*)(Arow + (ch + 1) * 32 + q * 4);
                pbb[q] = gBb[(ch + 1) * 1024 + tid + q * 256];
                pbs[q] = gBs[(ch + 1) * 1024 + tid + q * 256];
            }
        }
        // compute: 4 k8 steps
#pragma unroll
        for (int k8 = 0; k8 < 4; k8++) {
            uint32_t ab[4][4], as_[4][4];
#pragma unroll
            for (int mt = 0; mt < 4; mt++) {
                int o = (wm * 64 + mt * 16 + (lane >> 2)) * 36 + k8 * 8 + (lane & 3);
                ab[mt][0]  = __float_as_uint(sAb[o]);
                ab[mt][1]  = __float_as_uint(sAb[o + 8 * 36]);
                ab[mt][2]  = __float_as_uint(sAb[o + 4]);
                ab[mt][3]  = __float_as_uint(sAb[o + 8 * 36 + 4]);
                as_[mt][0] = __float_as_uint(sAs[o]);
                as_[mt][1] = __float_as_uint(sAs[o + 8 * 36]);
                as_[mt][2] = __float_as_uint(sAs[o + 4]);
                as_[mt][3] = __float_as_uint(sAs[o + 8 * 36 + 4]);
            }
            uint32_t bb[4][2], bs[4][2];
#pragma unroll
            for (int nt = 0; nt < 4; nt++) {
                int o = (((wn * 4 + nt) * 4 + k8) * 32 + lane) * 2;
                bb[nt][0] = __float_as_uint(sBb[o]);
                bb[nt][1] = __float_as_uint(sBb[o + 1]);
                bs[nt][0] = __float_as_uint(sBs[o]);
                bs[nt][1] = __float_as_uint(sBs[o + 1]);
            }
#pragma unroll
            for (int mt = 0; mt < 4; mt++)
#pragma unroll
                for (int nt = 0; nt < 4; nt++) {
                    MMA_TF32(acc[mt][nt], ab[mt], bb[nt]);
                    MMA_TF32(acc[mt][nt], ab[mt], bs[nt]);
                    MMA_TF32(acc[mt][nt], as_[mt], bb[nt]);
                }
        }
    }

    // epilogue: bias + relu, STG.64 pairs
#pragma unroll
    for (int mt = 0; mt < 4; mt++) {
        size_t rg = row0 + wm * 64 + mt * 16 + (lane >> 2);
#pragma unroll
        for (int nt = 0; nt < 4; nt++) {
            int cl = wn * 32 + nt * 8 + (lane & 3) * 2;
            float b0 = sbias[cl], b1 = sbias[cl + 1];
            float2 v0, v1;
            v0.x = fmaxf(acc[mt][nt][0] + b0, 0.f);
            v0.y = fmaxf(acc[mt][nt][1] + b1, 0.f);
            v1.x = fmaxf(acc[mt][nt][2] + b0, 0.f);
            v1.y = fmaxf(acc[mt][nt][3] + b1, 0.f);
            *(float2*)&C[rg * 256 + col0 + cl] = v0;
            *(float2*)&C[(rg + 8) * 256 + col0 + cl] = v1;
        }
    }
}

// ---------------- per-graph pairwise min distance (fp32) ----------------
#define MD_SMEM ((64 * 257 + 64 + 64) * 4)
__global__ __launch_bounds__(256)
void mindist_kernel(const float* __restrict__ h, float* __restrict__ mind)
{
    extern __shared__ float sm[];
    float* sh  = sm;
    float* ssq = sm + 64 * 257;
    int*   smn = (int*)(ssq + 64);
    int b = blockIdx.x, m = blockIdx.y;
    int tid = threadIdx.x;

    const float* H = h + ((size_t)m * N_ + (size_t)b * NPG_) * D_;
    for (int idx = tid; idx < NPG_ * D_; idx += 256) {
        int r = idx >> 8, d = idx & 255;
        sh[r * 257 + d] = H[idx];
    }
    if (tid < 64) smn[tid] = 0x7f7fffff;
    __syncthreads();

    if (tid < 64) {
        const float* row = sh + tid * 257;
        float s = 0.f;
        for (int d = 0; d < D_; d++) s = fmaf(row[d], row[d], s);
        ssq[tid] = s;
    }
    __syncthreads();

    int i  = tid >> 2;
    int j0 = (tid & 3) * 16;
    float acc[16];
#pragma unroll
    for (int jj = 0; jj < 16; jj++) acc[jj] = 0.f;
    const float* ri = sh + i * 257;
    for (int d = 0; d < D_; d++) {
        float a = ri[d];
#pragma unroll
        for (int jj = 0; jj < 16; jj++)
            acc[jj] = fmaf(a, sh[(j0 + jj) * 257 + d], acc[jj]);
    }
    float sqi = ssq[i];
    float lmin = 3.0e38f;
#pragma unroll
    for (int jj = 0; jj < 16; jj++) {
        int j = j0 + jj;
        float d2 = fmaxf(sqi + ssq[j] - 2.0f * acc[jj], 0.f);
        if (j == i) d2 += 1.0e9f;
        lmin = fminf(lmin, d2);
    }
    atomicMin(&smn[i], __float_as_int(lmin));
    __syncthreads();
    if (tid < 64)
        mind[(size_t)m * N_ + (size_t)b * NPG_ + tid] = __int_as_float(smn[tid]);
}

// ------------- gumbel sample + argmax + anchor set (exact JAX) -----------
__global__ void gumbel_kernel(const float* __restrict__ mind,
                              int* __restrict__ anchor,
                              int it, unsigned fk0, unsigned fk1,
                              int mind_stride_m)
{
    int b = blockIdx.x, m = blockIdx.y;
    int p = threadIdx.x;
    __shared__ float sg[NPG_];
    int node = m * N_ + b * NPG_ + p;

    unsigned o0, o1;
    tf2x32(fk0, fk1, 0u, (unsigned)node, &o0, &o1);
    unsigned bits = o0 ^ o1;
    float f = __uint_as_float((bits >> 9) | 0x3f800000u) - 1.0f;
    const float mn = 1e-9f;
    float u = fmaxf(mn, f * (1.0f - mn) + mn);
    float md = mind[(size_t)m * mind_stride_m + b * NPG_ + p];
    float logit = -md - 10.0f * (anchor[node] > 0 ? 1.0f : 0.0f);
    sg[p] = logit - logf(-logf(u));
    __syncthreads();
    if (p == 0) {
        int best = 0; float bv = sg[0];
        for (int q = 1; q < NPG_; q++)
            if (sg[q] > bv) { bv = sg[q]; best = q; }
        anchor[m * N_ + b * NPG_ + best] = it;
    }
}

// ---------------- xcur = tx * anchor_emb[anchor] + tx ----------------
__global__ void update_xcur_kernel(const float* __restrict__ h0,
                                   const int* __restrict__ anchor,
                                   const float* __restrict__ emb,
                                   float* __restrict__ xc)
{
    size_t idx = (size_t)blockIdx.x * 256 + threadIdx.x;
    size_t mn = idx >> 8;
    int d = (int)(idx & 255);
    int n = (int)(mn & (N_ - 1));
    int a = anchor[mn];
    float tv = h0[((size_t)n << 8) + d];
    xc[idx] = tv * emb[a * D_ + d] + tv;
}

// --------- finalize: per-m group mean -> dot W_pred -> mean over m --------
__global__ void finalize_kernel(const float* __restrict__ hn,
                                const float* __restrict__ Wp,
                                const float* __restrict__ bp,
                                float* __restrict__ out)
{
    int b = blockIdx.x;
    int d = threadIdx.x;
    __shared__ float g[M_][D_];
#pragma unroll
    for (int m = 0; m < M_; m++) {
        const float* base = hn + ((size_t)m * N_ + (size_t)b * NPG_) * D_ + d;
        float s = 0.f;
        for (int p = 0; p < NPG_; p++) s += base[(size_t)p * D_];
        g[m][d] = s * (1.0f / (float)NPG_);
    }
    __syncthreads();
    if (d < TASKS_) {
        float acc = 0.f;
#pragma unroll
        for (int m = 0; m < M_; m++) {
            float a = 0.f;
            for (int k = 0; k < D_; k++)
                a = fmaf(g[m][k], Wp[k * TASKS_ + d], a);
            acc += a + bp[d];
        }
        out[b * TASKS_ + d] = acc * (1.0f / (float)M_);
    }
}

// ---------------- host orchestration ----------------
extern "C" void kernel_launch(void* const* d_in, const int* in_sizes, int n_in,
                              void* d_out, int out_size)
{
    const float* x     = (const float*)d_in[0];
    const float* W_enc = (const float*)d_in[1];
    const float* b_enc = (const float*)d_in[2];
    const float* gW1   = (const float*)d_in[3];
    const float* gb1   = (const float*)d_in[4];
    const float* gW2   = (const float*)d_in[5];
    const float* gb2   = (const float*)d_in[6];
    const float* eps   = (const float*)d_in[7];
    const float* aemb  = (const float*)d_in[8];
    const float* Wn2n  = (const float*)d_in[9];
    const float* bn2n  = (const float*)d_in[10];
    const float* Wp    = (const float*)d_in[11];
    const float* bp    = (const float*)d_in[12];
    const int*   esrc  = (const int*)d_in[13];
    const int*   edst  = (const int*)d_in[14];
    float* out = (float*)d_out;

    float *h0, *xc, *hA, *z, *t, *mind, *wtb, *wts; int* anc;
    cudaGetSymbolAddress((void**)&h0,   g_h0);
    cudaGetSymbolAddress((void**)&xc,   g_xcur);
    cudaGetSymbolAddress((void**)&hA,   g_hA);
    cudaGetSymbolAddress((void**)&z,    g_z);
    cudaGetSymbolAddress((void**)&t,    g_t);
    cudaGetSymbolAddress((void**)&mind, g_mind);
    cudaGetSymbolAddress((void**)&anc,  g_anchor);
    cudaGetSymbolAddress((void**)&wtb,  g_wt_big);
    cudaGetSymbolAddress((void**)&wts,  g_wt_small);

    cudaFuncSetAttribute(agg_fast_kernel, cudaFuncAttributeMaxDynamicSharedMemorySize, AGG_SMEM);
    cudaFuncSetAttribute(mindist_kernel, cudaFuncAttributeMaxDynamicSharedMemorySize, MD_SMEM);
    cudaFuncSetAttribute(gemm_mma, cudaFuncAttributeMaxDynamicSharedMemorySize, GM_SMEM_BYTES);

    unsigned fk0[NA_ + 1], fk1[NA_ + 1];
    for (int i = 1; i <= NA_; i++)
        tf2x32(0u, 42u, 0u, (unsigned)i, &fk0[i], &fk1[i]);

    const dim3 graph_full(B_, M_), graph_q(B_, 1);
    const dim3 mma_full((M_ * N_) / 128, 2), mma_q(N_ / 128, 2);
    const int  bcast_blocks = (M_ * N_ * D_) / 256;

    auto WB = [&](int id) { return wtb + (size_t)id * 65536; };
    auto WS = [&](int id) { return wts + (size_t)id * 65536; };

    split_w_kernel<<<dim3(11, 16), 256>>>(gW1, gW2, Wn2n, wtb, wts);
    encoder_kernel<<<N_, 256>>>(x, W_enc, b_enc, h0);
    zero_anchor_kernel<<<(M_ * N_) / 256, 256>>>(anc);

    // ---- iteration 1: xcur broadcast of h0 -> compute once over N rows ----
    {
        const float* cur = h0;
        for (int l = 0; l < L_; l++) {
            agg_fast_kernel<<<graph_q, 256, AGG_SMEM>>>(cur, esrc, edst, eps, l, z);
            gemm_mma<<<mma_q, 256, GM_SMEM_BYTES>>>(z, WB(l), WS(l), gb1 + l * D_, t);
            gemm_mma<<<mma_q, 256, GM_SMEM_BYTES>>>(t, WB(5 + l), WS(5 + l), gb2 + l * D_, hA);
            cur = hA;
        }
        mindist_kernel<<<graph_q, 256, MD_SMEM>>>(hA, mind);
        gumbel_kernel<<<graph_full, 64>>>(mind, anc, 1, fk0[1], fk1[1], 0);
        update_xcur_kernel<<<bcast_blocks, 256>>>(h0, anc, aemb, xc);
    }

    // ---- iteration 2: full per-m pipeline ----
    {
        const float* cur = xc;
        for (int l = 0; l < L_; l++) {
            agg_fast_kernel<<<graph_full, 256, AGG_SMEM>>>(cur, esrc, edst, eps, l, z);
            gemm_mma<<<mma_full, 256, GM_SMEM_BYTES>>>(z, WB(l), WS(l), gb1 + l * D_, t);
            gemm_mma<<<mma_full, 256, GM_SMEM_BYTES>>>(t, WB(5 + l), WS(5 + l), gb2 + l * D_, hA);
            cur = hA;
        }
        mindist_kernel<<<graph_full, 256, MD_SMEM>>>(hA, mind);
        gumbel_kernel<<<graph_full, 64>>>(mind, anc, 2, fk0[2], fk1[2], N_);
        update_xcur_kernel<<<bcast_blocks, 256>>>(h0, anc, aemb, xc);
    }

    // ---- final GNN on xcur ----
    {
        const float* cur = xc;
        for (int l = 0; l < L_; l++) {
            agg_fast_kernel<<<graph_full, 256, AGG_SMEM>>>(cur, esrc, edst, eps, l, z);
            gemm_mma<<<mma_full, 256, GM_SMEM_BYTES>>>(z, WB(l), WS(l), gb1 + l * D_, t);
            gemm_mma<<<mma_full, 256, GM_SMEM_BYTES>>>(t, WB(5 + l), WS(5 + l), gb2 + l * D_, hA);
            cur = hA;
        }
    }
    gemm_mma<<<mma_full, 256, GM_SMEM_BYTES>>>(hA, WB(10), WS(10), bn2n, t);
    finalize_kernel<<<B_, 256>>>(t, Wp, bp, out);
}

// round 11
// speedup vs baseline: 2.1876x; 1.0843x over previous
#include <cuda_runtime.h>
#include <cstdint>

// ---------------- problem constants ----------------
#define M_     4
#define B_     256
#define NPG_   64
#define N_     16384
#define DEG_   8
#define E_     131072
#define DF_    16
#define D_     256
#define L_     5
#define NA_    2
#define TASKS_ 10

// ---------------- device scratch (no allocs allowed) ----------------
__device__ float g_h0[(size_t)N_ * D_];            // 16 MB
__device__ float g_xcur[(size_t)M_ * N_ * D_];     // 64 MB
__device__ float g_hA[(size_t)M_ * N_ * D_];       // 64 MB
__device__ float g_t[(size_t)M_ * N_ * D_];        // 64 MB
__device__ float g_mind[(size_t)M_ * N_];
__device__ int   g_anchor[(size_t)M_ * N_];
// pre-split, frag-permuted weights: [11][65536]
__device__ float g_wt_big[11 * 65536];
__device__ float g_wt_small[11 * 65536];
// static per-graph dedup'd adjacency CSR (counts): entry = src | (cnt<<8)
__device__ int   g_csr_ent[B_ * 512];
__device__ int   g_csr_off[B_ * 65];

static __device__ __forceinline__ float tf32r(float x) {
    float r;
    asm("cvt.rna.tf32.f32 %0, %1;" : "=f"(r) : "f"(x));
    return r;
}

// m16n8k8 tf32 mma (sm_80+ PTX, works on base compute_103 target)
#define MMA_TF32(d, a, b) \
    asm volatile("mma.sync.aligned.m16n8k8.row.col.f32.tf32.tf32.f32 " \
                 "{%0,%1,%2,%3}, {%4,%5,%6,%7}, {%8,%9}, {%0,%1,%2,%3};" \
                 : "+f"((d)[0]), "+f"((d)[1]), "+f"((d)[2]), "+f"((d)[3]) \
                 : "r"((a)[0]), "r"((a)[1]), "r"((a)[2]), "r"((a)[3]), \
                   "r"((b)[0]), "r"((b)[1]))

// ---------------- threefry2x32 (exact JAX rounds) ----------------
#define TF_ROT(x,d) (((x) << (d)) | ((x) >> (32 - (d))))
static __host__ __device__ __forceinline__
void tf2x32(unsigned k0, unsigned k1, unsigned x0, unsigned x1,
            unsigned* o0, unsigned* o1)
{
    unsigned ks2 = k0 ^ k1 ^ 0x1BD11BDAu;
    x0 += k0; x1 += k1;
    x0 += x1; x1 = TF_ROT(x1,13); x1 ^= x0;
    x0 += x1; x1 = TF_ROT(x1,15); x1 ^= x0;
    x0 += x1; x1 = TF_ROT(x1,26); x1 ^= x0;
    x0 += x1; x1 = TF_ROT(x1, 6); x1 ^= x0;
    x0 += k1; x1 += ks2 + 1u;
    x0 += x1; x1 = TF_ROT(x1,17); x1 ^= x0;
    x0 += x1; x1 = TF_ROT(x1,29); x1 ^= x0;
    x0 += x1; x1 = TF_ROT(x1,16); x1 ^= x0;
    x0 += x1; x1 = TF_ROT(x1,24); x1 ^= x0;
    x0 += ks2; x1 += k0 + 2u;
    x0 += x1; x1 = TF_ROT(x1,13); x1 ^= x0;
    x0 += x1; x1 = TF_ROT(x1,15); x1 ^= x0;
    x0 += x1; x1 = TF_ROT(x1,26); x1 ^= x0;
    x0 += x1; x1 = TF_ROT(x1, 6); x1 ^= x0;
    x0 += k0; x1 += k1 + 3u;
    x0 += x1; x1 = TF_ROT(x1,17); x1 ^= x0;
    x0 += x1; x1 = TF_ROT(x1,29); x1 ^= x0;
    x0 += x1; x1 = TF_ROT(x1,16); x1 ^= x0;
    x0 += x1; x1 = TF_ROT(x1,24); x1 ^= x0;
    x0 += k1; x1 += ks2 + 4u;
    x0 += x1; x1 = TF_ROT(x1,13); x1 ^= x0;
    x0 += x1; x1 = TF_ROT(x1,15); x1 ^= x0;
    x0 += x1; x1 = TF_ROT(x1,26); x1 ^= x0;
    x0 += x1; x1 = TF_ROT(x1, 6); x1 ^= x0;
    x0 += ks2; x1 += k0 + 5u;
    *o0 = x0; *o1 = x1;
}

// ---------------- encoder: h0 = relu(x @ W_enc + b_enc) ----------------
__global__ void encoder_kernel(const float* __restrict__ x,
                               const float* __restrict__ W,
                               const float* __restrict__ b,
                               float* __restrict__ h0)
{
    int n = blockIdx.x;
    int d = threadIdx.x;           // 256
    __shared__ float xr[DF_];
    if (d < DF_) xr[d] = x[n * DF_ + d];
    __syncthreads();
    float acc = b[d];
#pragma unroll
    for (int k = 0; k < DF_; k++) acc = fmaf(xr[k], W[k * D_ + d], acc);
    h0[(size_t)n * D_ + d] = fmaxf(acc, 0.f);
}

__global__ void zero_anchor_kernel(int* __restrict__ anc)
{
    int idx = blockIdx.x * 256 + threadIdx.x;
    if (idx < M_ * N_) anc[idx] = 0;
}

// ----- build per-graph dedup'd CSR once (edges are static) -----
__global__ void prep_csr_kernel(const int* __restrict__ esrc,
                                const int* __restrict__ edst,
                                int* __restrict__ ent, int* __restrict__ off)
{
    __shared__ int cnt[64 * 64];
    __shared__ int nnz[64], base[65];
    int g = blockIdx.x, tid = threadIdx.x;     // 256 threads
    for (int i = tid; i < 4096; i += 256) cnt[i] = 0;
    __syncthreads();
    int eb = g * 512;
#pragma unroll
    for (int k = 0; k < 2; k++) {
        int e = eb + tid + k * 256;
        int s = esrc[e] & 63, d = edst[e] & 63;
        atomicAdd(&cnt[d * 64 + s], 1);
    }
    __syncthreads();
    if (tid < 64) {
        int c = 0;
        for (int s = 0; s < 64; s++) c += (cnt[tid * 64 + s] != 0);
        nnz[tid] = c;
    }
    __syncthreads();
    if (tid == 0) {
        int a = 0;
        for (int d = 0; d < 64; d++) { base[d] = a; a += nnz[d]; }
        base[64] = a;
    }
    __syncthreads();
    if (tid < 64) {
        int o = base[tid];
        for (int s = 0; s < 64; s++) {
            int c = cnt[tid * 64 + s];
            if (c) ent[g * 512 + (o++)] = s | (c << 8);
        }
        off[g * 65 + tid] = base[tid];
        if (tid == 0) off[g * 65 + 64] = base[64];
    }
}

// ---- weight split into tf32 big/small, permuted to mma B-frag order ----
__global__ void split_w_kernel(const float* __restrict__ gW1,
                               const float* __restrict__ gW2,
                               const float* __restrict__ Wn2n,
                               float* __restrict__ big,
                               float* __restrict__ small)
{
    int id = blockIdx.x;  // 0..10
    const float* W = (id < 5) ? gW1 + (size_t)id * 65536
                   : (id < 10) ? gW2 + (size_t)(id - 5) * 65536
                   : Wn2n;
    int base = blockIdx.y * 4096;
    for (int i = threadIdx.x; i < 4096; i += 256) {
        int idx = base + i;              // = k*256 + n
        int k = idx >> 8, n = idx & 255;
        float v = W[idx];
        float b = tf32r(v), s = tf32r(v - b);
        int by = n >> 7, wn = (n >> 5) & 3, nt = (n >> 3) & 3, lh = n & 7;
        int ch = k >> 5, k8 = (k >> 3) & 3, tg = k & 3, br = (k >> 2) & 1;
        int ln = lh * 4 + tg;
        size_t o = (size_t)id * 65536 +
            (size_t)((((((by * 8 + ch) * 4 + wn) * 4 + nt) * 4 + k8) * 32 + ln) * 2 + br);
        big[o] = b; small[o] = s;
    }
}

// ===================== shared GEMM machinery =====================
// Block: 128 rows x 128 cols. 8 warps (2m x 4n), warp tile 64x32.
// A smem: stride-36 rows. B smem: frag-permuted (copied from global).
// FUSED=1 additionally computes z = (1+eps)*h + CSR-agg on the fly.

#define GA_F_AB   0
#define GA_F_AS   (128 * 36)
#define GA_F_H    (2 * 128 * 36)
#define GA_F_BB   (3 * 128 * 36)
#define GA_F_BS   (3 * 128 * 36 + 4096)
#define GA_F_BIAS (3 * 128 * 36 + 8192)
#define GA_F_ENT  (3 * 128 * 36 + 8192 + 128)         // 1024 ints
#define GA_F_OFF  (3 * 128 * 36 + 8192 + 128 + 1024)  // 130 ints
#define GA_SMEM_BYTES ((3 * 128 * 36 + 8192 + 128 + 1024 + 132) * 4)

template <int FUSED>
__device__ __forceinline__
void gemm_body(const float* __restrict__ A,
               const float* __restrict__ Bb_perm, const float* __restrict__ Bs_perm,
               const float* __restrict__ bias, float* __restrict__ C,
               const int* __restrict__ ent, const int* __restrict__ off,
               const float* __restrict__ eps, int layer)
{
    extern __shared__ float sm[];
    float* sAb = sm + GA_F_AB;
    float* sAs = sm + GA_F_AS;
    float* sH  = sm + GA_F_H;
    float* sBb = sm + GA_F_BB;
    float* sBs = sm + GA_F_BS;
    float* sbias = sm + GA_F_BIAS;
    int* sEnt = (int*)(sm + GA_F_ENT);
    int* sOff = (int*)(sm + GA_F_OFF);

    const int tid = threadIdx.x, lane = tid & 31, wid = tid >> 5;
    const int wm = wid >> 2, wn = wid & 3;
    const size_t row0 = (size_t)blockIdx.x * 128;
    const int by = blockIdx.y, col0 = by * 128;

    if (tid < 128) sbias[tid] = bias[col0 + tid];

    int nb_st = 0, nb_en = 0, gR = 0;
    float ep = 0.f;
    if (FUSED) {
        int g0 = (int)((row0 & (N_ - 1)) >> 6);      // 2 graphs: g0, g0+1
        for (int i = tid; i < 1024; i += 256)
            sEnt[i] = ent[(size_t)g0 * 512 + ((i >> 9) ? 512 - 512 : 0) +
                          (i & 511) + (i >> 9) * 512];
        if (tid < 130) {
            int gg = tid / 65;
            sOff[tid] = off[(size_t)(g0 + gg) * 65 + (tid - gg * 65)];
        }
        ep = 1.0f + eps[layer];
        __syncthreads();
        int R_ = tid >> 1;
        gR = R_ >> 6;
        int dloc = R_ & 63;
        nb_st = sOff[gR * 65 + dloc];
        nb_en = sOff[gR * 65 + dloc + 1];
    }

    float acc[4][4][4];
#pragma unroll
    for (int mt = 0; mt < 4; mt++)
#pragma unroll
        for (int nt = 0; nt < 4; nt++)
#pragma unroll
            for (int r = 0; r < 4; r++) acc[mt][nt][r] = 0.f;

    const int R  = tid >> 1;
    const int kh = (tid & 1) * 16;
    const float* Arow = A + (row0 + R) * 256 + kh;
    const float4* gBb = (const float4*)(Bb_perm + (size_t)by * 8 * 4096);
    const float4* gBs = (const float4*)(Bs_perm + (size_t)by * 8 * 4096);

    float4 pa[4], pbb[4], pbs[4];
#pragma unroll
    for (int q = 0; q < 4; q++) {
        pa[q]  = *(const float4*)(Arow + q * 4);
        pbb[q] = gBb[tid + q * 256];
        pbs[q] = gBs[tid + q * 256];
    }

#pragma unroll 1
    for (int ch = 0; ch < 8; ch++) {
        if (ch) __syncthreads();
        if (FUSED) {
            // stage raw H chunk + B copies
#pragma unroll
            for (int q = 0; q < 4; q++) {
                *(float4*)(sH + R * 36 + kh + q * 4) = pa[q];
                *(float4*)(sBb + (tid + q * 256) * 4) = pbb[q];
                *(float4*)(sBs + (tid + q * 256) * 4) = pbs[q];
            }
            __syncthreads();
            // z = (1+eps)*own + sum cnt * H[src]  (16 cols of row R)
            float4 zv[4];
#pragma unroll
            for (int q = 0; q < 4; q++) {
                zv[q].x = ep * pa[q].x; zv[q].y = ep * pa[q].y;
                zv[q].z = ep * pa[q].z; zv[q].w = ep * pa[q].w;
            }
            for (int e = nb_st; e < nb_en; e++) {
                int u = sEnt[gR * 512 + e];
                int src = u & 63;
                float c = (float)(u >> 8);
                const float* hr = sH + (gR * 64 + src) * 36 + kh;
#pragma unroll
                for (int q = 0; q < 4; q++) {
                    float4 hv = *(const float4*)(hr + q * 4);
                    zv[q].x = fmaf(c, hv.x, zv[q].x);
                    zv[q].y = fmaf(c, hv.y, zv[q].y);
                    zv[q].z = fmaf(c, hv.z, zv[q].z);
                    zv[q].w = fmaf(c, hv.w, zv[q].w);
                }
            }
#pragma unroll
            for (int q = 0; q < 4; q++) {
                float4 hb, hs;
                hb.x = tf32r(zv[q].x); hs.x = tf32r(zv[q].x - hb.x);
                hb.y = tf32r(zv[q].y); hs.y = tf32r(zv[q].y - hb.y);
                hb.z = tf32r(zv[q].z); hs.z = tf32r(zv[q].z - hb.z);
                hb.w = tf32r(zv[q].w); hs.w = tf32r(zv[q].w - hb.w);
                *(float4*)(sAb + R * 36 + kh + q * 4) = hb;
                *(float4*)(sAs + R * 36 + kh + q * 4) = hs;
            }
        } else {
#pragma unroll
            for (int q = 0; q < 4; q++) {
                float4 x = pa[q];
                float4 hb, hs;
                hb.x = tf32r(x.x); hs.x = tf32r(x.x - hb.x);
                hb.y = tf32r(x.y); hs.y = tf32r(x.y - hb.y);
                hb.z = tf32r(x.z); hs.z = tf32r(x.z - hb.z);
                hb.w = tf32r(x.w); hs.w = tf32r(x.w - hb.w);
                *(float4*)(sAb + R * 36 + kh + q * 4) = hb;
                *(float4*)(sAs + R * 36 + kh + q * 4) = hs;
                *(float4*)(sBb + (tid + q * 256) * 4) = pbb[q];
                *(float4*)(sBs + (tid + q * 256) * 4) = pbs[q];
            }
        }
        __syncthreads();
        if (ch < 7) {
#pragma unroll
            for (int q = 0; q < 4; q++) {
                pa[q]  = *(const float4*)(Arow + (ch + 1) * 32 + q * 4);
                pbb[q] = gBb[(ch + 1) * 1024 + tid + q * 256];
                pbs[q] = gBs[(ch + 1) * 1024 + tid + q * 256];
            }
        }
#pragma unroll
        for (int k8 = 0; k8 < 4; k8++) {
            uint32_t ab[4][4], as_[4][4];
#pragma unroll
            for (int mt = 0; mt < 4; mt++) {
                int o = (wm * 64 + mt * 16 + (lane >> 2)) * 36 + k8 * 8 + (lane & 3);
                ab[mt][0]  = __float_as_uint(sAb[o]);
                ab[mt][1]  = __float_as_uint(sAb[o + 8 * 36]);
                ab[mt][2]  = __float_as_uint(sAb[o + 4]);
                ab[mt][3]  = __float_as_uint(sAb[o + 8 * 36 + 4]);
                as_[mt][0] = __float_as_uint(sAs[o]);
                as_[mt][1] = __float_as_uint(sAs[o + 8 * 36]);
                as_[mt][2] = __float_as_uint(sAs[o + 4]);
                as_[mt][3] = __float_as_uint(sAs[o + 8 * 36 + 4]);
            }
            uint32_t bb[4][2], bs[4][2];
#pragma unroll
            for (int nt = 0; nt < 4; nt++) {
                int o = (((wn * 4 + nt) * 4 + k8) * 32 + lane) * 2;
                bb[nt][0] = __float_as_uint(sBb[o]);
                bb[nt][1] = __float_as_uint(sBb[o + 1]);
                bs[nt][0] = __float_as_uint(sBs[o]);
                bs[nt][1] = __float_as_uint(sBs[o + 1]);
            }
#pragma unroll
            for (int mt = 0; mt < 4; mt++)
#pragma unroll
                for (int nt = 0; nt < 4; nt++) {
                    MMA_TF32(acc[mt][nt], ab[mt], bb[nt]);
                    MMA_TF32(acc[mt][nt], ab[mt], bs[nt]);
                    MMA_TF32(acc[mt][nt], as_[mt], bb[nt]);
                }
        }
    }

#pragma unroll
    for (int mt = 0; mt < 4; mt++) {
        size_t rg = row0 + wm * 64 + mt * 16 + (lane >> 2);
#pragma unroll
        for (int nt = 0; nt < 4; nt++) {
            int cl = wn * 32 + nt * 8 + (lane & 3) * 2;
            float b0 = sbias[cl], b1 = sbias[cl + 1];
            float2 v0, v1;
            v0.x = fmaxf(acc[mt][nt][0] + b0, 0.f);
            v0.y = fmaxf(acc[mt][nt][1] + b1, 0.f);
            v1.x = fmaxf(acc[mt][nt][2] + b0, 0.f);
            v1.y = fmaxf(acc[mt][nt][3] + b1, 0.f);
            *(float2*)&C[rg * 256 + col0 + cl] = v0;
            *(float2*)&C[(rg + 8) * 256 + col0 + cl] = v1;
        }
    }
}

__global__ __launch_bounds__(256)
void gemm_mma(const float* __restrict__ A,
              const float* __restrict__ Bb, const float* __restrict__ Bs,
              const float* __restrict__ bias, float* __restrict__ C)
{
    gemm_body<0>(A, Bb, Bs, bias, C, nullptr, nullptr, nullptr, 0);
}

__global__ __launch_bounds__(256)
void gemm_mma_agg(const float* __restrict__ A,
                  const float* __restrict__ Bb, const float* __restrict__ Bs,
                  const float* __restrict__ bias, float* __restrict__ C,
                  const int* __restrict__ ent, const int* __restrict__ off,
                  const float* __restrict__ eps, int layer)
{
    gemm_body<1>(A, Bb, Bs, bias, C, ent, off, eps, layer);
}

// ---------------- per-graph pairwise min distance (fp32) ----------------
#define MD_SMEM ((64 * 257 + 64 + 64) * 4)
__global__ __launch_bounds__(256)
void mindist_kernel(const float* __restrict__ h, float* __restrict__ mind)
{
    extern __shared__ float sm[];
    float* sh  = sm;
    float* ssq = sm + 64 * 257;
    int*   smn = (int*)(ssq + 64);
    int b = blockIdx.x, m = blockIdx.y;
    int tid = threadIdx.x;

    const float* H = h + ((size_t)m * N_ + (size_t)b * NPG_) * D_;
    for (int idx = tid; idx < NPG_ * D_; idx += 256) {
        int r = idx >> 8, d = idx & 255;
        sh[r * 257 + d] = H[idx];
    }
    if (tid < 64) smn[tid] = 0x7f7fffff;
    __syncthreads();

    if (tid < 64) {
        const float* row = sh + tid * 257;
        float s = 0.f;
        for (int d = 0; d < D_; d++) s = fmaf(row[d], row[d], s);
        ssq[tid] = s;
    }
    __syncthreads();

    int i  = tid >> 2;
    int j0 = (tid & 3) * 16;
    float acc[16];
#pragma unroll
    for (int jj = 0; jj < 16; jj++) acc[jj] = 0.f;
    const float* ri = sh + i * 257;
    for (int d = 0; d < D_; d++) {
        float a = ri[d];
#pragma unroll
        for (int jj = 0; jj < 16; jj++)
            acc[jj] = fmaf(a, sh[(j0 + jj) * 257 + d], acc[jj]);
    }
    float sqi = ssq[i];
    float lmin = 3.0e38f;
#pragma unroll
    for (int jj = 0; jj < 16; jj++) {
        int j = j0 + jj;
        float d2 = fmaxf(sqi + ssq[j] - 2.0f * acc[jj], 0.f);
        if (j == i) d2 += 1.0e9f;
        lmin = fminf(lmin, d2);
    }
    atomicMin(&smn[i], __float_as_int(lmin));
    __syncthreads();
    if (tid < 64)
        mind[(size_t)m * N_ + (size_t)b * NPG_ + tid] = __int_as_float(smn[tid]);
}

// ------------- gumbel sample + argmax + anchor set (exact JAX) -----------
__global__ void gumbel_kernel(const float* __restrict__ mind,
                              int* __restrict__ anchor,
                              int it, unsigned fk0, unsigned fk1,
                              int mind_stride_m)
{
    int b = blockIdx.x, m = blockIdx.y;
    int p = threadIdx.x;
    __shared__ float sg[NPG_];
    int node = m * N_ + b * NPG_ + p;

    unsigned o0, o1;
    tf2x32(fk0, fk1, 0u, (unsigned)node, &o0, &o1);
    unsigned bits = o0 ^ o1;
    float f = __uint_as_float((bits >> 9) | 0x3f800000u) - 1.0f;
    const float mn = 1e-9f;
    float u = fmaxf(mn, f * (1.0f - mn) + mn);
    float md = mind[(size_t)m * mind_stride_m + b * NPG_ + p];
    float logit = -md - 10.0f * (anchor[node] > 0 ? 1.0f : 0.0f);
    sg[p] = logit - logf(-logf(u));
    __syncthreads();
    if (p == 0) {
        int best = 0; float bv = sg[0];
        for (int q = 1; q < NPG_; q++)
            if (sg[q] > bv) { bv = sg[q]; best = q; }
        anchor[m * N_ + b * NPG_ + best] = it;
    }
}

// ---------------- xcur = tx * anchor_emb[anchor] + tx ----------------
__global__ void update_xcur_kernel(const float* __restrict__ h0,
                                   const int* __restrict__ anchor,
                                   const float* __restrict__ emb,
                                   float* __restrict__ xc)
{
    size_t idx = (size_t)blockIdx.x * 256 + threadIdx.x;
    size_t mn = idx >> 8;
    int d = (int)(idx & 255);
    int n = (int)(mn & (N_ - 1));
    int a = anchor[mn];
    float tv = h0[((size_t)n << 8) + d];
    xc[idx] = tv * emb[a * D_ + d] + tv;
}

// --------- finalize: per-m group mean -> dot W_pred -> mean over m --------
__global__ void finalize_kernel(const float* __restrict__ hn,
                                const float* __restrict__ Wp,
                                const float* __restrict__ bp,
                                float* __restrict__ out)
{
    int b = blockIdx.x;
    int d = threadIdx.x;
    __shared__ float g[M_][D_];
#pragma unroll
    for (int m = 0; m < M_; m++) {
        const float* base = hn + ((size_t)m * N_ + (size_t)b * NPG_) * D_ + d;
        float s = 0.f;
        for (int p = 0; p < NPG_; p++) s += base[(size_t)p * D_];
        g[m][d] = s * (1.0f / (float)NPG_);
    }
    __syncthreads();
    if (d < TASKS_) {
        float acc = 0.f;
#pragma unroll
        for (int m = 0; m < M_; m++) {
            float a = 0.f;
            for (int k = 0; k < D_; k++)
                a = fmaf(g[m][k], Wp[k * TASKS_ + d], a);
            acc += a + bp[d];
        }
        out[b * TASKS_ + d] = acc * (1.0f / (float)M_);
    }
}

// ---------------- host orchestration ----------------
extern "C" void kernel_launch(void* const* d_in, const int* in_sizes, int n_in,
                              void* d_out, int out_size)
{
    const float* x     = (const float*)d_in[0];
    const float* W_enc = (const float*)d_in[1];
    const float* b_enc = (const float*)d_in[2];
    const float* gW1   = (const float*)d_in[3];
    const float* gb1   = (const float*)d_in[4];
    const float* gW2   = (const float*)d_in[5];
    const float* gb2   = (const float*)d_in[6];
    const float* eps   = (const float*)d_in[7];
    const float* aemb  = (const float*)d_in[8];
    const float* Wn2n  = (const float*)d_in[9];
    const float* bn2n  = (const float*)d_in[10];
    const float* Wp    = (const float*)d_in[11];
    const float* bp    = (const float*)d_in[12];
    const int*   esrc  = (const int*)d_in[13];
    const int*   edst  = (const int*)d_in[14];
    float* out = (float*)d_out;

    float *h0, *xc, *hA, *t, *mind, *wtb, *wts; int *anc, *ent, *off;
    cudaGetSymbolAddress((void**)&h0,   g_h0);
    cudaGetSymbolAddress((void**)&xc,   g_xcur);
    cudaGetSymbolAddress((void**)&hA,   g_hA);
    cudaGetSymbolAddress((void**)&t,    g_t);
    cudaGetSymbolAddress((void**)&mind, g_mind);
    cudaGetSymbolAddress((void**)&anc,  g_anchor);
    cudaGetSymbolAddress((void**)&wtb,  g_wt_big);
    cudaGetSymbolAddress((void**)&wts,  g_wt_small);
    cudaGetSymbolAddress((void**)&ent,  g_csr_ent);
    cudaGetSymbolAddress((void**)&off,  g_csr_off);

    cudaFuncSetAttribute(mindist_kernel, cudaFuncAttributeMaxDynamicSharedMemorySize, MD_SMEM);
    cudaFuncSetAttribute(gemm_mma, cudaFuncAttributeMaxDynamicSharedMemorySize, GA_SMEM_BYTES);
    cudaFuncSetAttribute(gemm_mma_agg, cudaFuncAttributeMaxDynamicSharedMemorySize, GA_SMEM_BYTES);

    unsigned fk0[NA_ + 1], fk1[NA_ + 1];
    for (int i = 1; i <= NA_; i++)
        tf2x32(0u, 42u, 0u, (unsigned)i, &fk0[i], &fk1[i]);

    const dim3 graph_full(B_, M_), graph_q(B_, 1);
    const dim3 mma_full((M_ * N_) / 128, 2), mma_q(N_ / 128, 2);
    const int  bcast_blocks = (M_ * N_ * D_) / 256;

    auto WB = [&](int id) { return wtb + (size_t)id * 65536; };
    auto WS = [&](int id) { return wts + (size_t)id * 65536; };

    prep_csr_kernel<<<B_, 256>>>(esrc, edst, ent, off);
    split_w_kernel<<<dim3(11, 16), 256>>>(gW1, gW2, Wn2n, wtb, wts);
    encoder_kernel<<<N_, 256>>>(x, W_enc, b_enc, h0);
    zero_anchor_kernel<<<(M_ * N_) / 256, 256>>>(anc);

    // ---- iteration 1: xcur broadcast of h0 -> compute once over N rows ----
    {
        const float* cur = h0;
        for (int l = 0; l < L_; l++) {
            gemm_mma_agg<<<mma_q, 256, GA_SMEM_BYTES>>>(
                cur, WB(l), WS(l), gb1 + l * D_, t, ent, off, eps, l);
            gemm_mma<<<mma_q, 256, GA_SMEM_BYTES>>>(t, WB(5 + l), WS(5 + l), gb2 + l * D_, hA);
            cur = hA;
        }
        mindist_kernel<<<graph_q, 256, MD_SMEM>>>(hA, mind);
        gumbel_kernel<<<graph_full, 64>>>(mind, anc, 1, fk0[1], fk1[1], 0);
        update_xcur_kernel<<<bcast_blocks, 256>>>(h0, anc, aemb, xc);
    }

    // ---- iteration 2: full per-m pipeline ----
    {
        const float* cur = xc;
        for (int l = 0; l < L_; l++) {
            gemm_mma_agg<<<mma_full, 256, GA_SMEM_BYTES>>>(
                cur, WB(l), WS(l), gb1 + l * D_, t, ent, off, eps, l);
            gemm_mma<<<mma_full, 256, GA_SMEM_BYTES>>>(t, WB(5 + l), WS(5 + l), gb2 + l * D_, hA);
            cur = hA;
        }
        mindist_kernel<<<graph_full, 256, MD_SMEM>>>(hA, mind);
        gumbel_kernel<<<graph_full, 64>>>(mind, anc, 2, fk0[2], fk1[2], N_);
        update_xcur_kernel<<<bcast_blocks, 256>>>(h0, anc, aemb, xc);
    }

    // ---- final GNN on xcur ----
    {
        const float* cur = xc;
        for (int l = 0; l < L_; l++) {
            gemm_mma_agg<<<mma_full, 256, GA_SMEM_BYTES>>>(
                cur, WB(l), WS(l), gb1 + l * D_, t, ent, off, eps, l);
            gemm_mma<<<mma_full, 256, GA_SMEM_BYTES>>>(t, WB(5 + l), WS(5 + l), gb2 + l * D_, hA);
            cur = hA;
        }
    }
    gemm_mma<<<mma_full, 256, GA_SMEM_BYTES>>>(hA, WB(10), WS(10), bn2n, t);
    finalize_kernel<<<B_, 256>>>(t, Wp, bp, out);
}

// round 12
// speedup vs baseline: 2.4909x; 1.1386x over previous
#include <cuda_runtime.h>
#include <cstdint>

// ---------------- problem constants ----------------
#define M_     4
#define B_     256
#define NPG_   64
#define N_     16384
#define DEG_   8
#define E_     131072
#define DF_    16
#define D_     256
#define L_     5
#define NA_    2
#define TASKS_ 10

// ---------------- device scratch (no allocs allowed) ----------------
__device__ float g_h0[(size_t)N_ * D_];            // 16 MB
__device__ float g_xcur[(size_t)M_ * N_ * D_];     // 64 MB
__device__ float g_hA[(size_t)M_ * N_ * D_];       // 64 MB
__device__ float g_t[(size_t)M_ * N_ * D_];        // 64 MB
__device__ float g_mind[(size_t)M_ * N_];
__device__ int   g_anchor[(size_t)M_ * N_];
// pre-split, frag-permuted weights: [11][65536]
__device__ float g_wt_big[11 * 65536];
__device__ float g_wt_small[11 * 65536];
// static per-graph dedup'd adjacency CSR (counts): entry = src | (cnt<<8)
__device__ int   g_csr_ent[B_ * 512];
__device__ int   g_csr_off[B_ * 65];

static __device__ __forceinline__ float tf32r(float x) {
    float r;
    asm("cvt.rna.tf32.f32 %0, %1;" : "=f"(r) : "f"(x));
    return r;
}

// m16n8k8 tf32 mma (sm_80+ PTX, works on base compute_103 target)
#define MMA_TF32(d, a, b) \
    asm volatile("mma.sync.aligned.m16n8k8.row.col.f32.tf32.tf32.f32 " \
                 "{%0,%1,%2,%3}, {%4,%5,%6,%7}, {%8,%9}, {%0,%1,%2,%3};" \
                 : "+f"((d)[0]), "+f"((d)[1]), "+f"((d)[2]), "+f"((d)[3]) \
                 : "r"((a)[0]), "r"((a)[1]), "r"((a)[2]), "r"((a)[3]), \
                   "r"((b)[0]), "r"((b)[1]))

// ---------------- threefry2x32 (exact JAX rounds) ----------------
#define TF_ROT(x,d) (((x) << (d)) | ((x) >> (32 - (d))))
static __host__ __device__ __forceinline__
void tf2x32(unsigned k0, unsigned k1, unsigned x0, unsigned x1,
            unsigned* o0, unsigned* o1)
{
    unsigned ks2 = k0 ^ k1 ^ 0x1BD11BDAu;
    x0 += k0; x1 += k1;
    x0 += x1; x1 = TF_ROT(x1,13); x1 ^= x0;
    x0 += x1; x1 = TF_ROT(x1,15); x1 ^= x0;
    x0 += x1; x1 = TF_ROT(x1,26); x1 ^= x0;
    x0 += x1; x1 = TF_ROT(x1, 6); x1 ^= x0;
    x0 += k1; x1 += ks2 + 1u;
    x0 += x1; x1 = TF_ROT(x1,17); x1 ^= x0;
    x0 += x1; x1 = TF_ROT(x1,29); x1 ^= x0;
    x0 += x1; x1 = TF_ROT(x1,16); x1 ^= x0;
    x0 += x1; x1 = TF_ROT(x1,24); x1 ^= x0;
    x0 += ks2; x1 += k0 + 2u;
    x0 += x1; x1 = TF_ROT(x1,13); x1 ^= x0;
    x0 += x1; x1 = TF_ROT(x1,15); x1 ^= x0;
    x0 += x1; x1 = TF_ROT(x1,26); x1 ^= x0;
    x0 += x1; x1 = TF_ROT(x1, 6); x1 ^= x0;
    x0 += k0; x1 += k1 + 3u;
    x0 += x1; x1 = TF_ROT(x1,17); x1 ^= x0;
    x0 += x1; x1 = TF_ROT(x1,29); x1 ^= x0;
    x0 += x1; x1 = TF_ROT(x1,16); x1 ^= x0;
    x0 += x1; x1 = TF_ROT(x1,24); x1 ^= x0;
    x0 += k1; x1 += ks2 + 4u;
    x0 += x1; x1 = TF_ROT(x1,13); x1 ^= x0;
    x0 += x1; x1 = TF_ROT(x1,15); x1 ^= x0;
    x0 += x1; x1 = TF_ROT(x1,26); x1 ^= x0;
    x0 += x1; x1 = TF_ROT(x1, 6); x1 ^= x0;
    x0 += ks2; x1 += k0 + 5u;
    *o0 = x0; *o1 = x1;
}

// ---------------- encoder: h0 = relu(x @ W_enc + b_enc) ----------------
__global__ void encoder_kernel(const float* __restrict__ x,
                               const float* __restrict__ W,
                               const float* __restrict__ b,
                               float* __restrict__ h0)
{
    int n = blockIdx.x;
    int d = threadIdx.x;           // 256
    __shared__ float xr[DF_];
    if (d < DF_) xr[d] = x[n * DF_ + d];
    __syncthreads();
    float acc = b[d];
#pragma unroll
    for (int k = 0; k < DF_; k++) acc = fmaf(xr[k], W[k * D_ + d], acc);
    h0[(size_t)n * D_ + d] = fmaxf(acc, 0.f);
}

__global__ void zero_anchor_kernel(int* __restrict__ anc)
{
    int idx = blockIdx.x * 256 + threadIdx.x;
    if (idx < M_ * N_) anc[idx] = 0;
}

// ----- build per-graph dedup'd CSR once (edges are static) -----
__global__ void prep_csr_kernel(const int* __restrict__ esrc,
                                const int* __restrict__ edst,
                                int* __restrict__ ent, int* __restrict__ off)
{
    __shared__ int cnt[64 * 64];
    __shared__ int nnz[64], base[65];
    int g = blockIdx.x, tid = threadIdx.x;     // 256 threads
    for (int i = tid; i < 4096; i += 256) cnt[i] = 0;
    __syncthreads();
    int eb = g * 512;
#pragma unroll
    for (int k = 0; k < 2; k++) {
        int e = eb + tid + k * 256;
        int s = esrc[e] & 63, d = edst[e] & 63;
        atomicAdd(&cnt[d * 64 + s], 1);
    }
    __syncthreads();
    if (tid < 64) {
        int c = 0;
        for (int s = 0; s < 64; s++) c += (cnt[tid * 64 + s] != 0);
        nnz[tid] = c;
    }
    __syncthreads();
    if (tid == 0) {
        int a = 0;
        for (int d = 0; d < 64; d++) { base[d] = a; a += nnz[d]; }
        base[64] = a;
    }
    __syncthreads();
    if (tid < 64) {
        int o = base[tid];
        for (int s = 0; s < 64; s++) {
            int c = cnt[tid * 64 + s];
            if (c) ent[g * 512 + (o++)] = s | (c << 8);
        }
        off[g * 65 + tid] = base[tid];
        if (tid == 0) off[g * 65 + 64] = base[64];
    }
}

// ---- weight split into tf32 big/small, permuted to mma B-frag order ----
__global__ void split_w_kernel(const float* __restrict__ gW1,
                               const float* __restrict__ gW2,
                               const float* __restrict__ Wn2n,
                               float* __restrict__ big,
                               float* __restrict__ small)
{
    int id = blockIdx.x;  // 0..10
    const float* W = (id < 5) ? gW1 + (size_t)id * 65536
                   : (id < 10) ? gW2 + (size_t)(id - 5) * 65536
                   : Wn2n;
    int base = blockIdx.y * 4096;
    for (int i = threadIdx.x; i < 4096; i += 256) {
        int idx = base + i;              // = k*256 + n
        int k = idx >> 8, n = idx & 255;
        float v = W[idx];
        float b = tf32r(v), s = tf32r(v - b);
        int by = n >> 7, wn = (n >> 5) & 3, nt = (n >> 3) & 3, lh = n & 7;
        int ch = k >> 5, k8 = (k >> 3) & 3, tg = k & 3, br = (k >> 2) & 1;
        int ln = lh * 4 + tg;
        size_t o = (size_t)id * 65536 +
            (size_t)((((((by * 8 + ch) * 4 + wn) * 4 + nt) * 4 + k8) * 32 + ln) * 2 + br);
        big[o] = b; small[o] = s;
    }
}

// ===================== GEMM machinery =====================
// Block: 128 rows x 128 cols. 8 warps (2m x 4n), warp tile 64x32.
// A smem: stride-36 rows. B smem: frag-permuted.
// FUSED=1: epilogue applies t = relu(Ctilde @ Y + bias) where Y = H@W1,
// using Ctilde = (1+eps)I + C (associativity: z@W1 == Ctilde@(H@W1)).

#define GB_AB   0
#define GB_AS   4608
#define GB_BB   9216
#define GB_BS   13312
#define GB_BIAS 17408
#define GB_ENT  17536
#define GB_OFF  18560
#define GB_SMEM_BYTES ((18560 + 132) * 4)
// sY (fused epilogue) overlays offsets [0, 16896) = sAb/sAs/sBb/part of sBs

template <int FUSED>
__device__ __forceinline__
void gemm_body(const float* __restrict__ A,
               const float* __restrict__ Bb_perm, const float* __restrict__ Bs_perm,
               const float* __restrict__ bias, float* __restrict__ C,
               const int* __restrict__ ent, const int* __restrict__ off,
               const float* __restrict__ eps, int layer)
{
    extern __shared__ float sm[];
    float* sAb = sm + GB_AB;
    float* sAs = sm + GB_AS;
    float* sBb = sm + GB_BB;
    float* sBs = sm + GB_BS;
    float* sbias = sm + GB_BIAS;
    int* sEnt = (int*)(sm + GB_ENT);
    int* sOff = (int*)(sm + GB_OFF);

    const int tid = threadIdx.x, lane = tid & 31, wid = tid >> 5;
    const int wm = wid >> 2, wn = wid & 3;
    const size_t row0 = (size_t)blockIdx.x * 128;
    const int by = blockIdx.y, col0 = by * 128;

    if (tid < 128) sbias[tid] = bias[col0 + tid];
    if (FUSED) {
        int g0 = (int)((row0 & (N_ - 1)) >> 6);      // graphs g0, g0+1
        for (int i = tid; i < 1024; i += 256)
            sEnt[i] = ent[(size_t)(g0 + (i >> 9)) * 512 + (i & 511)];
        if (tid < 130) {
            int gg = tid / 65;
            sOff[tid] = off[(size_t)(g0 + gg) * 65 + (tid - gg * 65)];
        }
    }

    float acc[4][4][4];
#pragma unroll
    for (int mt = 0; mt < 4; mt++)
#pragma unroll
        for (int nt = 0; nt < 4; nt++)
#pragma unroll
            for (int r = 0; r < 4; r++) acc[mt][nt][r] = 0.f;

    const int R  = tid >> 1;
    const int kh = (tid & 1) * 16;
    const float* Arow = A + (row0 + R) * 256 + kh;
    const float4* gBb = (const float4*)(Bb_perm + (size_t)by * 8 * 4096);
    const float4* gBs = (const float4*)(Bs_perm + (size_t)by * 8 * 4096);

    float4 pa[4], pbb[4], pbs[4];
#pragma unroll
    for (int q = 0; q < 4; q++) {
        pa[q]  = *(const float4*)(Arow + q * 4);
        pbb[q] = gBb[tid + q * 256];
        pbs[q] = gBs[tid + q * 256];
    }

#pragma unroll 1
    for (int ch = 0; ch < 8; ch++) {
        if (ch) __syncthreads();
#pragma unroll
        for (int q = 0; q < 4; q++) {
            float4 x = pa[q];
            float4 hb, hs;
            hb.x = tf32r(x.x); hs.x = tf32r(x.x - hb.x);
            hb.y = tf32r(x.y); hs.y = tf32r(x.y - hb.y);
            hb.z = tf32r(x.z); hs.z = tf32r(x.z - hb.z);
            hb.w = tf32r(x.w); hs.w = tf32r(x.w - hb.w);
            *(float4*)(sAb + R * 36 + kh + q * 4) = hb;
            *(float4*)(sAs + R * 36 + kh + q * 4) = hs;
            *(float4*)(sBb + (tid + q * 256) * 4) = pbb[q];
            *(float4*)(sBs + (tid + q * 256) * 4) = pbs[q];
        }
        __syncthreads();
        if (ch < 7) {
#pragma unroll
            for (int q = 0; q < 4; q++) {
                pa[q]  = *(const float4*)(Arow + (ch + 1) * 32 + q * 4);
                pbb[q] = gBb[(ch + 1) * 1024 + tid + q * 256];
                pbs[q] = gBs[(ch + 1) * 1024 + tid + q * 256];
            }
        }
#pragma unroll
        for (int k8 = 0; k8 < 4; k8++) {
            uint32_t ab[4][4], as_[4][4];
#pragma unroll
            for (int mt = 0; mt < 4; mt++) {
                int o = (wm * 64 + mt * 16 + (lane >> 2)) * 36 + k8 * 8 + (lane & 3);
                ab[mt][0]  = __float_as_uint(sAb[o]);
                ab[mt][1]  = __float_as_uint(sAb[o + 8 * 36]);
                ab[mt][2]  = __float_as_uint(sAb[o + 4]);
                ab[mt][3]  = __float_as_uint(sAb[o + 8 * 36 + 4]);
                as_[mt][0] = __float_as_uint(sAs[o]);
                as_[mt][1] = __float_as_uint(sAs[o + 8 * 36]);
                as_[mt][2] = __float_as_uint(sAs[o + 4]);
                as_[mt][3] = __float_as_uint(sAs[o + 8 * 36 + 4]);
            }
            uint32_t bb[4][2], bs[4][2];
#pragma unroll
            for (int nt = 0; nt < 4; nt++) {
                int o = (((wn * 4 + nt) * 4 + k8) * 32 + lane) * 2;
                bb[nt][0] = __float_as_uint(sBb[o]);
                bb[nt][1] = __float_as_uint(sBb[o + 1]);
                bs[nt][0] = __float_as_uint(sBs[o]);
                bs[nt][1] = __float_as_uint(sBs[o + 1]);
            }
#pragma unroll
            for (int mt = 0; mt < 4; mt++)
#pragma unroll
                for (int nt = 0; nt < 4; nt++) {
                    MMA_TF32(acc[mt][nt], ab[mt], bb[nt]);
                    MMA_TF32(acc[mt][nt], ab[mt], bs[nt]);
                    MMA_TF32(acc[mt][nt], as_[mt], bb[nt]);
                }
        }
    }

    if (!FUSED) {
#pragma unroll
        for (int mt = 0; mt < 4; mt++) {
            size_t rg = row0 + wm * 64 + mt * 16 + (lane >> 2);
#pragma unroll
            for (int nt = 0; nt < 4; nt++) {
                int cl = wn * 32 + nt * 8 + (lane & 3) * 2;
                float b0 = sbias[cl], b1 = sbias[cl + 1];
                float2 v0, v1;
                v0.x = fmaxf(acc[mt][nt][0] + b0, 0.f);
                v0.y = fmaxf(acc[mt][nt][1] + b1, 0.f);
                v1.x = fmaxf(acc[mt][nt][2] + b0, 0.f);
                v1.y = fmaxf(acc[mt][nt][3] + b1, 0.f);
                *(float2*)&C[rg * 256 + col0 + cl] = v0;
                *(float2*)&C[(rg + 8) * 256 + col0 + cl] = v1;
            }
        }
    } else {
        // ---- fused epilogue: t = relu(Ctilde @ Y + bias) ----
        float* sY = sm;   // 128 x 132 (overlays operand buffers)
        __syncthreads();  // mainloop smem reads done before overwrite
#pragma unroll
        for (int mt = 0; mt < 4; mt++) {
            int rg = wm * 64 + mt * 16 + (lane >> 2);
#pragma unroll
            for (int nt = 0; nt < 4; nt++) {
                int cl = wn * 32 + nt * 8 + (lane & 3) * 2;
                *(float2*)&sY[rg * 132 + cl] =
                    make_float2(acc[mt][nt][0], acc[mt][nt][1]);
                *(float2*)&sY[(rg + 8) * 132 + cl] =
                    make_float2(acc[mt][nt][2], acc[mt][nt][3]);
            }
        }
        __syncthreads();
        float ep = 1.0f + eps[layer];
        int c4 = lane;                       // column group: cols c4*4..+3
        int wg = wid;                        // warp owns rows wg*16..+15
        int gl = wg >> 2;                    // graph-local (0/1)
        float4 bv = *(const float4*)&sbias[c4 * 4];
#pragma unroll 1
        for (int i = 0; i < 16; i++) {
            int r = wg * 16 + i;
            int lr = r & 63;
            float4 a = *(const float4*)&sY[r * 132 + c4 * 4];
            a.x *= ep; a.y *= ep; a.z *= ep; a.w *= ep;
            int st = sOff[gl * 65 + lr], en = sOff[gl * 65 + lr + 1];
            for (int e = st; e < en; e++) {
                int u = sEnt[gl * 512 + e];
                float c = (float)(u >> 8);
                float4 hv = *(const float4*)&sY[(gl * 64 + (u & 63)) * 132 + c4 * 4];
                a.x = fmaf(c, hv.x, a.x);
                a.y = fmaf(c, hv.y, a.y);
                a.z = fmaf(c, hv.z, a.z);
                a.w = fmaf(c, hv.w, a.w);
            }
            float4 v;
            v.x = fmaxf(a.x + bv.x, 0.f);
            v.y = fmaxf(a.y + bv.y, 0.f);
            v.z = fmaxf(a.z + bv.z, 0.f);
            v.w = fmaxf(a.w + bv.w, 0.f);
            *(float4*)&C[(row0 + r) * 256 + col0 + c4 * 4] = v;
        }
    }
}

__global__ __launch_bounds__(256)
void gemm_mma(const float* __restrict__ A,
              const float* __restrict__ Bb, const float* __restrict__ Bs,
              const float* __restrict__ bias, float* __restrict__ C)
{
    gemm_body<0>(A, Bb, Bs, bias, C, nullptr, nullptr, nullptr, 0);
}

__global__ __launch_bounds__(256)
void gemm_fused(const float* __restrict__ A,
                const float* __restrict__ Bb, const float* __restrict__ Bs,
                const float* __restrict__ bias, float* __restrict__ C,
                const int* __restrict__ ent, const int* __restrict__ off,
                const float* __restrict__ eps, int layer)
{
    gemm_body<1>(A, Bb, Bs, bias, C, ent, off, eps, layer);
}

// ---------------- per-graph pairwise min distance (fp32) ----------------
#define MD_SMEM ((64 * 257 + 64 + 64) * 4)
__global__ __launch_bounds__(256)
void mindist_kernel(const float* __restrict__ h, float* __restrict__ mind)
{
    extern __shared__ float sm[];
    float* sh  = sm;
    float* ssq = sm + 64 * 257;
    int*   smn = (int*)(ssq + 64);
    int b = blockIdx.x, m = blockIdx.y;
    int tid = threadIdx.x;

    const float* H = h + ((size_t)m * N_ + (size_t)b * NPG_) * D_;
    for (int idx = tid; idx < NPG_ * D_; idx += 256) {
        int r = idx >> 8, d = idx & 255;
        sh[r * 257 + d] = H[idx];
    }
    if (tid < 64) smn[tid] = 0x7f7fffff;
    __syncthreads();

    if (tid < 64) {
        const float* row = sh + tid * 257;
        float s = 0.f;
        for (int d = 0; d < D_; d++) s = fmaf(row[d], row[d], s);
        ssq[tid] = s;
    }
    __syncthreads();

    int i  = tid >> 2;
    int j0 = (tid & 3) * 16;
    float acc[16];
#pragma unroll
    for (int jj = 0; jj < 16; jj++) acc[jj] = 0.f;
    const float* ri = sh + i * 257;
    for (int d = 0; d < D_; d++) {
        float a = ri[d];
#pragma unroll
        for (int jj = 0; jj < 16; jj++)
            acc[jj] = fmaf(a, sh[(j0 + jj) * 257 + d], acc[jj]);
    }
    float sqi = ssq[i];
    float lmin = 3.0e38f;
#pragma unroll
    for (int jj = 0; jj < 16; jj++) {
        int j = j0 + jj;
        float d2 = fmaxf(sqi + ssq[j] - 2.0f * acc[jj], 0.f);
        if (j == i) d2 += 1.0e9f;
        lmin = fminf(lmin, d2);
    }
    atomicMin(&smn[i], __float_as_int(lmin));
    __syncthreads();
    if (tid < 64)
        mind[(size_t)m * N_ + (size_t)b * NPG_ + tid] = __int_as_float(smn[tid]);
}

// ------------- gumbel sample + argmax + anchor set (exact JAX) -----------
__global__ void gumbel_kernel(const float* __restrict__ mind,
                              int* __restrict__ anchor,
                              int it, unsigned fk0, unsigned fk1,
                              int mind_stride_m)
{
    int b = blockIdx.x, m = blockIdx.y;
    int p = threadIdx.x;
    __shared__ float sg[NPG_];
    int node = m * N_ + b * NPG_ + p;

    unsigned o0, o1;
    tf2x32(fk0, fk1, 0u, (unsigned)node, &o0, &o1);
    unsigned bits = o0 ^ o1;
    float f = __uint_as_float((bits >> 9) | 0x3f800000u) - 1.0f;
    const float mn = 1e-9f;
    float u = fmaxf(mn, f * (1.0f - mn) + mn);
    float md = mind[(size_t)m * mind_stride_m + b * NPG_ + p];
    float logit = -md - 10.0f * (anchor[node] > 0 ? 1.0f : 0.0f);
    sg[p] = logit - logf(-logf(u));
    __syncthreads();
    if (p == 0) {
        int best = 0; float bv = sg[0];
        for (int q = 1; q < NPG_; q++)
            if (sg[q] > bv) { bv = sg[q]; best = q; }
        anchor[m * N_ + b * NPG_ + best] = it;
    }
}

// ---------------- xcur = tx * anchor_emb[anchor] + tx ----------------
__global__ void update_xcur_kernel(const float* __restrict__ h0,
                                   const int* __restrict__ anchor,
                                   const float* __restrict__ emb,
                                   float* __restrict__ xc)
{
    size_t idx = (size_t)blockIdx.x * 256 + threadIdx.x;
    size_t mn = idx >> 8;
    int d = (int)(idx & 255);
    int n = (int)(mn & (N_ - 1));
    int a = anchor[mn];
    float tv = h0[((size_t)n << 8) + d];
    xc[idx] = tv * emb[a * D_ + d] + tv;
}

// --------- finalize: per-m group mean -> dot W_pred -> mean over m --------
__global__ void finalize_kernel(const float* __restrict__ hn,
                                const float* __restrict__ Wp,
                                const float* __restrict__ bp,
                                float* __restrict__ out)
{
    int b = blockIdx.x;
    int d = threadIdx.x;
    __shared__ float g[M_][D_];
#pragma unroll
    for (int m = 0; m < M_; m++) {
        const float* base = hn + ((size_t)m * N_ + (size_t)b * NPG_) * D_ + d;
        float s = 0.f;
        for (int p = 0; p < NPG_; p++) s += base[(size_t)p * D_];
        g[m][d] = s * (1.0f / (float)NPG_);
    }
    __syncthreads();
    if (d < TASKS_) {
        float acc = 0.f;
#pragma unroll
        for (int m = 0; m < M_; m++) {
            float a = 0.f;
            for (int k = 0; k < D_; k++)
                a = fmaf(g[m][k], Wp[k * TASKS_ + d], a);
            acc += a + bp[d];
        }
        out[b * TASKS_ + d] = acc * (1.0f / (float)M_);
    }
}

// ---------------- host orchestration ----------------
extern "C" void kernel_launch(void* const* d_in, const int* in_sizes, int n_in,
                              void* d_out, int out_size)
{
    const float* x     = (const float*)d_in[0];
    const float* W_enc = (const float*)d_in[1];
    const float* b_enc = (const float*)d_in[2];
    const float* gW1   = (const float*)d_in[3];
    const float* gb1   = (const float*)d_in[4];
    const float* gW2   = (const float*)d_in[5];
    const float* gb2   = (const float*)d_in[6];
    const float* eps   = (const float*)d_in[7];
    const float* aemb  = (const float*)d_in[8];
    const float* Wn2n  = (const float*)d_in[9];
    const float* bn2n  = (const float*)d_in[10];
    const float* Wp    = (const float*)d_in[11];
    const float* bp    = (const float*)d_in[12];
    const int*   esrc  = (const int*)d_in[13];
    const int*   edst  = (const int*)d_in[14];
    float* out = (float*)d_out;

    float *h0, *xc, *hA, *t, *mind, *wtb, *wts; int *anc, *ent, *off;
    cudaGetSymbolAddress((void**)&h0,   g_h0);
    cudaGetSymbolAddress((void**)&xc,   g_xcur);
    cudaGetSymbolAddress((void**)&hA,   g_hA);
    cudaGetSymbolAddress((void**)&t,    g_t);
    cudaGetSymbolAddress((void**)&mind, g_mind);
    cudaGetSymbolAddress((void**)&anc,  g_anchor);
    cudaGetSymbolAddress((void**)&wtb,  g_wt_big);
    cudaGetSymbolAddress((void**)&wts,  g_wt_small);
    cudaGetSymbolAddress((void**)&ent,  g_csr_ent);
    cudaGetSymbolAddress((void**)&off,  g_csr_off);

    cudaFuncSetAttribute(mindist_kernel, cudaFuncAttributeMaxDynamicSharedMemorySize, MD_SMEM);
    cudaFuncSetAttribute(gemm_mma, cudaFuncAttributeMaxDynamicSharedMemorySize, GB_SMEM_BYTES);
    cudaFuncSetAttribute(gemm_fused, cudaFuncAttributeMaxDynamicSharedMemorySize, GB_SMEM_BYTES);

    unsigned fk0[NA_ + 1], fk1[NA_ + 1];
    for (int i = 1; i <= NA_; i++)
        tf2x32(0u, 42u, 0u, (unsigned)i, &fk0[i], &fk1[i]);

    const dim3 graph_full(B_, M_), graph_q(B_, 1);
    const dim3 mma_full((M_ * N_) / 128, 2), mma_q(N_ / 128, 2);
    const int  bcast_blocks = (M_ * N_ * D_) / 256;

    auto WB = [&](int id) { return wtb + (size_t)id * 65536; };
    auto WS = [&](int id) { return wts + (size_t)id * 65536; };

    prep_csr_kernel<<<B_, 256>>>(esrc, edst, ent, off);
    split_w_kernel<<<dim3(11, 16), 256>>>(gW1, gW2, Wn2n, wtb, wts);
    encoder_kernel<<<N_, 256>>>(x, W_enc, b_enc, h0);
    zero_anchor_kernel<<<(M_ * N_) / 256, 256>>>(anc);

    // ---- iteration 1: xcur broadcast of h0 -> compute once over N rows ----
    {
        const float* cur = h0;
        for (int l = 0; l < L_; l++) {
            gemm_fused<<<mma_q, 256, GB_SMEM_BYTES>>>(
                cur, WB(l), WS(l), gb1 + l * D_, t, ent, off, eps, l);
            gemm_mma<<<mma_q, 256, GB_SMEM_BYTES>>>(t, WB(5 + l), WS(5 + l), gb2 + l * D_, hA);
            cur = hA;
        }
        mindist_kernel<<<graph_q, 256, MD_SMEM>>>(hA, mind);
        gumbel_kernel<<<graph_full, 64>>>(mind, anc, 1, fk0[1], fk1[1], 0);
        update_xcur_kernel<<<bcast_blocks, 256>>>(h0, anc, aemb, xc);
    }

    // ---- iteration 2: full per-m pipeline ----
    {
        const float* cur = xc;
        for (int l = 0; l < L_; l++) {
            gemm_fused<<<mma_full, 256, GB_SMEM_BYTES>>>(
                cur, WB(l), WS(l), gb1 + l * D_, t, ent, off, eps, l);
            gemm_mma<<<mma_full, 256, GB_SMEM_BYTES>>>(t, WB(5 + l), WS(5 + l), gb2 + l * D_, hA);
            cur = hA;
        }
        mindist_kernel<<<graph_full, 256, MD_SMEM>>>(hA, mind);
        gumbel_kernel<<<graph_full, 64>>>(mind, anc, 2, fk0[2], fk1[2], N_);
        update_xcur_kernel<<<bcast_blocks, 256>>>(h0, anc, aemb, xc);
    }

    // ---- final GNN on xcur ----
    {
        const float* cur = xc;
        for (int l = 0; l < L_; l++) {
            gemm_fused<<<mma_full, 256, GB_SMEM_BYTES>>>(
                cur, WB(l), WS(l), gb1 + l * D_, t, ent, off, eps, l);
            gemm_mma<<<mma_full, 256, GB_SMEM_BYTES>>>(t, WB(5 + l), WS(5 + l), gb2 + l * D_, hA);
            cur = hA;
        }
    }
    gemm_mma<<<mma_full, 256, GB_SMEM_BYTES>>>(hA, WB(10), WS(10), bn2n, t);
    finalize_kernel<<<B_, 256>>>(t, Wp, bp, out);
}

// round 14
// speedup vs baseline: 2.7090x; 1.0876x over previous
#include <cuda_runtime.h>
#include <cstdint>

// ---------------- problem constants ----------------
#define M_     4
#define B_     256
#define NPG_   64
#define N_     16384
#define DEG_   8
#define E_     131072
#define DF_    16
#define D_     256
#define L_     5
#define NA_    2
#define TASKS_ 10

// ---------------- device scratch (no allocs allowed) ----------------
__device__ float g_h0[(size_t)N_ * D_];
__device__ float g_xcur[(size_t)M_ * N_ * D_];
__device__ float g_hA[(size_t)M_ * N_ * D_];
__device__ float g_t[(size_t)M_ * N_ * D_];
__device__ float g_mind[(size_t)M_ * N_];
__device__ int   g_anchor[(size_t)M_ * N_];
__device__ float g_wt_big[11 * 65536];
__device__ float g_wt_small[11 * 65536];
__device__ int   g_csr_ent[B_ * 512];
__device__ int   g_csr_off[B_ * 65];

static __device__ __forceinline__ float tf32r(float x) {
    float r;
    asm("cvt.rna.tf32.f32 %0, %1;" : "=f"(r) : "f"(x));
    return r;
}
static __device__ __forceinline__ uint32_t smem_u32(const void* p) {
    uint32_t a;
    asm("{ .reg .u64 t; cvta.to.shared.u64 t, %1; cvt.u32.u64 %0, t; }"
        : "=r"(a) : "l"(p));
    return a;
}
static __device__ __forceinline__ void cp16(uint32_t dst, const void* src) {
    asm volatile("cp.async.cg.shared.global [%0], [%1], 16;"
                 :: "r"(dst), "l"(src) : "memory");
}
#define CP_COMMIT() asm volatile("cp.async.commit_group;" ::: "memory")
#define CP_WAIT(n)  asm volatile("cp.async.wait_group %0;" :: "n"(n) : "memory")

// m16n8k8 tf32 mma (sm_80+ PTX, works on base compute_103 target)
#define MMA_TF32(d, a, b) \
    asm volatile("mma.sync.aligned.m16n8k8.row.col.f32.tf32.tf32.f32 " \
                 "{%0,%1,%2,%3}, {%4,%5,%6,%7}, {%8,%9}, {%0,%1,%2,%3};" \
                 : "+f"((d)[0]), "+f"((d)[1]), "+f"((d)[2]), "+f"((d)[3]) \
                 : "r"((a)[0]), "r"((a)[1]), "r"((a)[2]), "r"((a)[3]), \
                   "r"((b)[0]), "r"((b)[1]))

// ---------------- threefry2x32 (exact JAX rounds) ----------------
#define TF_ROT(x,d) (((x) << (d)) | ((x) >> (32 - (d))))
static __host__ __device__ __forceinline__
void tf2x32(unsigned k0, unsigned k1, unsigned x0, unsigned x1,
            unsigned* o0, unsigned* o1)
{
    unsigned ks2 = k0 ^ k1 ^ 0x1BD11BDAu;
    x0 += k0; x1 += k1;
    x0 += x1; x1 = TF_ROT(x1,13); x1 ^= x0;
    x0 += x1; x1 = TF_ROT(x1,15); x1 ^= x0;
    x0 += x1; x1 = TF_ROT(x1,26); x1 ^= x0;
    x0 += x1; x1 = TF_ROT(x1, 6); x1 ^= x0;
    x0 += k1; x1 += ks2 + 1u;
    x0 += x1; x1 = TF_ROT(x1,17); x1 ^= x0;
    x0 += x1; x1 = TF_ROT(x1,29); x1 ^= x0;
    x0 += x1; x1 = TF_ROT(x1,16); x1 ^= x0;
    x0 += x1; x1 = TF_ROT(x1,24); x1 ^= x0;
    x0 += ks2; x1 += k0 + 2u;
    x0 += x1; x1 = TF_ROT(x1,13); x1 ^= x0;
    x0 += x1; x1 = TF_ROT(x1,15); x1 ^= x0;
    x0 += x1; x1 = TF_ROT(x1,26); x1 ^= x0;
    x0 += x1; x1 = TF_ROT(x1, 6); x1 ^= x0;
    x0 += k0; x1 += k1 + 3u;
    x0 += x1; x1 = TF_ROT(x1,17); x1 ^= x0;
    x0 += x1; x1 = TF_ROT(x1,29); x1 ^= x0;
    x0 += x1; x1 = TF_ROT(x1,16); x1 ^= x0;
    x0 += x1; x1 = TF_ROT(x1,24); x1 ^= x0;
    x0 += k1; x1 += ks2 + 4u;
    x0 += x1; x1 = TF_ROT(x1,13); x1 ^= x0;
    x0 += x1; x1 = TF_ROT(x1,15); x1 ^= x0;
    x0 += x1; x1 = TF_ROT(x1,26); x1 ^= x0;
    x0 += x1; x1 = TF_ROT(x1, 6); x1 ^= x0;
    x0 += ks2; x1 += k0 + 5u;
    *o0 = x0; *o1 = x1;
}

// ---------------- encoder: h0 = relu(x @ W_enc + b_enc) ----------------
__global__ void encoder_kernel(const float* __restrict__ x,
                               const float* __restrict__ W,
                               const float* __restrict__ b,
                               float* __restrict__ h0)
{
    int n = blockIdx.x;
    int d = threadIdx.x;
    __shared__ float xr[DF_];
    if (d < DF_) xr[d] = x[n * DF_ + d];
    __syncthreads();
    float acc = b[d];
#pragma unroll
    for (int k = 0; k < DF_; k++) acc = fmaf(xr[k], W[k * D_ + d], acc);
    h0[(size_t)n * D_ + d] = fmaxf(acc, 0.f);
}

__global__ void zero_anchor_kernel(int* __restrict__ anc)
{
    int idx = blockIdx.x * 256 + threadIdx.x;
    if (idx < M_ * N_) anc[idx] = 0;
}

// ----- build per-graph dedup'd CSR once (edges are static) -----
__global__ void prep_csr_kernel(const int* __restrict__ esrc,
                                const int* __restrict__ edst,
                                int* __restrict__ ent, int* __restrict__ off)
{
    __shared__ int cnt[64 * 64];
    __shared__ int nnz[64], base[65];
    int g = blockIdx.x, tid = threadIdx.x;
    for (int i = tid; i < 4096; i += 256) cnt[i] = 0;
    __syncthreads();
    int eb = g * 512;
#pragma unroll
    for (int k = 0; k < 2; k++) {
        int e = eb + tid + k * 256;
        int s = esrc[e] & 63, d = edst[e] & 63;
        atomicAdd(&cnt[d * 64 + s], 1);
    }
    __syncthreads();
    if (tid < 64) {
        int c = 0;
        for (int s = 0; s < 64; s++) c += (cnt[tid * 64 + s] != 0);
        nnz[tid] = c;
    }
    __syncthreads();
    if (tid == 0) {
        int a = 0;
        for (int d = 0; d < 64; d++) { base[d] = a; a += nnz[d]; }
        base[64] = a;
    }
    __syncthreads();
    if (tid < 64) {
        int o = base[tid];
        for (int s = 0; s < 64; s++) {
            int c = cnt[tid * 64 + s];
            if (c) ent[g * 512 + (o++)] = s | (c << 8);
        }
        off[g * 65 + tid] = base[tid];
        if (tid == 0) off[g * 65 + 64] = base[64];
    }
}

// ---- weight split into tf32 big/small, permuted to mma B-frag order ----
// flat = (((ch*4 + wn)*8 + nt)*4 + k8)*64 + lane*2 + br
// n = wn*64 + nt*8 + (lane>>2), k = ch*32 + k8*8 + (lane&3) + br*4
__global__ void split_w_kernel(const float* __restrict__ gW1,
                               const float* __restrict__ gW2,
                               const float* __restrict__ Wn2n,
                               float* __restrict__ big,
                               float* __restrict__ small)
{
    int id = blockIdx.x;  // 0..10
    const float* W = (id < 5) ? gW1 + (size_t)id * 65536
                   : (id < 10) ? gW2 + (size_t)(id - 5) * 65536
                   : Wn2n;
    int base = blockIdx.y * 4096;
    for (int i = threadIdx.x; i < 4096; i += 256) {
        int idx = base + i;              // = k*256 + n
        int k = idx >> 8, n = idx & 255;
        float v = W[idx];
        float b = tf32r(v), s = tf32r(v - b);
        int wn = n >> 6, nt = (n >> 3) & 7, lh = n & 7;
        int ch = k >> 5, k8 = (k >> 3) & 3, tg = k & 3, br = (k >> 2) & 1;
        int ln = lh * 4 + tg;
        size_t o = (size_t)id * 65536 +
            (size_t)(((((ch * 4 + wn) * 8 + nt) * 4 + k8) * 64) + ln * 2 + br);
        big[o] = b; small[o] = s;
    }
}

// ===================== GEMM: block 128 rows x 256 cols =====================
// 8 warps (2m x 4n), warp tile 64x64. A: reg-prefetch + in-reg tf32 split,
// stride-36 smem. B: cp.async double-buffered, frag-permuted.
// FUSED=1: epilogue t = relu(Ctilde @ Y + bias), Ctilde = (1+eps)I + C.

#define GC_AB    0
#define GC_AS    4608
#define GC_B0B   9216
#define GC_B0S   17408
#define GC_B1B   25600
#define GC_B1S   33792
#define GC_BIAS  41984
#define GC_ENT   42240
#define GC_OFF   43264
#define GC_SMEM_BYTES ((43264 + 132) * 4)
// fused epilogue sY: 128 x 260 floats = 33280 floats, overlays [0, GC_BIAS)

template <int FUSED>
__device__ __forceinline__
void gemm_body(const float* __restrict__ A,
               const float* __restrict__ Bb, const float* __restrict__ Bs,
               const float* __restrict__ bias, float* __restrict__ C,
               const int* __restrict__ ent, const int* __restrict__ off,
               const float* __restrict__ eps, int layer)
{
    extern __shared__ float sm[];
    float* sAb = sm + GC_AB;
    float* sAs = sm + GC_AS;
    float* sbias = sm + GC_BIAS;
    int* sEnt = (int*)(sm + GC_ENT);
    int* sOff = (int*)(sm + GC_OFF);
    uint32_t smb = smem_u32(sm);

    const int tid = threadIdx.x, lane = tid & 31, wid = tid >> 5;
    const int wm = wid >> 2, wn = wid & 3;
    const size_t row0 = (size_t)blockIdx.x * 128;

    sbias[tid] = bias[tid];
    if (tid < 128) { } // (all 256 bias entries covered: blockDim=256)
    if (FUSED) {
        int g0 = (int)((row0 & (N_ - 1)) >> 6);
        for (int i = tid; i < 1024; i += 256)
            sEnt[i] = ent[(size_t)(g0 + (i >> 9)) * 512 + (i & 511)];
        if (tid < 130) {
            int gg = tid / 65;
            sOff[tid] = off[(size_t)(g0 + gg) * 65 + (tid - gg * 65)];
        }
    }

    float acc[4][8][4];
#pragma unroll
    for (int mt = 0; mt < 4; mt++)
#pragma unroll
        for (int nt = 0; nt < 8; nt++)
#pragma unroll
            for (int r = 0; r < 4; r++) acc[mt][nt][r] = 0.f;

    const int R  = tid >> 1;
    const int kh = (tid & 1) * 16;
    const float* Arow = A + (row0 + R) * 256 + kh;

    const uint32_t bufb[2] = { smb + GC_B0B * 4, smb + GC_B1B * 4 };
    const uint32_t bufs[2] = { smb + GC_B0S * 4, smb + GC_B1S * 4 };

    // prologue: cp.async B chunk 0 -> buf0; prefetch A chunk 0 regs
#pragma unroll
    for (int q = 0; q < 8; q++) {
        cp16(bufb[0] + (uint32_t)(tid + q * 256) * 16, Bb + (tid + q * 256) * 4);
        cp16(bufs[0] + (uint32_t)(tid + q * 256) * 16, Bs + (tid + q * 256) * 4);
    }
    CP_COMMIT();
    float4 pa[4];
#pragma unroll
    for (int q = 0; q < 4; q++) pa[q] = *(const float4*)(Arow + q * 4);

#pragma unroll 1
    for (int ch = 0; ch < 8; ch++) {
        if (ch) __syncthreads();
        // store A split (chunk ch)
#pragma unroll
        for (int q = 0; q < 4; q++) {
            float4 x = pa[q];
            float4 hb, hs;
            hb.x = tf32r(x.x); hs.x = tf32r(x.x - hb.x);
            hb.y = tf32r(x.y); hs.y = tf32r(x.y - hb.y);
            hb.z = tf32r(x.z); hs.z = tf32r(x.z - hb.z);
            hb.w = tf32r(x.w); hs.w = tf32r(x.w - hb.w);
            *(float4*)(sAb + R * 36 + kh + q * 4) = hb;
            *(float4*)(sAs + R * 36 + kh + q * 4) = hs;
        }
        if (ch < 7) {
            const float* srcb = Bb + (ch + 1) * 8192;
            const float* srcs = Bs + (ch + 1) * 8192;
            uint32_t db = bufb[(ch + 1) & 1], ds = bufs[(ch + 1) & 1];
#pragma unroll
            for (int q = 0; q < 8; q++) {
                cp16(db + (uint32_t)(tid + q * 256) * 16, srcb + (tid + q * 256) * 4);
                cp16(ds + (uint32_t)(tid + q * 256) * 16, srcs + (tid + q * 256) * 4);
            }
            CP_COMMIT();
#pragma unroll
            for (int q = 0; q < 4; q++)
                pa[q] = *(const float4*)(Arow + (ch + 1) * 32 + q * 4);
            CP_WAIT(1);
        } else {
            CP_WAIT(0);
        }
        __syncthreads();

        const float* cBb = sm + ((ch & 1) ? GC_B1B : GC_B0B);
        const float* cBs = sm + ((ch & 1) ? GC_B1S : GC_B0S);
#pragma unroll
        for (int k8 = 0; k8 < 4; k8++) {
            uint32_t ab[4][4], as_[4][4];
#pragma unroll
            for (int mt = 0; mt < 4; mt++) {
                int o = (wm * 64 + mt * 16 + (lane >> 2)) * 36 + k8 * 8 + (lane & 3);
                ab[mt][0]  = __float_as_uint(sAb[o]);
                ab[mt][1]  = __float_as_uint(sAb[o + 8 * 36]);
                ab[mt][2]  = __float_as_uint(sAb[o + 4]);
                ab[mt][3]  = __float_as_uint(sAs[o - 4608 + 8 * 36 + 4]); // placeholder fix below
                ab[mt][3]  = __float_as_uint(sAb[o + 8 * 36 + 4]);
                as_[mt][0] = __float_as_uint(sAs[o]);
                as_[mt][1] = __float_as_uint(sAs[o + 8 * 36]);
                as_[mt][2] = __float_as_uint(sAs[o + 4]);
                as_[mt][3] = __float_as_uint(sAs[o + 8 * 36 + 4]);
            }
            uint32_t bb[8][2], bs[8][2];
#pragma unroll
            for (int nt = 0; nt < 8; nt++) {
                int o = ((wn * 8 + nt) * 4 + k8) * 64 + lane * 2;
                float2 vb = *(const float2*)&cBb[o];
                float2 vs = *(const float2*)&cBs[o];
                bb[nt][0] = __float_as_uint(vb.x);
                bb[nt][1] = __float_as_uint(vb.y);
                bs[nt][0] = __float_as_uint(vs.x);
                bs[nt][1] = __float_as_uint(vs.y);
            }
#pragma unroll
            for (int mt = 0; mt < 4; mt++)
#pragma unroll
                for (int nt = 0; nt < 8; nt++) {
                    MMA_TF32(acc[mt][nt], ab[mt], bb[nt]);
                    MMA_TF32(acc[mt][nt], ab[mt], bs[nt]);
                    MMA_TF32(acc[mt][nt], as_[mt], bb[nt]);
                }
        }
    }

    if (!FUSED) {
#pragma unroll
        for (int mt = 0; mt < 4; mt++) {
            size_t rg = row0 + wm * 64 + mt * 16 + (lane >> 2);
#pragma unroll
            for (int nt = 0; nt < 8; nt++) {
                int cl = wn * 64 + nt * 8 + (lane & 3) * 2;
                float b0 = sbias[cl], b1 = sbias[cl + 1];
                float2 v0, v1;
                v0.x = fmaxf(acc[mt][nt][0] + b0, 0.f);
                v0.y = fmaxf(acc[mt][nt][1] + b1, 0.f);
                v1.x = fmaxf(acc[mt][nt][2] + b0, 0.f);
                v1.y = fmaxf(acc[mt][nt][3] + b1, 0.f);
                *(float2*)&C[rg * 256 + cl] = v0;
                *(float2*)&C[(rg + 8) * 256 + cl] = v1;
            }
        }
    } else {
        float* sY = sm;   // 128 x 260 overlays operand buffers
        __syncthreads();
#pragma unroll
        for (int mt = 0; mt < 4; mt++) {
            int rg = wm * 64 + mt * 16 + (lane >> 2);
#pragma unroll
            for (int nt = 0; nt < 8; nt++) {
                int cl = wn * 64 + nt * 8 + (lane & 3) * 2;
                *(float2*)&sY[rg * 260 + cl] =
                    make_float2(acc[mt][nt][0], acc[mt][nt][1]);
                *(float2*)&sY[(rg + 8) * 260 + cl] =
                    make_float2(acc[mt][nt][2], acc[mt][nt][3]);
            }
        }
        __syncthreads();
        float ep = 1.0f + eps[layer];
        int wg = wid, gl = wg >> 2;
#pragma unroll 1
        for (int pass = 0; pass < 2; pass++) {
            int c4 = lane + pass * 32;        // column group 0..63 (4 cols)
            float4 bv = *(const float4*)&sbias[c4 * 4];
#pragma unroll 1
            for (int i = 0; i < 16; i++) {
                int r = wg * 16 + i;
                int lr = r & 63;
                float4 a = *(const float4*)&sY[r * 260 + c4 * 4];
                a.x *= ep; a.y *= ep; a.z *= ep; a.w *= ep;
                int st = sOff[gl * 65 + lr], en = sOff[gl * 65 + lr + 1];
                for (int e = st; e < en; e++) {
                    int u = sEnt[gl * 512 + e];
                    float c = (float)(u >> 8);
                    float4 hv = *(const float4*)&sY[(gl * 64 + (u & 63)) * 260 + c4 * 4];
                    a.x = fmaf(c, hv.x, a.x);
                    a.y = fmaf(c, hv.y, a.y);
                    a.z = fmaf(c, hv.z, a.z);
                    a.w = fmaf(c, hv.w, a.w);
                }
                float4 v;
                v.x = fmaxf(a.x + bv.x, 0.f);
                v.y = fmaxf(a.y + bv.y, 0.f);
                v.z = fmaxf(a.z + bv.z, 0.f);
                v.w = fmaxf(a.w + bv.w, 0.f);
                *(float4*)&C[(row0 + r) * 256 + c4 * 4] = v;
            }
        }
    }
}

__global__ __launch_bounds__(256, 1)
void gemm_mma(const float* __restrict__ A,
              const float* __restrict__ Bb, const float* __restrict__ Bs,
              const float* __restrict__ bias, float* __restrict__ C)
{
    gemm_body<0>(A, Bb, Bs, bias, C, nullptr, nullptr, nullptr, 0);
}

__global__ __launch_bounds__(256, 1)
void gemm_fused(const float* __restrict__ A,
                const float* __restrict__ Bb, const float* __restrict__ Bs,
                const float* __restrict__ bias, float* __restrict__ C,
                const int* __restrict__ ent, const int* __restrict__ off,
                const float* __restrict__ eps, int layer)
{
    gemm_body<1>(A, Bb, Bs, bias, C, ent, off, eps, layer);
}

// ---------------- per-graph pairwise min distance (fp32) ----------------
#define MD_SMEM ((64 * 257 + 64 + 64) * 4)
__global__ __launch_bounds__(256)
void mindist_kernel(const float* __restrict__ h, float* __restrict__ mind)
{
    extern __shared__ float sm[];
    float* sh  = sm;
    float* ssq = sm + 64 * 257;
    int*   smn = (int*)(ssq + 64);
    int b = blockIdx.x, m = blockIdx.y;
    int tid = threadIdx.x;

    const float* H = h + ((size_t)m * N_ + (size_t)b * NPG_) * D_;
    for (int idx = tid; idx < NPG_ * D_; idx += 256) {
        int r = idx >> 8, d = idx & 255;
        sh[r * 257 + d] = H[idx];
    }
    if (tid < 64) smn[tid] = 0x7f7fffff;
    __syncthreads();

    if (tid < 64) {
        const float* row = sh + tid * 257;
        float s = 0.f;
        for (int d = 0; d < D_; d++) s = fmaf(row[d], row[d], s);
        ssq[tid] = s;
    }
    __syncthreads();

    int i  = tid >> 2;
    int j0 = (tid & 3) * 16;
    float acc[16];
#pragma unroll
    for (int jj = 0; jj < 16; jj++) acc[jj] = 0.f;
    const float* ri = sh + i * 257;
    for (int d = 0; d < D_; d++) {
        float a = ri[d];
#pragma unroll
        for (int jj = 0; jj < 16; jj++)
            acc[jj] = fmaf(a, sh[(j0 + jj) * 257 + d], acc[jj]);
    }
    float sqi = ssq[i];
    float lmin = 3.0e38f;
#pragma unroll
    for (int jj = 0; jj < 16; jj++) {
        int j = j0 + jj;
        float d2 = fmaxf(sqi + ssq[j] - 2.0f * acc[jj], 0.f);
        if (j == i) d2 += 1.0e9f;
        lmin = fminf(lmin, d2);
    }
    atomicMin(&smn[i], __float_as_int(lmin));
    __syncthreads();
    if (tid < 64)
        mind[(size_t)m * N_ + (size_t)b * NPG_ + tid] = __int_as_float(smn[tid]);
}

// ------------- gumbel sample + argmax + anchor set (exact JAX) -----------
__global__ void gumbel_kernel(const float* __restrict__ mind,
                              int* __restrict__ anchor,
                              int it, unsigned fk0, unsigned fk1,
                              int mind_stride_m)
{
    int b = blockIdx.x, m = blockIdx.y;
    int p = threadIdx.x;
    __shared__ float sg[NPG_];
    int node = m * N_ + b * NPG_ + p;

    unsigned o0, o1;
    tf2x32(fk0, fk1, 0u, (unsigned)node, &o0, &o1);
    unsigned bits = o0 ^ o1;
    float f = __uint_as_float((bits >> 9) | 0x3f800000u) - 1.0f;
    const float mn = 1e-9f;
    float u = fmaxf(mn, f * (1.0f - mn) + mn);
    float md = mind[(size_t)m * mind_stride_m + b * NPG_ + p];
    float logit = -md - 10.0f * (anchor[node] > 0 ? 1.0f : 0.0f);
    sg[p] = logit - logf(-logf(u));
    __syncthreads();
    if (p == 0) {
        int best = 0; float bv = sg[0];
        for (int q = 1; q < NPG_; q++)
            if (sg[q] > bv) { bv = sg[q]; best = q; }
        anchor[m * N_ + b * NPG_ + best] = it;
    }
}

// ---------------- xcur = tx * anchor_emb[anchor] + tx ----------------
__global__ void update_xcur_kernel(const float* __restrict__ h0,
                                   const int* __restrict__ anchor,
                                   const float* __restrict__ emb,
                                   float* __restrict__ xc)
{
    size_t idx = (size_t)blockIdx.x * 256 + threadIdx.x;
    size_t mn = idx >> 8;
    int d = (int)(idx & 255);
    int n = (int)(mn & (N_ - 1));
    int a = anchor[mn];
    float tv = h0[((size_t)n << 8) + d];
    xc[idx] = tv * emb[a * D_ + d] + tv;
}

// --------- finalize: per-m group mean -> dot W_pred -> mean over m --------
__global__ void finalize_kernel(const float* __restrict__ hn,
                                const float* __restrict__ Wp,
                                const float* __restrict__ bp,
                                float* __restrict__ out)
{
    int b = blockIdx.x;
    int d = threadIdx.x;
    __shared__ float g[M_][D_];
#pragma unroll
    for (int m = 0; m < M_; m++) {
        const float* base = hn + ((size_t)m * N_ + (size_t)b * NPG_) * D_ + d;
        float s = 0.f;
        for (int p = 0; p < NPG_; p++) s += base[(size_t)p * D_];
        g[m][d] = s * (1.0f / (float)NPG_);
    }
    __syncthreads();
    if (d < TASKS_) {
        float acc = 0.f;
#pragma unroll
        for (int m = 0; m < M_; m++) {
            float a = 0.f;
            for (int k = 0; k < D_; k++)
                a = fmaf(g[m][k], Wp[k * TASKS_ + d], a);
            acc += a + bp[d];
        }
        out[b * TASKS_ + d] = acc * (1.0f / (float)M_);
    }
}

// ---------------- host orchestration ----------------
extern "C" void kernel_launch(void* const* d_in, const int* in_sizes, int n_in,
                              void* d_out, int out_size)
{
    const float* x     = (const float*)d_in[0];
    const float* W_enc = (const float*)d_in[1];
    const float* b_enc = (const float*)d_in[2];
    const float* gW1   = (const float*)d_in[3];
    const float* gb1   = (const float*)d_in[4];
    const float* gW2   = (const float*)d_in[5];
    const float* gb2   = (const float*)d_in[6];
    const float* eps   = (const float*)d_in[7];
    const float* aemb  = (const float*)d_in[8];
    const float* Wn2n  = (const float*)d_in[9];
    const float* bn2n  = (const float*)d_in[10];
    const float* Wp    = (const float*)d_in[11];
    const float* bp    = (const float*)d_in[12];
    const int*   esrc  = (const int*)d_in[13];
    const int*   edst  = (const int*)d_in[14];
    float* out = (float*)d_out;

    float *h0, *xc, *hA, *t, *mind, *wtb, *wts; int *anc, *ent, *off;
    cudaGetSymbolAddress((void**)&h0,   g_h0);
    cudaGetSymbolAddress((void**)&xc,   g_xcur);
    cudaGetSymbolAddress((void**)&hA,   g_hA);
    cudaGetSymbolAddress((void**)&t,    g_t);
    cudaGetSymbolAddress((void**)&mind, g_mind);
    cudaGetSymbolAddress((void**)&anc,  g_anchor);
    cudaGetSymbolAddress((void**)&wtb,  g_wt_big);
    cudaGetSymbolAddress((void**)&wts,  g_wt_small);
    cudaGetSymbolAddress((void**)&ent,  g_csr_ent);
    cudaGetSymbolAddress((void**)&off,  g_csr_off);

    cudaFuncSetAttribute(mindist_kernel, cudaFuncAttributeMaxDynamicSharedMemorySize, MD_SMEM);
    cudaFuncSetAttribute(gemm_mma, cudaFuncAttributeMaxDynamicSharedMemorySize, GC_SMEM_BYTES);
    cudaFuncSetAttribute(gemm_fused, cudaFuncAttributeMaxDynamicSharedMemorySize, GC_SMEM_BYTES);

    unsigned fk0[NA_ + 1], fk1[NA_ + 1];
    for (int i = 1; i <= NA_; i++)
        tf2x32(0u, 42u, 0u, (unsigned)i, &fk0[i], &fk1[i]);

    const dim3 graph_full(B_, M_), graph_q(B_, 1);
    const int  mma_full = (M_ * N_) / 128;   // 512 blocks
    const int  mma_q    = N_ / 128;          // 128 blocks
    const int  bcast_blocks = (M_ * N_ * D_) / 256;

    auto WB = [&](int id) { return wtb + (size_t)id * 65536; };
    auto WS = [&](int id) { return wts + (size_t)id * 65536; };

    prep_csr_kernel<<<B_, 256>>>(esrc, edst, ent, off);
    split_w_kernel<<<dim3(11, 16), 256>>>(gW1, gW2, Wn2n, wtb, wts);
    encoder_kernel<<<N_, 256>>>(x, W_enc, b_enc, h0);
    zero_anchor_kernel<<<(M_ * N_) / 256, 256>>>(anc);

    // ---- iteration 1: xcur broadcast of h0 -> compute once over N rows ----
    {
        const float* cur = h0;
        for (int l = 0; l < L_; l++) {
            gemm_fused<<<mma_q, 256, GC_SMEM_BYTES>>>(
                cur, WB(l), WS(l), gb1 + l * D_, t, ent, off, eps, l);
            gemm_mma<<<mma_q, 256, GC_SMEM_BYTES>>>(t, WB(5 + l), WS(5 + l), gb2 + l * D_, hA);
            cur = hA;
        }
        mindist_kernel<<<graph_q, 256, MD_SMEM>>>(hA, mind);
        gumbel_kernel<<<graph_full, 64>>>(mind, anc, 1, fk0[1], fk1[1], 0);
        update_xcur_kernel<<<bcast_blocks, 256>>>(h0, anc, aemb, xc);
    }

    // ---- iteration 2: full per-m pipeline ----
    {
        const float* cur = xc;
        for (int l = 0; l < L_; l++) {
            gemm_fused<<<mma_full, 256, GC_SMEM_BYTES>>>(
                cur, WB(l), WS(l), gb1 + l * D_, t, ent, off, eps, l);
            gemm_mma<<<mma_full, 256, GC_SMEM_BYTES>>>(t, WB(5 + l), WS(5 + l), gb2 + l * D_, hA);
            cur = hA;
        }
        mindist_kernel<<<graph_full, 256, MD_SMEM>>>(hA, mind);
        gumbel_kernel<<<graph_full, 64>>>(mind, anc, 2, fk0[2], fk1[2], N_);
        update_xcur_kernel<<<bcast_blocks, 256>>>(h0, anc, aemb, xc);
    }

    // ---- final GNN on xcur ----
    {
        const float* cur = xc;
        for (int l = 0; l < L_; l++) {
            gemm_fused<<<mma_full, 256, GC_SMEM_BYTES>>>(
                cur, WB(l), WS(l), gb1 + l * D_, t, ent, off, eps, l);
            gemm_mma<<<mma_full, 256, GC_SMEM_BYTES>>>(t, WB(5 + l), WS(5 + l), gb2 + l * D_, hA);
            cur = hA;
        }
    }
    gemm_mma<<<mma_full, 256, GC_SMEM_BYTES>>>(hA, WB(10), WS(10), bn2n, t);
    finalize_kernel<<<B_, 256>>>(t, Wp, bp, out);
}

// round 15
// speedup vs baseline: 3.7020x; 1.3666x over previous
#include <cuda_runtime.h>
#include <cuda_fp16.h>
#include <cstdint>

// ---------------- problem constants ----------------
#define M_     4
#define B_     256
#define NPG_   64
#define N_     16384
#define DEG_   8
#define E_     131072
#define DF_    16
#define D_     256
#define L_     5
#define NA_    2
#define TASKS_ 10

// ---------------- device scratch (no allocs allowed) ----------------
__device__ float    g_h0[(size_t)N_ * D_];
__device__ float    g_xcur[(size_t)M_ * N_ * D_];
__device__ float    g_hA[(size_t)M_ * N_ * D_];
__device__ float    g_t[(size_t)M_ * N_ * D_];
__device__ float    g_mind[(size_t)M_ * N_];
__device__ int      g_anchor[(size_t)M_ * N_];
// fp16-split, frag-permuted weights (packed half2 words): [11][32768]
__device__ unsigned g_wt_big[11 * 32768];
__device__ unsigned g_wt_small[11 * 32768];
// static per-graph dedup'd adjacency CSR (counts): entry = src | (cnt<<8)
__device__ int      g_csr_ent[B_ * 512];
__device__ int      g_csr_off[B_ * 65];

static __device__ __forceinline__ uint32_t smem_u32(const void* p) {
    uint32_t a;
    asm("{ .reg .u64 t; cvta.to.shared.u64 t, %1; cvt.u32.u64 %0, t; }"
        : "=r"(a) : "l"(p));
    return a;
}
static __device__ __forceinline__ void cp16(uint32_t dst, const void* src) {
    asm volatile("cp.async.cg.shared.global [%0], [%1], 16;"
                 :: "r"(dst), "l"(src) : "memory");
}
#define CP_COMMIT() asm volatile("cp.async.commit_group;" ::: "memory")
#define CP_WAIT(n)  asm volatile("cp.async.wait_group %0;" :: "n"(n) : "memory")

static __device__ __forceinline__ unsigned packh2(float a, float b) {
    __half ha = __float2half_rn(a), hb = __float2half_rn(b);
    return ((unsigned)__half_as_ushort(hb) << 16) | (unsigned)__half_as_ushort(ha);
}
// split x = hi + lo (both fp16); returns packed words for a pair of values
static __device__ __forceinline__ void split2(float x, float y,
                                              unsigned* big, unsigned* small) {
    __half hx = __float2half_rn(x), hy = __float2half_rn(y);
    float rx = x - __half2float(hx), ry = y - __half2float(hy);
    *big = ((unsigned)__half_as_ushort(hy) << 16) | (unsigned)__half_as_ushort(hx);
    __half sx = __float2half_rn(rx), sy = __float2half_rn(ry);
    *small = ((unsigned)__half_as_ushort(sy) << 16) | (unsigned)__half_as_ushort(sx);
}

// m16n8k16 f16 mma, fp32 accum (sm_80+ PTX, legal on base compute_103)
#define MMA_F16(d, a, b) \
    asm volatile("mma.sync.aligned.m16n8k16.row.col.f32.f16.f16.f32 " \
                 "{%0,%1,%2,%3}, {%4,%5,%6,%7}, {%8,%9}, {%0,%1,%2,%3};" \
                 : "+f"((d)[0]), "+f"((d)[1]), "+f"((d)[2]), "+f"((d)[3]) \
                 : "r"((a)[0]), "r"((a)[1]), "r"((a)[2]), "r"((a)[3]), \
                   "r"((b)[0]), "r"((b)[1]))

// ---------------- threefry2x32 (exact JAX rounds) ----------------
#define TF_ROT(x,d) (((x) << (d)) | ((x) >> (32 - (d))))
static __host__ __device__ __forceinline__
void tf2x32(unsigned k0, unsigned k1, unsigned x0, unsigned x1,
            unsigned* o0, unsigned* o1)
{
    unsigned ks2 = k0 ^ k1 ^ 0x1BD11BDAu;
    x0 += k0; x1 += k1;
    x0 += x1; x1 = TF_ROT(x1,13); x1 ^= x0;
    x0 += x1; x1 = TF_ROT(x1,15); x1 ^= x0;
    x0 += x1; x1 = TF_ROT(x1,26); x1 ^= x0;
    x0 += x1; x1 = TF_ROT(x1, 6); x1 ^= x0;
    x0 += k1; x1 += ks2 + 1u;
    x0 += x1; x1 = TF_ROT(x1,17); x1 ^= x0;
    x0 += x1; x1 = TF_ROT(x1,29); x1 ^= x0;
    x0 += x1; x1 = TF_ROT(x1,16); x1 ^= x0;
    x0 += x1; x1 = TF_ROT(x1,24); x1 ^= x0;
    x0 += ks2; x1 += k0 + 2u;
    x0 += x1; x1 = TF_ROT(x1,13); x1 ^= x0;
    x0 += x1; x1 = TF_ROT(x1,15); x1 ^= x0;
    x0 += x1; x1 = TF_ROT(x1,26); x1 ^= x0;
    x0 += x1; x1 = TF_ROT(x1, 6); x1 ^= x0;
    x0 += k0; x1 += k1 + 3u;
    x0 += x1; x1 = TF_ROT(x1,17); x1 ^= x0;
    x0 += x1; x1 = TF_ROT(x1,29); x1 ^= x0;
    x0 += x1; x1 = TF_ROT(x1,16); x1 ^= x0;
    x0 += x1; x1 = TF_ROT(x1,24); x1 ^= x0;
    x0 += k1; x1 += ks2 + 4u;
    x0 += x1; x1 = TF_ROT(x1,13); x1 ^= x0;
    x0 += x1; x1 = TF_ROT(x1,15); x1 ^= x0;
    x0 += x1; x1 = TF_ROT(x1,26); x1 ^= x0;
    x0 += x1; x1 = TF_ROT(x1, 6); x1 ^= x0;
    x0 += ks2; x1 += k0 + 5u;
    *o0 = x0; *o1 = x1;
}

// ---------------- encoder: h0 = relu(x @ W_enc + b_enc) ----------------
__global__ void encoder_kernel(const float* __restrict__ x,
                               const float* __restrict__ W,
                               const float* __restrict__ b,
                               float* __restrict__ h0)
{
    int n = blockIdx.x;
    int d = threadIdx.x;
    __shared__ float xr[DF_];
    if (d < DF_) xr[d] = x[n * DF_ + d];
    __syncthreads();
    float acc = b[d];
#pragma unroll
    for (int k = 0; k < DF_; k++) acc = fmaf(xr[k], W[k * D_ + d], acc);
    h0[(size_t)n * D_ + d] = fmaxf(acc, 0.f);
}

__global__ void zero_anchor_kernel(int* __restrict__ anc)
{
    int idx = blockIdx.x * 256 + threadIdx.x;
    if (idx < M_ * N_) anc[idx] = 0;
}

// ----- build per-graph dedup'd CSR once (edges are static) -----
__global__ void prep_csr_kernel(const int* __restrict__ esrc,
                                const int* __restrict__ edst,
                                int* __restrict__ ent, int* __restrict__ off)
{
    __shared__ int cnt[64 * 64];
    __shared__ int nnz[64], base[65];
    int g = blockIdx.x, tid = threadIdx.x;
    for (int i = tid; i < 4096; i += 256) cnt[i] = 0;
    __syncthreads();
    int eb = g * 512;
#pragma unroll
    for (int k = 0; k < 2; k++) {
        int e = eb + tid + k * 256;
        int s = esrc[e] & 63, d = edst[e] & 63;
        atomicAdd(&cnt[d * 64 + s], 1);
    }
    __syncthreads();
    if (tid < 64) {
        int c = 0;
        for (int s = 0; s < 64; s++) c += (cnt[tid * 64 + s] != 0);
        nnz[tid] = c;
    }
    __syncthreads();
    if (tid == 0) {
        int a = 0;
        for (int d = 0; d < 64; d++) { base[d] = a; a += nnz[d]; }
        base[64] = a;
    }
    __syncthreads();
    if (tid < 64) {
        int o = base[tid];
        for (int s = 0; s < 64; s++) {
            int c = cnt[tid * 64 + s];
            if (c) ent[g * 512 + (o++)] = s | (c << 8);
        }
        off[g * 65 + tid] = base[tid];
        if (tid == 0) off[g * 65 + 64] = base[64];
    }
}

// ---- weight fp16-split + pack, permuted to m16n8k16 B-frag order ----
// word w bits: reg[0], lane[1:6), ks[6], nt[7:10), wn[10:12), ch[12:15)
// n = wn*64 + nt*8 + (lane>>2); k0 = ch*32 + ks*16 + (lane&3)*2 + reg*8
// word packs (k0, k0+1)
__global__ void split_w_kernel(const float* __restrict__ gW1,
                               const float* __restrict__ gW2,
                               const float* __restrict__ Wn2n,
                               unsigned* __restrict__ big,
                               unsigned* __restrict__ small)
{
    int id = blockIdx.x;  // 0..10
    const float* W = (id < 5) ? gW1 + (size_t)id * 65536
                   : (id < 10) ? gW2 + (size_t)(id - 5) * 65536
                   : Wn2n;
    int base = blockIdx.y * 2048;
    for (int i = threadIdx.x; i < 2048; i += 256) {
        int w = base + i;
        int reg = w & 1, ln = (w >> 1) & 31, ks = (w >> 6) & 1;
        int nt = (w >> 7) & 7, wn = (w >> 10) & 3, ch = (w >> 12) & 7;
        int n = wn * 64 + nt * 8 + (ln >> 2);
        int k0 = ch * 32 + ks * 16 + (ln & 3) * 2 + reg * 8;
        float v0 = W[k0 * 256 + n], v1 = W[(k0 + 1) * 256 + n];
        unsigned wb, wsm;
        split2(v0, v1, &wb, &wsm);
        big[(size_t)id * 32768 + w] = wb;
        small[(size_t)id * 32768 + w] = wsm;
    }
}

// ============ GEMM: block 128 rows x 256 cols, fp16x2 3-term ============
// 8 warps (2m x 4n), warp tile 64x64. A: fp32 LDG + in-reg fp16 split,
// packed-half2 smem stride-20. B: cp.async double-buffered, frag-permuted.
// FUSED=1: epilogue t = relu(Ctilde @ Y + bias), Ctilde = (1+eps)I + C.

#define GC_AB    0          // 128*20 words
#define GC_AS    2560
#define GC_B0B   5120       // 4096 words each
#define GC_B0S   9216
#define GC_B1B   13312
#define GC_B1S   17408
#define GC_BIAS  33280      // above sY overlay (128*260 = 33280 words)
#define GC_ENT   33536
#define GC_OFF   34560
#define GC_SMEM_BYTES ((34560 + 132) * 4)

template <int FUSED>
__device__ __forceinline__
void gemm_body(const float* __restrict__ A,
               const unsigned* __restrict__ Bb, const unsigned* __restrict__ Bs,
               const float* __restrict__ bias, float* __restrict__ C,
               const int* __restrict__ ent, const int* __restrict__ off,
               const float* __restrict__ eps, int layer)
{
    extern __shared__ float sm[];
    unsigned* sAb = (unsigned*)sm + GC_AB;
    unsigned* sAs = (unsigned*)sm + GC_AS;
    float* sbias = sm + GC_BIAS;
    int* sEnt = (int*)(sm + GC_ENT);
    int* sOff = (int*)(sm + GC_OFF);
    uint32_t smb = smem_u32(sm);

    const int tid = threadIdx.x, lane = tid & 31, wid = tid >> 5;
    const int wm = wid >> 2, wn = wid & 3;
    const size_t row0 = (size_t)blockIdx.x * 128;

    sbias[tid] = bias[tid];
    if (FUSED) {
        int g0 = (int)((row0 & (N_ - 1)) >> 6);
        for (int i = tid; i < 1024; i += 256)
            sEnt[i] = ent[(size_t)(g0 + (i >> 9)) * 512 + (i & 511)];
        if (tid < 130) {
            int gg = tid / 65;
            sOff[tid] = off[(size_t)(g0 + gg) * 65 + (tid - gg * 65)];
        }
    }

    float acc[4][8][4];
#pragma unroll
    for (int mt = 0; mt < 4; mt++)
#pragma unroll
        for (int nt = 0; nt < 8; nt++)
#pragma unroll
            for (int r = 0; r < 4; r++) acc[mt][nt][r] = 0.f;

    const int R  = tid >> 1;
    const int kh = (tid & 1) * 16;              // 16 floats of the 32-K chunk
    const int cpb = (tid & 1) * 8;              // 8 packed words
    const float* Arow = A + (row0 + R) * 256 + kh;

    const uint32_t bufb[2] = { smb + GC_B0B * 4, smb + GC_B1B * 4 };
    const uint32_t bufs[2] = { smb + GC_B0S * 4, smb + GC_B1S * 4 };

    // prologue: cp.async B chunk 0; prefetch A chunk 0
#pragma unroll
    for (int q = 0; q < 4; q++) {
        cp16(bufb[0] + (uint32_t)(tid + q * 256) * 16, Bb + (tid + q * 256) * 4);
        cp16(bufs[0] + (uint32_t)(tid + q * 256) * 16, Bs + (tid + q * 256) * 4);
    }
    CP_COMMIT();
    float4 pa[4];
#pragma unroll
    for (int q = 0; q < 4; q++) pa[q] = *(const float4*)(Arow + q * 4);

#pragma unroll 1
    for (int ch = 0; ch < 8; ch++) {
        if (ch) __syncthreads();
        // store A split chunk (packed half2, stride-20 words)
#pragma unroll
        for (int q = 0; q < 4; q++) {
            unsigned b0, s0, b1, s1;
            split2(pa[q].x, pa[q].y, &b0, &s0);
            split2(pa[q].z, pa[q].w, &b1, &s1);
            sAb[R * 20 + cpb + 2 * q]     = b0;
            sAb[R * 20 + cpb + 2 * q + 1] = b1;
            sAs[R * 20 + cpb + 2 * q]     = s0;
            sAs[R * 20 + cpb + 2 * q + 1] = s1;
        }
        if (ch < 7) {
            const unsigned* srcb = Bb + (ch + 1) * 4096;
            const unsigned* srcs = Bs + (ch + 1) * 4096;
            uint32_t db = bufb[(ch + 1) & 1], ds = bufs[(ch + 1) & 1];
#pragma unroll
            for (int q = 0; q < 4; q++) {
                cp16(db + (uint32_t)(tid + q * 256) * 16, srcb + (tid + q * 256) * 4);
                cp16(ds + (uint32_t)(tid + q * 256) * 16, srcs + (tid + q * 256) * 4);
            }
            CP_COMMIT();
#pragma unroll
            for (int q = 0; q < 4; q++)
                pa[q] = *(const float4*)(Arow + (ch + 1) * 32 + q * 4);
            CP_WAIT(1);
        } else {
            CP_WAIT(0);
        }
        __syncthreads();

        const unsigned* cBb = (unsigned*)sm + ((ch & 1) ? GC_B1B : GC_B0B);
        const unsigned* cBs = (unsigned*)sm + ((ch & 1) ? GC_B1S : GC_B0S);
#pragma unroll
        for (int ks = 0; ks < 2; ks++) {
            uint32_t ab[4][4], as_[4][4];
#pragma unroll
            for (int mt = 0; mt < 4; mt++) {
                int o = (wm * 64 + mt * 16 + (lane >> 2)) * 20 + ks * 8 + (lane & 3);
                ab[mt][0]  = sAb[o];
                ab[mt][1]  = sAb[o + 8 * 20];
                ab[mt][2]  = sAb[o + 4];
                ab[mt][3]  = sAb[o + 8 * 20 + 4];
                as_[mt][0] = sAs[o];
                as_[mt][1] = sAs[o + 8 * 20];
                as_[mt][2] = sAs[o + 4];
                as_[mt][3] = sAs[o + 8 * 20 + 4];
            }
            uint32_t bb[8][2], bs[8][2];
#pragma unroll
            for (int nt = 0; nt < 8; nt++) {
                int o = ((wn * 8 + nt) * 2 + ks) * 64 + lane * 2;
                uint2 vb = *(const uint2*)&cBb[o];
                uint2 vs = *(const uint2*)&cBs[o];
                bb[nt][0] = vb.x; bb[nt][1] = vb.y;
                bs[nt][0] = vs.x; bs[nt][1] = vs.y;
            }
#pragma unroll
            for (int mt = 0; mt < 4; mt++)
#pragma unroll
                for (int nt = 0; nt < 8; nt++) {
                    MMA_F16(acc[mt][nt], ab[mt], bb[nt]);
                    MMA_F16(acc[mt][nt], ab[mt], bs[nt]);
                    MMA_F16(acc[mt][nt], as_[mt], bb[nt]);
                }
        }
    }

    if (!FUSED) {
#pragma unroll
        for (int mt = 0; mt < 4; mt++) {
            size_t rg = row0 + wm * 64 + mt * 16 + (lane >> 2);
#pragma unroll
            for (int nt = 0; nt < 8; nt++) {
                int cl = wn * 64 + nt * 8 + (lane & 3) * 2;
                float b0 = sbias[cl], b1 = sbias[cl + 1];
                float2 v0, v1;
                v0.x = fmaxf(acc[mt][nt][0] + b0, 0.f);
                v0.y = fmaxf(acc[mt][nt][1] + b1, 0.f);
                v1.x = fmaxf(acc[mt][nt][2] + b0, 0.f);
                v1.y = fmaxf(acc[mt][nt][3] + b1, 0.f);
                *(float2*)&C[rg * 256 + cl] = v0;
                *(float2*)&C[(rg + 8) * 256 + cl] = v1;
            }
        }
    } else {
        float* sY = sm;   // 128 x 260 overlays operand buffers
        __syncthreads();
#pragma unroll
        for (int mt = 0; mt < 4; mt++) {
            int rg = wm * 64 + mt * 16 + (lane >> 2);
#pragma unroll
            for (int nt = 0; nt < 8; nt++) {
                int cl = wn * 64 + nt * 8 + (lane & 3) * 2;
                *(float2*)&sY[rg * 260 + cl] =
                    make_float2(acc[mt][nt][0], acc[mt][nt][1]);
                *(float2*)&sY[(rg + 8) * 260 + cl] =
                    make_float2(acc[mt][nt][2], acc[mt][nt][3]);
            }
        }
        __syncthreads();
        float ep = 1.0f + eps[layer];
        int wg = wid, gl = wg >> 2;
#pragma unroll 1
        for (int pass = 0; pass < 2; pass++) {
            int c4 = lane + pass * 32;
            float4 bv = *(const float4*)&sbias[c4 * 4];
#pragma unroll 1
            for (int i = 0; i < 16; i++) {
                int r = wg * 16 + i;
                int lr = r & 63;
                float4 a = *(const float4*)&sY[r * 260 + c4 * 4];
                a.x *= ep; a.y *= ep; a.z *= ep; a.w *= ep;
                int st = sOff[gl * 65 + lr], en = sOff[gl * 65 + lr + 1];
                for (int e = st; e < en; e++) {
                    int u = sEnt[gl * 512 + e];
                    float c = (float)(u >> 8);
                    float4 hv = *(const float4*)&sY[(gl * 64 + (u & 63)) * 260 + c4 * 4];
                    a.x = fmaf(c, hv.x, a.x);
                    a.y = fmaf(c, hv.y, a.y);
                    a.z = fmaf(c, hv.z, a.z);
                    a.w = fmaf(c, hv.w, a.w);
                }
                float4 v;
                v.x = fmaxf(a.x + bv.x, 0.f);
                v.y = fmaxf(a.y + bv.y, 0.f);
                v.z = fmaxf(a.z + bv.z, 0.f);
                v.w = fmaxf(a.w + bv.w, 0.f);
                *(float4*)&C[(row0 + r) * 256 + c4 * 4] = v;
            }
        }
    }
}

__global__ __launch_bounds__(256, 1)
void gemm_mma(const float* __restrict__ A,
              const unsigned* __restrict__ Bb, const unsigned* __restrict__ Bs,
              const float* __restrict__ bias, float* __restrict__ C)
{
    gemm_body<0>(A, Bb, Bs, bias, C, nullptr, nullptr, nullptr, 0);
}

__global__ __launch_bounds__(256, 1)
void gemm_fused(const float* __restrict__ A,
                const unsigned* __restrict__ Bb, const unsigned* __restrict__ Bs,
                const float* __restrict__ bias, float* __restrict__ C,
                const int* __restrict__ ent, const int* __restrict__ off,
                const float* __restrict__ eps, int layer)
{
    gemm_body<1>(A, Bb, Bs, bias, C, ent, off, eps, layer);
}

// ---------------- per-graph pairwise min distance (fp32) ----------------
#define MD_SMEM ((64 * 257 + 64 + 64) * 4)
__global__ __launch_bounds__(256)
void mindist_kernel(const float* __restrict__ h, float* __restrict__ mind)
{
    extern __shared__ float sm[];
    float* sh  = sm;
    float* ssq = sm + 64 * 257;
    int*   smn = (int*)(ssq + 64);
    int b = blockIdx.x, m = blockIdx.y;
    int tid = threadIdx.x;

    const float* H = h + ((size_t)m * N_ + (size_t)b * NPG_) * D_;
    for (int idx = tid; idx < NPG_ * D_; idx += 256) {
        int r = idx >> 8, d = idx & 255;
        sh[r * 257 + d] = H[idx];
    }
    if (tid < 64) smn[tid] = 0x7f7fffff;
    __syncthreads();

    if (tid < 64) {
        const float* row = sh + tid * 257;
        float s = 0.f;
        for (int d = 0; d < D_; d++) s = fmaf(row[d], row[d], s);
        ssq[tid] = s;
    }
    __syncthreads();

    int i  = tid >> 2;
    int j0 = (tid & 3) * 16;
    float acc[16];
#pragma unroll
    for (int jj = 0; jj < 16; jj++) acc[jj] = 0.f;
    const float* ri = sh + i * 257;
    for (int d = 0; d < D_; d++) {
        float a = ri[d];
#pragma unroll
        for (int jj = 0; jj < 16; jj++)
            acc[jj] = fmaf(a, sh[(j0 + jj) * 257 + d], acc[jj]);
    }
    float sqi = ssq[i];
    float lmin = 3.0e38f;
#pragma unroll
    for (int jj = 0; jj < 16; jj++) {
        int j = j0 + jj;
        float d2 = fmaxf(sqi + ssq[j] - 2.0f * acc[jj], 0.f);
        if (j == i) d2 += 1.0e9f;
        lmin = fminf(lmin, d2);
    }
    atomicMin(&smn[i], __float_as_int(lmin));
    __syncthreads();
    if (tid < 64)
        mind[(size_t)m * N_ + (size_t)b * NPG_ + tid] = __int_as_float(smn[tid]);
}

// ------------- gumbel sample + argmax + anchor set (exact JAX) -----------
__global__ void gumbel_kernel(const float* __restrict__ mind,
                              int* __restrict__ anchor,
                              int it, unsigned fk0, unsigned fk1,
                              int mind_stride_m)
{
    int b = blockIdx.x, m = blockIdx.y;
    int p = threadIdx.x;
    __shared__ float sg[NPG_];
    int node = m * N_ + b * NPG_ + p;

    unsigned o0, o1;
    tf2x32(fk0, fk1, 0u, (unsigned)node, &o0, &o1);
    unsigned bits = o0 ^ o1;
    float f = __uint_as_float((bits >> 9) | 0x3f800000u) - 1.0f;
    const float mn = 1e-9f;
    float u = fmaxf(mn, f * (1.0f - mn) + mn);
    float md = mind[(size_t)m * mind_stride_m + b * NPG_ + p];
    float logit = -md - 10.0f * (anchor[node] > 0 ? 1.0f : 0.0f);
    sg[p] = logit - logf(-logf(u));
    __syncthreads();
    if (p == 0) {
        int best = 0; float bv = sg[0];
        for (int q = 1; q < NPG_; q++)
            if (sg[q] > bv) { bv = sg[q]; best = q; }
        anchor[m * N_ + b * NPG_ + best] = it;
    }
}

// ---------------- xcur = tx * anchor_emb[anchor] + tx ----------------
__global__ void update_xcur_kernel(const float* __restrict__ h0,
                                   const int* __restrict__ anchor,
                                   const float* __restrict__ emb,
                                   float* __restrict__ xc)
{
    size_t idx = (size_t)blockIdx.x * 256 + threadIdx.x;
    size_t mn = idx >> 8;
    int d = (int)(idx & 255);
    int n = (int)(mn & (N_ - 1));
    int a = anchor[mn];
    float tv = h0[((size_t)n << 8) + d];
    xc[idx] = tv * emb[a * D_ + d] + tv;
}

// --------- finalize: per-m group mean -> dot W_pred -> mean over m --------
__global__ void finalize_kernel(const float* __restrict__ hn,
                                const float* __restrict__ Wp,
                                const float* __restrict__ bp,
                                float* __restrict__ out)
{
    int b = blockIdx.x;
    int d = threadIdx.x;
    __shared__ float g[M_][D_];
#pragma unroll
    for (int m = 0; m < M_; m++) {
        const float* base = hn + ((size_t)m * N_ + (size_t)b * NPG_) * D_ + d;
        float s = 0.f;
        for (int p = 0; p < NPG_; p++) s += base[(size_t)p * D_];
        g[m][d] = s * (1.0f / (float)NPG_);
    }
    __syncthreads();
    if (d < TASKS_) {
        float acc = 0.f;
#pragma unroll
        for (int m = 0; m < M_; m++) {
            float a = 0.f;
            for (int k = 0; k < D_; k++)
                a = fmaf(g[m][k], Wp[k * TASKS_ + d], a);
            acc += a + bp[d];
        }
        out[b * TASKS_ + d] = acc * (1.0f / (float)M_);
    }
}

// ---------------- host orchestration ----------------
extern "C" void kernel_launch(void* const* d_in, const int* in_sizes, int n_in,
                              void* d_out, int out_size)
{
    const float* x     = (const float*)d_in[0];
    const float* W_enc = (const float*)d_in[1];
    const float* b_enc = (const float*)d_in[2];
    const float* gW1   = (const float*)d_in[3];
    const float* gb1   = (const float*)d_in[4];
    const float* gW2   = (const float*)d_in[5];
    const float* gb2   = (const float*)d_in[6];
    const float* eps   = (const float*)d_in[7];
    const float* aemb  = (const float*)d_in[8];
    const float* Wn2n  = (const float*)d_in[9];
    const float* bn2n  = (const float*)d_in[10];
    const float* Wp    = (const float*)d_in[11];
    const float* bp    = (const float*)d_in[12];
    const int*   esrc  = (const int*)d_in[13];
    const int*   edst  = (const int*)d_in[14];
    float* out = (float*)d_out;

    float *h0, *xc, *hA, *t, *mind; int *anc, *ent, *off;
    unsigned *wtb, *wts;
    cudaGetSymbolAddress((void**)&h0,   g_h0);
    cudaGetSymbolAddress((void**)&xc,   g_xcur);
    cudaGetSymbolAddress((void**)&hA,   g_hA);
    cudaGetSymbolAddress((void**)&t,    g_t);
    cudaGetSymbolAddress((void**)&mind, g_mind);
    cudaGetSymbolAddress((void**)&anc,  g_anchor);
    cudaGetSymbolAddress((void**)&wtb,  g_wt_big);
    cudaGetSymbolAddress((void**)&wts,  g_wt_small);
    cudaGetSymbolAddress((void**)&ent,  g_csr_ent);
    cudaGetSymbolAddress((void**)&off,  g_csr_off);

    cudaFuncSetAttribute(mindist_kernel, cudaFuncAttributeMaxDynamicSharedMemorySize, MD_SMEM);
    cudaFuncSetAttribute(gemm_mma, cudaFuncAttributeMaxDynamicSharedMemorySize, GC_SMEM_BYTES);
    cudaFuncSetAttribute(gemm_fused, cudaFuncAttributeMaxDynamicSharedMemorySize, GC_SMEM_BYTES);

    unsigned fk0[NA_ + 1], fk1[NA_ + 1];
    for (int i = 1; i <= NA_; i++)
        tf2x32(0u, 42u, 0u, (unsigned)i, &fk0[i], &fk1[i]);

    const dim3 graph_full(B_, M_), graph_q(B_, 1);
    const int  mma_full = (M_ * N_) / 128;   // 512 blocks
    const int  mma_q    = N_ / 128;          // 128 blocks
    const int  bcast_blocks = (M_ * N_ * D_) / 256;

    auto WB = [&](int id) { return wtb + (size_t)id * 32768; };
    auto WS = [&](int id) { return wts + (size_t)id * 32768; };

    prep_csr_kernel<<<B_, 256>>>(esrc, edst, ent, off);
    split_w_kernel<<<dim3(11, 16), 256>>>(gW1, gW2, Wn2n, wtb, wts);
    encoder_kernel<<<N_, 256>>>(x, W_enc, b_enc, h0);
    zero_anchor_kernel<<<(M_ * N_) / 256, 256>>>(anc);

    // ---- iteration 1: xcur broadcast of h0 -> compute once over N rows ----
    {
        const float* cur = h0;
        for (int l = 0; l < L_; l++) {
            gemm_fused<<<mma_q, 256, GC_SMEM_BYTES>>>(
                cur, WB(l), WS(l), gb1 + l * D_, t, ent, off, eps, l);
            gemm_mma<<<mma_q, 256, GC_SMEM_BYTES>>>(t, WB(5 + l), WS(5 + l), gb2 + l * D_, hA);
            cur = hA;
        }
        mindist_kernel<<<graph_q, 256, MD_SMEM>>>(hA, mind);
        gumbel_kernel<<<graph_full, 64>>>(mind, anc, 1, fk0[1], fk1[1], 0);
        update_xcur_kernel<<<bcast_blocks, 256>>>(h0, anc, aemb, xc);
    }

    // ---- iteration 2: full per-m pipeline ----
    {
        const float* cur = xc;
        for (int l = 0; l < L_; l++) {
            gemm_fused<<<mma_full, 256, GC_SMEM_BYTES>>>(
                cur, WB(l), WS(l), gb1 + l * D_, t, ent, off, eps, l);
            gemm_mma<<<mma_full, 256, GC_SMEM_BYTES>>>(t, WB(5 + l), WS(5 + l), gb2 + l * D_, hA);
            cur = hA;
        }
        mindist_kernel<<<graph_full, 256, MD_SMEM>>>(hA, mind);
        gumbel_kernel<<<graph_full, 64>>>(mind, anc, 2, fk0[2], fk1[2], N_);
        update_xcur_kernel<<<bcast_blocks, 256>>>(h0, anc, aemb, xc);
    }

    // ---- final GNN on xcur ----
    {
        const float* cur = xc;
        for (int l = 0; l < L_; l++) {
            gemm_fused<<<mma_full, 256, GC_SMEM_BYTES>>>(
                cur, WB(l), WS(l), gb1 + l * D_, t, ent, off, eps, l);
            gemm_mma<<<mma_full, 256, GC_SMEM_BYTES>>>(t, WB(5 + l), WS(5 + l), gb2 + l * D_, hA);
            cur = hA;
        }
    }
    gemm_mma<<<mma_full, 256, GC_SMEM_BYTES>>>(hA, WB(10), WS(10), bn2n, t);
    finalize_kernel<<<B_, 256>>>(t, Wp, bp, out);
}

// round 17
// speedup vs baseline: 4.0173x; 1.0851x over previous
#include <cuda_runtime.h>
#include <cuda_fp16.h>
#include <cstdint>

// ---------------- problem constants ----------------
#define M_     4
#define B_     256
#define NPG_   64
#define N_     16384
#define DEG_   8
#define E_     131072
#define DF_    16
#define D_     256
#define L_     5
#define NA_    2
#define TASKS_ 10

// ---------------- device scratch (no allocs allowed) ----------------
__device__ float    g_h0[(size_t)N_ * D_];
__device__ float    g_hA[(size_t)M_ * N_ * D_];
__device__ float    g_t[(size_t)M_ * N_ * D_];
__device__ float    g_mind[(size_t)M_ * N_];
__device__ int      g_anchor[(size_t)M_ * N_];
// fp16-split, frag-permuted weights (packed half2 words): [11][32768]
__device__ unsigned g_wt_big[11 * 32768];
__device__ unsigned g_wt_small[11 * 32768];
// static per-graph dedup'd adjacency CSR (counts): entry = src | (cnt<<8)
__device__ int      g_csr_ent[B_ * 512];
__device__ int      g_csr_off[B_ * 65];

static __device__ __forceinline__ uint32_t smem_u32(const void* p) {
    uint32_t a;
    asm("{ .reg .u64 t; cvta.to.shared.u64 t, %1; cvt.u32.u64 %0, t; }"
        : "=r"(a) : "l"(p));
    return a;
}
static __device__ __forceinline__ void cp16(uint32_t dst, const void* src) {
    asm volatile("cp.async.cg.shared.global [%0], [%1], 16;"
                 :: "r"(dst), "l"(src) : "memory");
}
#define CP_COMMIT() asm volatile("cp.async.commit_group;" ::: "memory")
#define CP_WAIT(n)  asm volatile("cp.async.wait_group %0;" :: "n"(n) : "memory")

// split x = hi + lo (both fp16); packs pairs (x,y) into half2 words
static __device__ __forceinline__ void split2(float x, float y,
                                              unsigned* big, unsigned* small) {
    __half hx = __float2half_rn(x), hy = __float2half_rn(y);
    float rx = x - __half2float(hx), ry = y - __half2float(hy);
    *big = ((unsigned)__half_as_ushort(hy) << 16) | (unsigned)__half_as_ushort(hx);
    __half sx = __float2half_rn(rx), sy = __float2half_rn(ry);
    *small = ((unsigned)__half_as_ushort(sy) << 16) | (unsigned)__half_as_ushort(sx);
}

// m16n8k16 f16 mma, fp32 accum
#define MMA_F16(d, a, b) \
    asm volatile("mma.sync.aligned.m16n8k16.row.col.f32.f16.f16.f32 " \
                 "{%0,%1,%2,%3}, {%4,%5,%6,%7}, {%8,%9}, {%0,%1,%2,%3};" \
                 : "+f"((d)[0]), "+f"((d)[1]), "+f"((d)[2]), "+f"((d)[3]) \
                 : "r"((a)[0]), "r"((a)[1]), "r"((a)[2]), "r"((a)[3]), \
                   "r"((b)[0]), "r"((b)[1]))

// ---------------- threefry2x32 (exact JAX rounds) ----------------
#define TF_ROT(x,d) (((x) << (d)) | ((x) >> (32 - (d))))
static __host__ __device__ __forceinline__
void tf2x32(unsigned k0, unsigned k1, unsigned x0, unsigned x1,
            unsigned* o0, unsigned* o1)
{
    unsigned ks2 = k0 ^ k1 ^ 0x1BD11BDAu;
    x0 += k0; x1 += k1;
    x0 += x1; x1 = TF_ROT(x1,13); x1 ^= x0;
    x0 += x1; x1 = TF_ROT(x1,15); x1 ^= x0;
    x0 += x1; x1 = TF_ROT(x1,26); x1 ^= x0;
    x0 += x1; x1 = TF_ROT(x1, 6); x1 ^= x0;
    x0 += k1; x1 += ks2 + 1u;
    x0 += x1; x1 = TF_ROT(x1,17); x1 ^= x0;
    x0 += x1; x1 = TF_ROT(x1,29); x1 ^= x0;
    x0 += x1; x1 = TF_ROT(x1,16); x1 ^= x0;
    x0 += x1; x1 = TF_ROT(x1,24); x1 ^= x0;
    x0 += ks2; x1 += k0 + 2u;
    x0 += x1; x1 = TF_ROT(x1,13); x1 ^= x0;
    x0 += x1; x1 = TF_ROT(x1,15); x1 ^= x0;
    x0 += x1; x1 = TF_ROT(x1,26); x1 ^= x0;
    x0 += x1; x1 = TF_ROT(x1, 6); x1 ^= x0;
    x0 += k0; x1 += k1 + 3u;
    x0 += x1; x1 = TF_ROT(x1,17); x1 ^= x0;
    x0 += x1; x1 = TF_ROT(x1,29); x1 ^= x0;
    x0 += x1; x1 = TF_ROT(x1,16); x1 ^= x0;
    x0 += x1; x1 = TF_ROT(x1,24); x1 ^= x0;
    x0 += k1; x1 += ks2 + 4u;
    x0 += x1; x1 = TF_ROT(x1,13); x1 ^= x0;
    x0 += x1; x1 = TF_ROT(x1,15); x1 ^= x0;
    x0 += x1; x1 = TF_ROT(x1,26); x1 ^= x0;
    x0 += x1; x1 = TF_ROT(x1, 6); x1 ^= x0;
    x0 += ks2; x1 += k0 + 5u;
    *o0 = x0; *o1 = x1;
}

// ---------------- encoder: h0 = relu(x @ W_enc + b_enc) ----------------
__global__ void encoder_kernel(const float* __restrict__ x,
                               const float* __restrict__ W,
                               const float* __restrict__ b,
                               float* __restrict__ h0)
{
    int n = blockIdx.x;
    int d = threadIdx.x;
    __shared__ float xr[DF_];
    if (d < DF_) xr[d] = x[n * DF_ + d];
    __syncthreads();
    float acc = b[d];
#pragma unroll
    for (int k = 0; k < DF_; k++) acc = fmaf(xr[k], W[k * D_ + d], acc);
    h0[(size_t)n * D_ + d] = fmaxf(acc, 0.f);
}

__global__ void zero_anchor_kernel(int* __restrict__ anc)
{
    int idx = blockIdx.x * 256 + threadIdx.x;
    if (idx < M_ * N_) anc[idx] = 0;
}

// ----- build per-graph dedup'd CSR once (edges are static) -----
__global__ void prep_csr_kernel(const int* __restrict__ esrc,
                                const int* __restrict__ edst,
                                int* __restrict__ ent, int* __restrict__ off)
{
    __shared__ int cnt[64 * 64];
    __shared__ int nnz[64];
    __shared__ int base[65];
    int g = blockIdx.x, tid = threadIdx.x;
    for (int i = tid; i < 4096; i += 256) cnt[i] = 0;
    __syncthreads();
    int eb = g * 512;
#pragma unroll
    for (int k = 0; k < 2; k++) {
        int e = eb + tid + k * 256;
        int s = esrc[e] & 63, d = edst[e] & 63;
        atomicAdd(&cnt[d * 64 + s], 1);
    }
    __syncthreads();
    if (tid < 64) {
        int c = 0;
        for (int s = 0; s < 64; s++) c += (cnt[tid * 64 + s] != 0);
        nnz[tid] = c;
    }
    __syncthreads();
    if (tid == 0) {
        int a = 0;
        for (int d = 0; d < 64; d++) { base[d] = a; a += nnz[d]; }
        base[64] = a;
    }
    __syncthreads();
    if (tid < 64) {
        int o = base[tid];
        for (int s = 0; s < 64; s++) {
            int c = cnt[tid * 64 + s];
            if (c) ent[g * 512 + (o++)] = s | (c << 8);
        }
        off[g * 65 + tid] = base[tid];
        if (tid == 0) off[g * 65 + 64] = base[64];
    }
}

// ---- weight fp16-split + pack, permuted to m16n8k16 B-frag order ----
__global__ void split_w_kernel(const float* __restrict__ gW1,
                               const float* __restrict__ gW2,
                               const float* __restrict__ Wn2n,
                               unsigned* __restrict__ big,
                               unsigned* __restrict__ small)
{
    int id = blockIdx.x;  // 0..10
    const float* W = (id < 5) ? gW1 + (size_t)id * 65536
                   : (id < 10) ? gW2 + (size_t)(id - 5) * 65536
                   : Wn2n;
    int base = blockIdx.y * 2048;
    for (int i = threadIdx.x; i < 2048; i += 256) {
        int w = base + i;
        int reg = w & 1, ln = (w >> 1) & 31, ks = (w >> 6) & 1;
        int nt = (w >> 7) & 7, wn = (w >> 10) & 3, ch = (w >> 12) & 7;
        int n = wn * 64 + nt * 8 + (ln >> 2);
        int k0 = ch * 32 + ks * 16 + (ln & 3) * 2 + reg * 8;
        float v0 = W[k0 * 256 + n], v1 = W[(k0 + 1) * 256 + n];
        unsigned wb, wsm;
        split2(v0, v1, &wb, &wsm);
        big[(size_t)id * 32768 + w] = wb;
        small[(size_t)id * 32768 + w] = wsm;
    }
}

// =================== merged GNN layer kernel ===================
// One 128-row x 256-col block does: Y = A@W1 -> t = relu(Ctilde@Y + b1)
// (kept in smem, pre-split fp16) -> Out = relu(t@W2 + b2).
// a_bcast: A has N rows, broadcast across m (h0 input). use_anchor:
// A-row multiplied on the fly by (1 + emb[anchor[full_row]]).

#define MG_A1B   0          // stage-1 A chunk, stride 20 words
#define MG_A1S   2560
#define MG_B0B   5120       // B double buffers, 4096 words each
#define MG_B0S   9216
#define MG_B1B   13312
#define MG_B1S   17408
#define MG_STB   21504      // split-t big, 128 rows x stride 132 words
#define MG_STS   38400      // split-t small
#define MG_BIAS  55296      // 512 floats: b1[0..255], b2[256..511]
#define MG_ENT   55808
#define MG_OFF   56832
#define MG_SMEM_BYTES (56964 * 4)
// fp32 Y scratch (sY, stride 132, 16896 words) overlays [0, 16896)

__global__ __launch_bounds__(256, 1)
void gnn_layer(const float* __restrict__ A,
               const unsigned* __restrict__ B1b, const unsigned* __restrict__ B1s,
               const float* __restrict__ b1,
               const unsigned* __restrict__ B2b, const unsigned* __restrict__ B2s,
               const float* __restrict__ b2,
               float* __restrict__ Out,
               const int* __restrict__ ent, const int* __restrict__ off,
               const float* __restrict__ eps, int layer,
               const int* __restrict__ anchor, const float* __restrict__ emb,
               int use_anchor, int a_bcast)
{
    extern __shared__ float sm[];
    unsigned* sA1b = (unsigned*)sm + MG_A1B;
    unsigned* sA1s = (unsigned*)sm + MG_A1S;
    unsigned* sTb  = (unsigned*)sm + MG_STB;
    unsigned* sTs  = (unsigned*)sm + MG_STS;
    float* sbias = sm + MG_BIAS;
    int* sEnt = (int*)(sm + MG_ENT);
    int* sOff = (int*)(sm + MG_OFF);
    uint32_t smb = smem_u32(sm);

    const int tid = threadIdx.x, lane = tid & 31, wid = tid >> 5;
    const int wm = wid >> 2, wn = wid & 3;
    const size_t row0 = (size_t)blockIdx.x * 128;

    sbias[tid] = b1[tid];
    sbias[256 + tid] = b2[tid];
    {
        int g0 = (int)((row0 & (N_ - 1)) >> 6);
        for (int i = tid; i < 1024; i += 256)
            sEnt[i] = ent[(size_t)(g0 + (i >> 9)) * 512 + (i & 511)];
        if (tid < 130) {
            int gg = tid / 65;
            sOff[tid] = off[(size_t)(g0 + gg) * 65 + (tid - gg * 65)];
        }
    }

    const int R  = tid >> 1;
    const int kh = (tid & 1) * 16;
    const int cpb = (tid & 1) * 8;
    // BROADCAST FIX: h0 has only N rows; mask when A is the broadcast input.
    const size_t arow_idx = a_bcast ? ((row0 + R) & (size_t)(N_ - 1))
                                    : (row0 + R);
    const float* Arow = A + arow_idx * 256 + kh;
    const float* Erow = nullptr;
    if (use_anchor) {
        int aidx = anchor[row0 + R];        // anchor indexed by FULL row
        Erow = emb + aidx * 256 + kh;
    }

    const uint32_t bufb[2] = { smb + MG_B0B * 4, smb + MG_B1B * 4 };
    const uint32_t bufs[2] = { smb + MG_B0S * 4, smb + MG_B1S * 4 };

    float acc[4][8][4];
#pragma unroll
    for (int mt = 0; mt < 4; mt++)
#pragma unroll
        for (int nt = 0; nt < 8; nt++)
#pragma unroll
            for (int r = 0; r < 4; r++) acc[mt][nt][r] = 0.f;

    // ---------- stage 1: Y = A @ W1 ----------
#pragma unroll
    for (int q = 0; q < 4; q++) {
        cp16(bufb[0] + (uint32_t)(tid + q * 256) * 16, B1b + (tid + q * 256) * 4);
        cp16(bufs[0] + (uint32_t)(tid + q * 256) * 16, B1s + (tid + q * 256) * 4);
    }
    CP_COMMIT();
    float4 pa[4];
#pragma unroll
    for (int q = 0; q < 4; q++) {
        pa[q] = *(const float4*)(Arow + q * 4);
        if (use_anchor) {
            float4 ev = *(const float4*)(Erow + q * 4);
            pa[q].x *= (1.f + ev.x); pa[q].y *= (1.f + ev.y);
            pa[q].z *= (1.f + ev.z); pa[q].w *= (1.f + ev.w);
        }
    }

#pragma unroll 1
    for (int ch = 0; ch < 8; ch++) {
        if (ch) __syncthreads();
#pragma unroll
        for (int q = 0; q < 4; q++) {
            unsigned b0, s0, b1w, s1;
            split2(pa[q].x, pa[q].y, &b0, &s0);
            split2(pa[q].z, pa[q].w, &b1w, &s1);
            sA1b[R * 20 + cpb + 2 * q]     = b0;
            sA1b[R * 20 + cpb + 2 * q + 1] = b1w;
            sA1s[R * 20 + cpb + 2 * q]     = s0;
            sA1s[R * 20 + cpb + 2 * q + 1] = s1;
        }
        if (ch < 7) {
            const unsigned* srcb = B1b + (ch + 1) * 4096;
            const unsigned* srcs = B1s + (ch + 1) * 4096;
            uint32_t db = bufb[(ch + 1) & 1], ds = bufs[(ch + 1) & 1];
#pragma unroll
            for (int q = 0; q < 4; q++) {
                cp16(db + (uint32_t)(tid + q * 256) * 16, srcb + (tid + q * 256) * 4);
                cp16(ds + (uint32_t)(tid + q * 256) * 16, srcs + (tid + q * 256) * 4);
            }
            CP_COMMIT();
#pragma unroll
            for (int q = 0; q < 4; q++) {
                pa[q] = *(const float4*)(Arow + (ch + 1) * 32 + q * 4);
                if (use_anchor) {
                    float4 ev = *(const float4*)(Erow + (ch + 1) * 32 + q * 4);
                    pa[q].x *= (1.f + ev.x); pa[q].y *= (1.f + ev.y);
                    pa[q].z *= (1.f + ev.z); pa[q].w *= (1.f + ev.w);
                }
            }
            CP_WAIT(1);
        } else {
            CP_WAIT(0);
        }
        __syncthreads();

        const unsigned* cBb = (unsigned*)sm + ((ch & 1) ? MG_B1B : MG_B0B);
        const unsigned* cBs = (unsigned*)sm + ((ch & 1) ? MG_B1S : MG_B0S);
#pragma unroll
        for (int ks = 0; ks < 2; ks++) {
            uint32_t ab[4][4], as_[4][4];
#pragma unroll
            for (int mt = 0; mt < 4; mt++) {
                int o = (wm * 64 + mt * 16 + (lane >> 2)) * 20 + ks * 8 + (lane & 3);
                ab[mt][0]  = sA1b[o];
                ab[mt][1]  = sA1b[o + 8 * 20];
                ab[mt][2]  = sA1b[o + 4];
                ab[mt][3]  = sA1b[o + 8 * 20 + 4];
                as_[mt][0] = sA1s[o];
                as_[mt][1] = sA1s[o + 8 * 20];
                as_[mt][2] = sA1s[o + 4];
                as_[mt][3] = sA1s[o + 8 * 20 + 4];
            }
            uint32_t bb[8][2], bs[8][2];
#pragma unroll
            for (int nt = 0; nt < 8; nt++) {
                int o = ((wn * 8 + nt) * 2 + ks) * 64 + lane * 2;
                uint2 vb = *(const uint2*)&cBb[o];
                uint2 vs = *(const uint2*)&cBs[o];
                bb[nt][0] = vb.x; bb[nt][1] = vb.y;
                bs[nt][0] = vs.x; bs[nt][1] = vs.y;
            }
#pragma unroll
            for (int mt = 0; mt < 4; mt++)
#pragma unroll
                for (int nt = 0; nt < 8; nt++) {
                    MMA_F16(acc[mt][nt], ab[mt], bb[nt]);
                    MMA_F16(acc[mt][nt], ab[mt], bs[nt]);
                    MMA_F16(acc[mt][nt], as_[mt], bb[nt]);
                }
        }
    }

    // ---------- stage-1 epilogue: t = relu(Ctilde@Y + b1), split to smem ----
    {
        float* sY = sm;                       // stride 132, overlays [0,16896)
        float ep = 1.0f + eps[layer];
        int gl = wid >> 2;
#pragma unroll 1
        for (int p = 0; p < 2; p++) {
            __syncthreads();                  // prior smem reads complete
            if ((wn >> 1) == p) {
#pragma unroll
                for (int mt = 0; mt < 4; mt++) {
                    int rg = wm * 64 + mt * 16 + (lane >> 2);
#pragma unroll
                    for (int nt = 0; nt < 8; nt++) {
                        int cl = (wn & 1) * 64 + nt * 8 + (lane & 3) * 2;
                        *(float2*)&sY[rg * 132 + cl] =
                            make_float2(acc[mt][nt][0], acc[mt][nt][1]);
                        *(float2*)&sY[(rg + 8) * 132 + cl] =
                            make_float2(acc[mt][nt][2], acc[mt][nt][3]);
                    }
                }
            }
            __syncthreads();
            float4 bv = *(const float4*)&sbias[p * 128 + lane * 4];
#pragma unroll 1
            for (int i = 0; i < 16; i++) {
                int r = wid * 16 + i;
                int lr = r & 63;
                float4 a = *(const float4*)&sY[r * 132 + lane * 4];
                a.x *= ep; a.y *= ep; a.z *= ep; a.w *= ep;
                int st = sOff[gl * 65 + lr], en = sOff[gl * 65 + lr + 1];
                for (int e = st; e < en; e++) {
                    int u = sEnt[gl * 512 + e];
                    float c = (float)(u >> 8);
                    const float* hv = &sY[(gl * 64 + (u & 63)) * 132 + lane * 4];
                    a.x = fmaf(c, hv[0], a.x);
                    a.y = fmaf(c, hv[1], a.y);
                    a.z = fmaf(c, hv[2], a.z);
                    a.w = fmaf(c, hv[3], a.w);
                }
                float4 v;
                v.x = fmaxf(a.x + bv.x, 0.f);
                v.y = fmaxf(a.y + bv.y, 0.f);
                v.z = fmaxf(a.z + bv.z, 0.f);
                v.w = fmaxf(a.w + bv.w, 0.f);
                unsigned b0, s0, b1w, s1;
                split2(v.x, v.y, &b0, &s0);
                split2(v.z, v.w, &b1w, &s1);
                int w = r * 132 + p * 64 + lane * 2;
                sTb[w] = b0; sTb[w + 1] = b1w;
                sTs[w] = s0; sTs[w + 1] = s1;
            }
        }
    }
    __syncthreads();

    // ---------- stage 2: Out = relu(t @ W2 + b2) ----------
#pragma unroll
    for (int mt = 0; mt < 4; mt++)
#pragma unroll
        for (int nt = 0; nt < 8; nt++)
#pragma unroll
            for (int r = 0; r < 4; r++) acc[mt][nt][r] = 0.f;

#pragma unroll
    for (int q = 0; q < 4; q++) {
        cp16(bufb[0] + (uint32_t)(tid + q * 256) * 16, B2b + (tid + q * 256) * 4);
        cp16(bufs[0] + (uint32_t)(tid + q * 256) * 16, B2s + (tid + q * 256) * 4);
    }
    CP_COMMIT();

#pragma unroll 1
    for (int ch = 0; ch < 8; ch++) {
        if (ch) __syncthreads();
        if (ch < 7) {
            const unsigned* srcb = B2b + (ch + 1) * 4096;
            const unsigned* srcs = B2s + (ch + 1) * 4096;
            uint32_t db = bufb[(ch + 1) & 1], ds = bufs[(ch + 1) & 1];
#pragma unroll
            for (int q = 0; q < 4; q++) {
                cp16(db + (uint32_t)(tid + q * 256) * 16, srcb + (tid + q * 256) * 4);
                cp16(ds + (uint32_t)(tid + q * 256) * 16, srcs + (tid + q * 256) * 4);
            }
            CP_COMMIT();
            CP_WAIT(1);
        } else {
            CP_WAIT(0);
        }
        __syncthreads();

        const unsigned* cBb = (unsigned*)sm + ((ch & 1) ? MG_B1B : MG_B0B);
        const unsigned* cBs = (unsigned*)sm + ((ch & 1) ? MG_B1S : MG_B0S);
#pragma unroll
        for (int ks = 0; ks < 2; ks++) {
            uint32_t ab[4][4], as_[4][4];
#pragma unroll
            for (int mt = 0; mt < 4; mt++) {
                int o = (wm * 64 + mt * 16 + (lane >> 2)) * 132
                        + ch * 16 + ks * 8 + (lane & 3);
                ab[mt][0]  = sTb[o];
                ab[mt][1]  = sTb[o + 8 * 132];
                ab[mt][2]  = sTb[o + 4];
                ab[mt][3]  = sTb[o + 8 * 132 + 4];
                as_[mt][0] = sTs[o];
                as_[mt][1] = sTs[o + 8 * 132];
                as_[mt][2] = sTs[o + 4];
                as_[mt][3] = sTs[o + 8 * 132 + 4];
            }
            uint32_t bb[8][2], bs[8][2];
#pragma unroll
            for (int nt = 0; nt < 8; nt++) {
                int o = ((wn * 8 + nt) * 2 + ks) * 64 + lane * 2;
                uint2 vb = *(const uint2*)&cBb[o];
                uint2 vs = *(const uint2*)&cBs[o];
                bb[nt][0] = vb.x; bb[nt][1] = vb.y;
                bs[nt][0] = vs.x; bs[nt][1] = vs.y;
            }
#pragma unroll
            for (int mt = 0; mt < 4; mt++)
#pragma unroll
                for (int nt = 0; nt < 8; nt++) {
                    MMA_F16(acc[mt][nt], ab[mt], bb[nt]);
                    MMA_F16(acc[mt][nt], ab[mt], bs[nt]);
                    MMA_F16(acc[mt][nt], as_[mt], bb[nt]);
                }
        }
    }

#pragma unroll
    for (int mt = 0; mt < 4; mt++) {
        size_t rg = row0 + wm * 64 + mt * 16 + (lane >> 2);
#pragma unroll
        for (int nt = 0; nt < 8; nt++) {
            int cl = wn * 64 + nt * 8 + (lane & 3) * 2;
            float b0 = sbias[256 + cl], b1v = sbias[256 + cl + 1];
            float2 v0, v1;
            v0.x = fmaxf(acc[mt][nt][0] + b0, 0.f);
            v0.y = fmaxf(acc[mt][nt][1] + b1v, 0.f);
            v1.x = fmaxf(acc[mt][nt][2] + b0, 0.f);
            v1.y = fmaxf(acc[mt][nt][3] + b1v, 0.f);
            *(float2*)&Out[rg * 256 + cl] = v0;
            *(float2*)&Out[(rg + 8) * 256 + cl] = v1;
        }
    }
}

// ============ standalone plain GEMM (n2n): Out = relu(A@W + b) ============
#define GP_AB    0
#define GP_AS    2560
#define GP_B0B   5120
#define GP_B0S   9216
#define GP_B1B   13312
#define GP_B1S   17408
#define GP_BIAS  21504
#define GP_SMEM_BYTES ((21760) * 4)

__global__ __launch_bounds__(256, 1)
void gemm_plain(const float* __restrict__ A,
                const unsigned* __restrict__ Bb, const unsigned* __restrict__ Bs,
                const float* __restrict__ bias, float* __restrict__ C)
{
    extern __shared__ float sm[];
    unsigned* sAb = (unsigned*)sm + GP_AB;
    unsigned* sAs = (unsigned*)sm + GP_AS;
    float* sbias = sm + GP_BIAS;
    uint32_t smb = smem_u32(sm);

    const int tid = threadIdx.x, lane = tid & 31, wid = tid >> 5;
    const int wm = wid >> 2, wn = wid & 3;
    const size_t row0 = (size_t)blockIdx.x * 128;

    sbias[tid] = bias[tid];

    float acc[4][8][4];
#pragma unroll
    for (int mt = 0; mt < 4; mt++)
#pragma unroll
        for (int nt = 0; nt < 8; nt++)
#pragma unroll
            for (int r = 0; r < 4; r++) acc[mt][nt][r] = 0.f;

    const int R  = tid >> 1;
    const int kh = (tid & 1) * 16;
    const int cpb = (tid & 1) * 8;
    const float* Arow = A + (row0 + R) * 256 + kh;

    const uint32_t bufb[2] = { smb + GP_B0B * 4, smb + GP_B1B * 4 };
    const uint32_t bufs[2] = { smb + GP_B0S * 4, smb + GP_B1S * 4 };

#pragma unroll
    for (int q = 0; q < 4; q++) {
        cp16(bufb[0] + (uint32_t)(tid + q * 256) * 16, Bb + (tid + q * 256) * 4);
        cp16(bufs[0] + (uint32_t)(tid + q * 256) * 16, Bs + (tid + q * 256) * 4);
    }
    CP_COMMIT();
    float4 pa[4];
#pragma unroll
    for (int q = 0; q < 4; q++) pa[q] = *(const float4*)(Arow + q * 4);

#pragma unroll 1
    for (int ch = 0; ch < 8; ch++) {
        if (ch) __syncthreads();
#pragma unroll
        for (int q = 0; q < 4; q++) {
            unsigned b0, s0, b1, s1;
            split2(pa[q].x, pa[q].y, &b0, &s0);
            split2(pa[q].z, pa[q].w, &b1, &s1);
            sAb[R * 20 + cpb + 2 * q]     = b0;
            sAb[R * 20 + cpb + 2 * q + 1] = b1;
            sAs[R * 20 + cpb + 2 * q]     = s0;
            sAs[R * 20 + cpb + 2 * q + 1] = s1;
        }
        if (ch < 7) {
            const unsigned* srcb = Bb + (ch + 1) * 4096;
            const unsigned* srcs = Bs + (ch + 1) * 4096;
            uint32_t db = bufb[(ch + 1) & 1], ds = bufs[(ch + 1) & 1];
#pragma unroll
            for (int q = 0; q < 4; q++) {
                cp16(db + (uint32_t)(tid + q * 256) * 16, srcb + (tid + q * 256) * 4);
                cp16(ds + (uint32_t)(tid + q * 256) * 16, srcs + (tid + q * 256) * 4);
            }
            CP_COMMIT();
#pragma unroll
            for (int q = 0; q < 4; q++)
                pa[q] = *(const float4*)(Arow + (ch + 1) * 32 + q * 4);
            CP_WAIT(1);
        } else {
            CP_WAIT(0);
        }
        __syncthreads();

        const unsigned* cBb = (unsigned*)sm + ((ch & 1) ? GP_B1B : GP_B0B);
        const unsigned* cBs = (unsigned*)sm + ((ch & 1) ? GP_B1S : GP_B0S);
#pragma unroll
        for (int ks = 0; ks < 2; ks++) {
            uint32_t ab[4][4], as_[4][4];
#pragma unroll
            for (int mt = 0; mt < 4; mt++) {
                int o = (wm * 64 + mt * 16 + (lane >> 2)) * 20 + ks * 8 + (lane & 3);
                ab[mt][0]  = sAb[o];
                ab[mt][1]  = sAb[o + 8 * 20];
                ab[mt][2]  = sAb[o + 4];
                ab[mt][3]  = sAb[o + 8 * 20 + 4];
                as_[mt][0] = sAs[o];
                as_[mt][1] = sAs[o + 8 * 20];
                as_[mt][2] = sAs[o + 4];
                as_[mt][3] = sAs[o + 8 * 20 + 4];
            }
            uint32_t bb[8][2], bs[8][2];
#pragma unroll
            for (int nt = 0; nt < 8; nt++) {
                int o = ((wn * 8 + nt) * 2 + ks) * 64 + lane * 2;
                uint2 vb = *(const uint2*)&cBb[o];
                uint2 vs = *(const uint2*)&cBs[o];
                bb[nt][0] = vb.x; bb[nt][1] = vb.y;
                bs[nt][0] = vs.x; bs[nt][1] = vs.y;
            }
#pragma unroll
            for (int mt = 0; mt < 4; mt++)
#pragma unroll
                for (int nt = 0; nt < 8; nt++) {
                    MMA_F16(acc[mt][nt], ab[mt], bb[nt]);
                    MMA_F16(acc[mt][nt], ab[mt], bs[nt]);
                    MMA_F16(acc[mt][nt], as_[mt], bb[nt]);
                }
        }
    }

#pragma unroll
    for (int mt = 0; mt < 4; mt++) {
        size_t rg = row0 + wm * 64 + mt * 16 + (lane >> 2);
#pragma unroll
        for (int nt = 0; nt < 8; nt++) {
            int cl = wn * 64 + nt * 8 + (lane & 3) * 2;
            float b0 = sbias[cl], b1 = sbias[cl + 1];
            float2 v0, v1;
            v0.x = fmaxf(acc[mt][nt][0] + b0, 0.f);
            v0.y = fmaxf(acc[mt][nt][1] + b1, 0.f);
            v1.x = fmaxf(acc[mt][nt][2] + b0, 0.f);
            v1.y = fmaxf(acc[mt][nt][3] + b1, 0.f);
            *(float2*)&C[rg * 256 + cl] = v0;
            *(float2*)&C[(rg + 8) * 256 + cl] = v1;
        }
    }
}

// ---------------- per-graph pairwise min distance (fp32) ----------------
#define MD_SMEM ((64 * 257 + 64 + 64) * 4)
__global__ __launch_bounds__(256)
void mindist_kernel(const float* __restrict__ h, float* __restrict__ mind)
{
    extern __shared__ float sm[];
    float* sh  = sm;
    float* ssq = sm + 64 * 257;
    int*   smn = (int*)(ssq + 64);
    int b = blockIdx.x, m = blockIdx.y;
    int tid = threadIdx.x;

    const float* H = h + ((size_t)m * N_ + (size_t)b * NPG_) * D_;
    for (int idx = tid; idx < NPG_ * D_; idx += 256) {
        int r = idx >> 8, d = idx & 255;
        sh[r * 257 + d] = H[idx];
    }
    if (tid < 64) smn[tid] = 0x7f7fffff;
    __syncthreads();

    if (tid < 64) {
        const float* row = sh + tid * 257;
        float s = 0.f;
        for (int d = 0; d < D_; d++) s = fmaf(row[d], row[d], s);
        ssq[tid] = s;
    }
    __syncthreads();

    int i  = tid >> 2;
    int j0 = (tid & 3) * 16;
    float acc[16];
#pragma unroll
    for (int jj = 0; jj < 16; jj++) acc[jj] = 0.f;
    const float* ri = sh + i * 257;
    for (int d = 0; d < D_; d++) {
        float a = ri[d];
#pragma unroll
        for (int jj = 0; jj < 16; jj++)
            acc[jj] = fmaf(a, sh[(j0 + jj) * 257 + d], acc[jj]);
    }
    float sqi = ssq[i];
    float lmin = 3.0e38f;
#pragma unroll
    for (int jj = 0; jj < 16; jj++) {
        int j = j0 + jj;
        float d2 = fmaxf(sqi + ssq[j] - 2.0f * acc[jj], 0.f);
        if (j == i) d2 += 1.0e9f;
        lmin = fminf(lmin, d2);
    }
    atomicMin(&smn[i], __float_as_int(lmin));
    __syncthreads();
    if (tid < 64)
        mind[(size_t)m * N_ + (size_t)b * NPG_ + tid] = __int_as_float(smn[tid]);
}

// ------------- gumbel sample + argmax + anchor set (exact JAX) -----------
__global__ void gumbel_kernel(const float* __restrict__ mind,
                              int* __restrict__ anchor,
                              int it, unsigned fk0, unsigned fk1,
                              int mind_stride_m)
{
    int b = blockIdx.x, m = blockIdx.y;
    int p = threadIdx.x;
    __shared__ float sg[NPG_];
    int node = m * N_ + b * NPG_ + p;

    unsigned o0, o1;
    tf2x32(fk0, fk1, 0u, (unsigned)node, &o0, &o1);
    unsigned bits = o0 ^ o1;
    float f = __uint_as_float((bits >> 9) | 0x3f800000u) - 1.0f;
    const float mn = 1e-9f;
    float u = fmaxf(mn, f * (1.0f - mn) + mn);
    float md = mind[(size_t)m * mind_stride_m + b * NPG_ + p];
    float logit = -md - 10.0f * (anchor[node] > 0 ? 1.0f : 0.0f);
    sg[p] = logit - logf(-logf(u));
    __syncthreads();
    if (p == 0) {
        int best = 0; float bv = sg[0];
        for (int q = 1; q < NPG_; q++)
            if (sg[q] > bv) { bv = sg[q]; best = q; }
        anchor[m * N_ + b * NPG_ + best] = it;
    }
}

// --------- finalize: per-m group mean -> dot W_pred -> mean over m --------
__global__ void finalize_kernel(const float* __restrict__ hn,
                                const float* __restrict__ Wp,
                                const float* __restrict__ bp,
                                float* __restrict__ out)
{
    int b = blockIdx.x;
    int d = threadIdx.x;
    __shared__ float g[M_][D_];
#pragma unroll
    for (int m = 0; m < M_; m++) {
        const float* base = hn + ((size_t)m * N_ + (size_t)b * NPG_) * D_ + d;
        float s = 0.f;
        for (int p = 0; p < NPG_; p++) s += base[(size_t)p * D_];
        g[m][d] = s * (1.0f / (float)NPG_);
    }
    __syncthreads();
    if (d < TASKS_) {
        float acc = 0.f;
#pragma unroll
        for (int m = 0; m < M_; m++) {
            float a = 0.f;
            for (int k = 0; k < D_; k++)
                a = fmaf(g[m][k], Wp[k * TASKS_ + d], a);
            acc += a + bp[d];
        }
        out[b * TASKS_ + d] = acc * (1.0f / (float)M_);
    }
}

// ---------------- host orchestration ----------------
extern "C" void kernel_launch(void* const* d_in, const int* in_sizes, int n_in,
                              void* d_out, int out_size)
{
    const float* x     = (const float*)d_in[0];
    const float* W_enc = (const float*)d_in[1];
    const float* b_enc = (const float*)d_in[2];
    const float* gW1   = (const float*)d_in[3];
    const float* gb1   = (const float*)d_in[4];
    const float* gW2   = (const float*)d_in[5];
    const float* gb2   = (const float*)d_in[6];
    const float* eps   = (const float*)d_in[7];
    const float* aemb  = (const float*)d_in[8];
    const float* Wn2n  = (const float*)d_in[9];
    const float* bn2n  = (const float*)d_in[10];
    const float* Wp    = (const float*)d_in[11];
    const float* bp    = (const float*)d_in[12];
    const int*   esrc  = (const int*)d_in[13];
    const int*   edst  = (const int*)d_in[14];
    float* out = (float*)d_out;

    float *h0, *hA, *t, *mind; int *anc, *ent, *off;
    unsigned *wtb, *wts;
    cudaGetSymbolAddress((void**)&h0,   g_h0);
    cudaGetSymbolAddress((void**)&hA,   g_hA);
    cudaGetSymbolAddress((void**)&t,    g_t);
    cudaGetSymbolAddress((void**)&mind, g_mind);
    cudaGetSymbolAddress((void**)&anc,  g_anchor);
    cudaGetSymbolAddress((void**)&wtb,  g_wt_big);
    cudaGetSymbolAddress((void**)&wts,  g_wt_small);
    cudaGetSymbolAddress((void**)&ent,  g_csr_ent);
    cudaGetSymbolAddress((void**)&off,  g_csr_off);

    cudaFuncSetAttribute(mindist_kernel, cudaFuncAttributeMaxDynamicSharedMemorySize, MD_SMEM);
    cudaFuncSetAttribute(gnn_layer, cudaFuncAttributeMaxDynamicSharedMemorySize, MG_SMEM_BYTES);
    cudaFuncSetAttribute(gemm_plain, cudaFuncAttributeMaxDynamicSharedMemorySize, GP_SMEM_BYTES);

    unsigned fk0[NA_ + 1], fk1[NA_ + 1];
    for (int i = 1; i <= NA_; i++)
        tf2x32(0u, 42u, 0u, (unsigned)i, &fk0[i], &fk1[i]);

    const dim3 graph_full(B_, M_), graph_q(B_, 1);
    const int  mg_full = (M_ * N_) / 128;   // 512 blocks
    const int  mg_q    = N_ / 128;          // 128 blocks

    auto WB = [&](int id) { return wtb + (size_t)id * 32768; };
    auto WS = [&](int id) { return wts + (size_t)id * 32768; };

    prep_csr_kernel<<<B_, 256>>>(esrc, edst, ent, off);
    split_w_kernel<<<dim3(11, 16), 256>>>(gW1, gW2, Wn2n, wtb, wts);
    encoder_kernel<<<N_, 256>>>(x, W_enc, b_enc, h0);
    zero_anchor_kernel<<<(M_ * N_) / 256, 256>>>(anc);

    // ---- iteration 1: xcur == h0 broadcast -> compute once over N rows ----
    {
        const float* cur = h0;
        for (int l = 0; l < L_; l++) {
            gnn_layer<<<mg_q, 256, MG_SMEM_BYTES>>>(
                cur, WB(l), WS(l), gb1 + l * D_,
                WB(5 + l), WS(5 + l), gb2 + l * D_, hA,
                ent, off, eps, l, nullptr, nullptr, 0, 0);
            cur = hA;
        }
        mindist_kernel<<<graph_q, 256, MD_SMEM>>>(hA, mind);
        gumbel_kernel<<<graph_full, 64>>>(mind, anc, 1, fk0[1], fk1[1], 0);
    }

    // ---- iteration 2: full per-m pipeline (layer0: h0 broadcast + emb) ----
    {
        const float* cur = h0;   // layer 0 computes xcur on the fly
        for (int l = 0; l < L_; l++) {
            gnn_layer<<<mg_full, 256, MG_SMEM_BYTES>>>(
                cur, WB(l), WS(l), gb1 + l * D_,
                WB(5 + l), WS(5 + l), gb2 + l * D_, hA,
                ent, off, eps, l, anc, aemb,
                l == 0 ? 1 : 0, l == 0 ? 1 : 0);
            cur = hA;
        }
        mindist_kernel<<<graph_full, 256, MD_SMEM>>>(hA, mind);
        gumbel_kernel<<<graph_full, 64>>>(mind, anc, 2, fk0[2], fk1[2], N_);
    }

    // ---- final GNN (anchor now has it=2 values) ----
    {
        const float* cur = h0;
        for (int l = 0; l < L_; l++) {
            gnn_layer<<<mg_full, 256, MG_SMEM_BYTES>>>(
                cur, WB(l), WS(l), gb1 + l * D_,
                WB(5 + l), WS(5 + l), gb2 + l * D_, hA,
                ent, off, eps, l, anc, aemb,
                l == 0 ? 1 : 0, l == 0 ? 1 : 0);
            cur = hA;
        }
    }
    gemm_plain<<<mg_full, 256, GP_SMEM_BYTES>>>(hA, WB(10), WS(10), bn2n, t);
    finalize_kernel<<<B_, 256>>>(t, Wp, bp, out);
}